// round 4
// baseline (speedup 1.0000x reference)
#include <cuda_runtime.h>
#include <cuda_bf16.h>
#include <math_constants.h>
#include <cstdint>

#define D_MODEL   1024
#define NUM_HEADS 16
#define D_HEAD    64
#define PATCH     128
#define BATCH     4
#define SEQ       8192
#define M_TOTAL   (BATCH * SEQ)          // 32768 rows
#define NBLK      (M_TOTAL / PATCH)      // 256 patch blocks

// ---------------------------------------------------------------------------
// Scratch (static device globals — no runtime allocation)
// ---------------------------------------------------------------------------
__device__ int8_t g_xq1[(size_t)M_TOTAL * D_MODEL];
__device__ int8_t g_xq2[(size_t)M_TOTAL * D_MODEL];
__device__ float  g_sx [M_TOTAL];
__device__ float  g_Q  [(size_t)M_TOTAL * D_MODEL];
__device__ float  g_K  [(size_t)M_TOTAL * D_MODEL];
__device__ float  g_V  [(size_t)M_TOTAL * D_MODEL];
__device__ float  g_A  [(size_t)M_TOTAL * D_MODEL];
__device__ int8_t g_aq1[(size_t)M_TOTAL * D_MODEL];
__device__ int8_t g_aq2[(size_t)M_TOTAL * D_MODEL];
__device__ float  g_sa [M_TOTAL];
// transposed+quantized weights (W^T: row n, col k), 2 slices + col multiplier
__device__ int8_t g_w1[4][D_MODEL * D_MODEL];
__device__ int8_t g_w2[4][D_MODEL * D_MODEL];
__device__ float  g_sw[4][D_MODEL];

// ---------------------------------------------------------------------------
// PTX helpers (base ISA only)
// ---------------------------------------------------------------------------
__device__ __forceinline__ uint32_t smem_u32(const void* p) {
    uint32_t a;
    asm("{ .reg .u64 t; cvta.to.shared.u64 t, %1; cvt.u32.u64 %0, t; }" : "=r"(a) : "l"(p));
    return a;
}
__device__ __forceinline__ void cp16(uint32_t dst, const void* src) {
    asm volatile("cp.async.cg.shared.global [%0], [%1], 16;" :: "r"(dst), "l"(src));
}
#define CP_COMMIT() asm volatile("cp.async.commit_group;" ::: "memory")
#define CP_WAIT2()  asm volatile("cp.async.wait_group 2;" ::: "memory")

#define LDSM4(r0, r1, r2, r3, addr) \
    asm volatile("ldmatrix.sync.aligned.m8n8.x4.shared.b16 {%0,%1,%2,%3}, [%4];" \
        : "=r"(r0), "=r"(r1), "=r"(r2), "=r"(r3) : "r"(addr))

#define IMMA16832(c, a, b0, b1) \
    asm volatile("mma.sync.aligned.m16n8k32.row.col.s32.s8.s8.s32 " \
        "{%0,%1,%2,%3}, {%4,%5,%6,%7}, {%8,%9}, {%0,%1,%2,%3};" \
        : "+r"((c)[0]), "+r"((c)[1]), "+r"((c)[2]), "+r"((c)[3]) \
        : "r"((a)[0]), "r"((a)[1]), "r"((a)[2]), "r"((a)[3]), "r"(b0), "r"(b1))

// ---------------------------------------------------------------------------
// Row-wise dual-slice int8 quantization of fp32 [R][1024].
// One warp per row; lane handles elements lane*4 + j*128 (4 consecutive).
// block 256 (8 rows), grid R/8.
// ---------------------------------------------------------------------------
__global__ __launch_bounds__(256)
void rowquant_kernel(const float* __restrict__ in,
                     int8_t* __restrict__ q1, int8_t* __restrict__ q2,
                     float* __restrict__ mult)
{
    const int row  = blockIdx.x * 8 + (threadIdx.x >> 5);
    const int lane = threadIdx.x & 31;
    const float* rp = in + (size_t)row * D_MODEL;

    float v[32];
    float mx = 0.f;
    #pragma unroll
    for (int j = 0; j < 8; j++) {
        float4 t = *reinterpret_cast<const float4*>(rp + j * 128 + lane * 4);
        v[j*4+0] = t.x; v[j*4+1] = t.y; v[j*4+2] = t.z; v[j*4+3] = t.w;
        mx = fmaxf(mx, fmaxf(fmaxf(fabsf(t.x), fabsf(t.y)), fmaxf(fabsf(t.z), fabsf(t.w))));
    }
    #pragma unroll
    for (int o = 16; o; o >>= 1) mx = fmaxf(mx, __shfl_xor_sync(0xffffffffu, mx, o));

    const float inv = mx > 0.f ? 127.f / mx : 0.f;
    if (lane == 0) mult[row] = mx * (1.f / 127.f);

    #pragma unroll
    for (int j = 0; j < 8; j++) {
        int p1 = 0, p2 = 0;
        #pragma unroll
        for (int e = 0; e < 4; e++) {
            float a  = v[j*4+e] * inv;          // in [-127, 127]
            float a1 = rintf(a);
            float a2 = rintf((a - a1) * 256.f); // in [-128, 128]
            a2 = fminf(fmaxf(a2, -127.f), 127.f);
            p1 |= ((int)a1 & 0xFF) << (e * 8);
            p2 |= ((int)a2 & 0xFF) << (e * 8);
        }
        *reinterpret_cast<int*>(q1 + (size_t)row * D_MODEL + j * 128 + lane * 4) = p1;
        *reinterpret_cast<int*>(q2 + (size_t)row * D_MODEL + j * 128 + lane * 4) = p2;
    }
}

// ---------------------------------------------------------------------------
// Column abs-max of W[1024][1024] -> mult[n] = colmax/127.  grid 4, block 256.
// ---------------------------------------------------------------------------
__global__ void colmax_kernel(const float* __restrict__ W, float* __restrict__ mult)
{
    int n = blockIdx.x * 256 + threadIdx.x;
    float mx = 0.f;
    #pragma unroll 8
    for (int k = 0; k < D_MODEL; k++)
        mx = fmaxf(mx, fabsf(W[(size_t)k * D_MODEL + n]));
    mult[n] = mx * (1.f / 127.f);
}

// ---------------------------------------------------------------------------
// Transpose + dual-slice quantize: W[k][n] -> Wt1/Wt2 [n][k] int8.
// block (32,8), grid (32,32).
// ---------------------------------------------------------------------------
__global__ void wquant_kernel(const float* __restrict__ W, const float* __restrict__ mult,
                              int8_t* __restrict__ q1, int8_t* __restrict__ q2)
{
    __shared__ float t[32][33];
    int bx = blockIdx.x * 32, by = blockIdx.y * 32;
    int x = threadIdx.x, y = threadIdx.y;
    #pragma unroll
    for (int d = 0; d < 32; d += 8)
        t[y + d][x] = W[(size_t)(by + y + d) * D_MODEL + bx + x];
    __syncthreads();
    #pragma unroll
    for (int d = 0; d < 32; d += 8) {
        int n = bx + y + d;                 // output row (W column)
        float m = mult[n];
        float inv = m > 0.f ? 1.f / m : 0.f;
        float a  = t[x][y + d] * inv;
        float a1 = rintf(a);
        float a2 = rintf((a - a1) * 256.f);
        a2 = fminf(fmaxf(a2, -127.f), 127.f);
        size_t o = (size_t)n * D_MODEL + by + x;
        q1[o] = (int8_t)(int)a1;
        q2[o] = (int8_t)(int)a2;
    }
}

// ---------------------------------------------------------------------------
// Dual-slice int8 GEMM: C[M,1024] = multA⊗multB ⊙ ((A1+A2/256)(B1+B2/256)^T) + bias
// CTA tile 128x128, BK=64 (int8), 3-stage cp.async pipeline.
// 8 warps, warp tile 64x32. P1 = a1b1, P2 = a1b2 + a2b1 (a2b2 dropped).
// smem/stage: 4 planes x 128 rows x 80B = 40960 B; 3 stages = 122880 B.
// ---------------------------------------------------------------------------
#define STAGE_B   40960
#define PLANE_B   10240
#define GEMM_SMEM (3 * STAGE_B)
#define KCHUNKS   16

__global__ __launch_bounds__(256, 1)
void gemm_i8(const int8_t* __restrict__ A1, const int8_t* __restrict__ A2,
             const float* __restrict__ multA,
             const int8_t* __restrict__ B1, const int8_t* __restrict__ B2,
             const float* __restrict__ multB,
             const float* __restrict__ bias, float* __restrict__ C)
{
    extern __shared__ char smem_raw[];
    const uint32_t sbase = smem_u32(smem_raw);

    const int tid    = threadIdx.x;
    const int wid    = tid >> 5;
    const int lane   = tid & 31;
    const int warp_m = (wid >> 2) * 64;   // 0 or 64
    const int warp_n = (wid & 3) * 32;    // 0,32,64,96
    const size_t m0  = (size_t)blockIdx.y * 128;
    const size_t n0  = (size_t)blockIdx.x * 128;

    const char* src[4] = {
        (const char*)(A1 + m0 * D_MODEL),
        (const char*)(A2 + m0 * D_MODEL),
        (const char*)(B1 + n0 * D_MODEL),
        (const char*)(B2 + n0 * D_MODEL)
    };

    // fill one stage: 4 planes, 128 rows x 64B data, 80B smem stride
    auto fill = [&](int stage, int kc) {
        #pragma unroll
        for (int i = 0; i < 8; i++) {
            int c   = tid + i * 256;        // 0..2047
            int mat = c >> 9;               // 0..3
            int cc  = c & 511;
            int row = cc >> 2, col = cc & 3;
            cp16(sbase + stage * STAGE_B + mat * PLANE_B + row * 80 + col * 16,
                 src[mat] + (size_t)row * D_MODEL + kc * 64 + col * 16);
        }
        CP_COMMIT();
    };

    int acc1[4][4][4], acc2[4][4][4];
    #pragma unroll
    for (int i = 0; i < 4; i++)
        #pragma unroll
        for (int j = 0; j < 4; j++)
            #pragma unroll
            for (int q = 0; q < 4; q++) { acc1[i][j][q] = 0; acc2[i][j][q] = 0; }

    fill(0, 0);
    fill(1, 1);

    // per-lane ldmatrix offsets (identical byte pattern to the bf16 version)
    const int lr = lane & 7, g = lane >> 3;
    const uint32_t a_loff = (uint32_t)((lr + (g & 1) * 8) * 80 + (g >> 1) * 16);
    const uint32_t b_loff = (uint32_t)((lr + (g >> 1) * 8) * 80 + (g & 1) * 16);

    for (int j = 0; j < KCHUNKS; j++) {
        if (j + 2 < KCHUNKS) fill((j + 2) % 3, j + 2);
        else CP_COMMIT();
        CP_WAIT2();
        __syncthreads();

        const uint32_t st  = sbase + (j % 3) * STAGE_B;
        const uint32_t aP1 = st +               warp_m * 80 + a_loff;
        const uint32_t aP2 = st + 1 * PLANE_B + warp_m * 80 + a_loff;
        const uint32_t bP1 = st + 2 * PLANE_B + warp_n * 80 + b_loff;
        const uint32_t bP2 = st + 3 * PLANE_B + warp_n * 80 + b_loff;

        #pragma unroll
        for (int ks = 0; ks < 2; ks++) {
            const uint32_t ko = ks * 32;    // 32 int8 = 32B per k32 step
            uint32_t a_r[4][4], b1_r[8], b2_r[8];

            // P1 += a1 * b1
            #pragma unroll
            for (int mt = 0; mt < 4; mt++)
                LDSM4(a_r[mt][0], a_r[mt][1], a_r[mt][2], a_r[mt][3],
                      aP1 + mt * (16 * 80) + ko);
            #pragma unroll
            for (int p = 0; p < 2; p++)
                LDSM4(b1_r[p*4+0], b1_r[p*4+1], b1_r[p*4+2], b1_r[p*4+3],
                      bP1 + p * (16 * 80) + ko);
            #pragma unroll
            for (int mt = 0; mt < 4; mt++)
                #pragma unroll
                for (int nt = 0; nt < 4; nt++)
                    IMMA16832(acc1[mt][nt], a_r[mt], b1_r[nt*2], b1_r[nt*2+1]);

            // P2 += a1 * b2
            #pragma unroll
            for (int p = 0; p < 2; p++)
                LDSM4(b2_r[p*4+0], b2_r[p*4+1], b2_r[p*4+2], b2_r[p*4+3],
                      bP2 + p * (16 * 80) + ko);
            #pragma unroll
            for (int mt = 0; mt < 4; mt++)
                #pragma unroll
                for (int nt = 0; nt < 4; nt++)
                    IMMA16832(acc2[mt][nt], a_r[mt], b2_r[nt*2], b2_r[nt*2+1]);

            // P2 += a2 * b1   (reuse a_r registers)
            #pragma unroll
            for (int mt = 0; mt < 4; mt++)
                LDSM4(a_r[mt][0], a_r[mt][1], a_r[mt][2], a_r[mt][3],
                      aP2 + mt * (16 * 80) + ko);
            #pragma unroll
            for (int mt = 0; mt < 4; mt++)
                #pragma unroll
                for (int nt = 0; nt < 4; nt++)
                    IMMA16832(acc2[mt][nt], a_r[mt], b1_r[nt*2], b1_r[nt*2+1]);
        }
        __syncthreads();
    }

    // epilogue: C = multA*multB*(P1 + P2/256) + bias
    #pragma unroll
    for (int mt = 0; mt < 4; mt++) {
        #pragma unroll
        for (int nt = 0; nt < 4; nt++) {
            int r0   = (int)m0 + warp_m + mt * 16 + (lane >> 2);
            int colg = (int)n0 + warp_n + nt * 8 + (lane & 3) * 2;
            float sA0 = multA[r0], sA1 = multA[r0 + 8];
            float2 sB = *reinterpret_cast<const float2*>(multB + colg);
            float2 bv = *reinterpret_cast<const float2*>(bias + colg);
            float2 o0, o1;
            o0.x = sA0 * sB.x * ((float)acc1[mt][nt][0] + (float)acc2[mt][nt][0] * 0.00390625f) + bv.x;
            o0.y = sA0 * sB.y * ((float)acc1[mt][nt][1] + (float)acc2[mt][nt][1] * 0.00390625f) + bv.y;
            o1.x = sA1 * sB.x * ((float)acc1[mt][nt][2] + (float)acc2[mt][nt][2] * 0.00390625f) + bv.x;
            o1.y = sA1 * sB.y * ((float)acc1[mt][nt][3] + (float)acc2[mt][nt][3] * 0.00390625f) + bv.y;
            *reinterpret_cast<float2*>(C + (size_t)r0 * D_MODEL + colg) = o0;
            *reinterpret_cast<float2*>(C + (size_t)(r0 + 8) * D_MODEL + colg) = o1;
        }
    }
}

// ---------------------------------------------------------------------------
// Fused patch attention (fp32). grid = (NUM_HEADS, NBLK), 256 threads.
// smem 131584 B. Writes fp32 to g_A.
// ---------------------------------------------------------------------------
__global__ __launch_bounds__(256, 1)
void attn_kernel()
{
    extern __shared__ float sm[];
    float* Ks = sm;
    float* Vs = Ks + 128 * 64;
    float* S  = Vs + 128 * 64;       // [128][129]

    const int h   = blockIdx.x;
    const int pb  = blockIdx.y;
    const int tid = threadIdx.x;
    const size_t base = (size_t)pb * 128 * D_MODEL + (size_t)h * D_HEAD;

    for (int i = tid; i < 128 * 16; i += 256) {
        int row = i >> 4;
        int c   = i & 15;
        size_t gidx = base + (size_t)row * D_MODEL + c * 4;
        *reinterpret_cast<float4*>(&Ks[row * 64 + c * 4]) =
            *reinterpret_cast<const float4*>(&g_K[gidx]);
        *reinterpret_cast<float4*>(&Vs[row * 64 + c * 4]) =
            *reinterpret_cast<const float4*>(&g_V[gidx]);
    }
    __syncthreads();

    const int r    = tid >> 1;
    const int half = tid & 1;

    float q[64];
    {
        const float* qp = &g_Q[base + (size_t)r * D_MODEL];
        #pragma unroll
        for (int c = 0; c < 16; c++) {
            float4 v = *reinterpret_cast<const float4*>(qp + c * 4);
            q[c * 4 + 0] = v.x * 0.125f;
            q[c * 4 + 1] = v.y * 0.125f;
            q[c * 4 + 2] = v.z * 0.125f;
            q[c * 4 + 3] = v.w * 0.125f;
        }
    }

    #pragma unroll 1
    for (int j0 = 0; j0 < 64; j0++) {
        int j = half * 64 + j0;
        const float* kp = &Ks[j * 64];
        float s0 = 0.f, s1 = 0.f, s2 = 0.f, s3 = 0.f;
        #pragma unroll
        for (int c = 0; c < 16; c++) {
            float4 kv = *reinterpret_cast<const float4*>(kp + c * 4);
            s0 += q[c * 4 + 0] * kv.x;
            s1 += q[c * 4 + 1] * kv.y;
            s2 += q[c * 4 + 2] * kv.z;
            s3 += q[c * 4 + 3] * kv.w;
        }
        S[r * 129 + j] = (s0 + s1) + (s2 + s3);
    }
    __syncthreads();

    float mx = -CUDART_INF_F;
    #pragma unroll 4
    for (int j0 = 0; j0 < 64; j0++)
        mx = fmaxf(mx, S[r * 129 + half * 64 + j0]);
    mx = fmaxf(mx, __shfl_xor_sync(0xffffffffu, mx, 1));

    float l = 0.f;
    #pragma unroll 4
    for (int j0 = 0; j0 < 64; j0++) {
        float e = __expf(S[r * 129 + half * 64 + j0] - mx);
        S[r * 129 + half * 64 + j0] = e;
        l += e;
    }
    l += __shfl_xor_sync(0xffffffffu, l, 1);
    float inv = 1.0f / l;
    __syncthreads();

    float acc[32];
    #pragma unroll
    for (int c = 0; c < 32; c++) acc[c] = 0.f;

    #pragma unroll 1
    for (int j = 0; j < 128; j++) {
        float w = S[r * 129 + j];
        const float* vp = &Vs[j * 64 + half * 32];
        #pragma unroll
        for (int c = 0; c < 8; c++) {
            float4 vv = *reinterpret_cast<const float4*>(vp + c * 4);
            acc[c * 4 + 0] += w * vv.x;
            acc[c * 4 + 1] += w * vv.y;
            acc[c * 4 + 2] += w * vv.z;
            acc[c * 4 + 3] += w * vv.w;
        }
    }

    float* op = &g_A[base + (size_t)r * D_MODEL + half * 32];
    #pragma unroll
    for (int c = 0; c < 8; c++) {
        float4 o;
        o.x = acc[c * 4 + 0] * inv;
        o.y = acc[c * 4 + 1] * inv;
        o.z = acc[c * 4 + 2] * inv;
        o.w = acc[c * 4 + 3] * inv;
        *reinterpret_cast<float4*>(op + c * 4) = o;
    }
}

// ---------------------------------------------------------------------------
extern "C" void kernel_launch(void* const* d_in, const int* in_sizes, int n_in,
                              void* d_out, int out_size)
{
    const float* x  = (const float*)d_in[0];
    // d_in[1] = coords (unused by reference)
    const float* W[4]  = { (const float*)d_in[2], (const float*)d_in[4],
                           (const float*)d_in[6], (const float*)d_in[8] };
    const float* bq = (const float*)d_in[3];
    const float* bk = (const float*)d_in[5];
    const float* bv = (const float*)d_in[7];
    const float* bo = (const float*)d_in[9];
    float* out = (float*)d_out;

    int8_t *xq1, *xq2, *aq1, *aq2;
    float *sx, *sa, *pQ, *pK, *pV, *pA;
    cudaGetSymbolAddress((void**)&xq1, g_xq1);
    cudaGetSymbolAddress((void**)&xq2, g_xq2);
    cudaGetSymbolAddress((void**)&sx,  g_sx);
    cudaGetSymbolAddress((void**)&aq1, g_aq1);
    cudaGetSymbolAddress((void**)&aq2, g_aq2);
    cudaGetSymbolAddress((void**)&sa,  g_sa);
    cudaGetSymbolAddress((void**)&pQ,  g_Q);
    cudaGetSymbolAddress((void**)&pK,  g_K);
    cudaGetSymbolAddress((void**)&pV,  g_V);
    cudaGetSymbolAddress((void**)&pA,  g_A);
    int8_t *w1, *w2; float *sw;
    cudaGetSymbolAddress((void**)&w1, g_w1);
    cudaGetSymbolAddress((void**)&w2, g_w2);
    cudaGetSymbolAddress((void**)&sw, g_sw);

    cudaFuncSetAttribute(gemm_i8, cudaFuncAttributeMaxDynamicSharedMemorySize, GEMM_SMEM);
    static const size_t attn_smem = (128 * 64 * 2 + 128 * 129) * sizeof(float);
    cudaFuncSetAttribute(attn_kernel, cudaFuncAttributeMaxDynamicSharedMemorySize, (int)attn_smem);

    // 1. quantize x (row-wise dual-slice)
    rowquant_kernel<<<M_TOTAL / 8, 256>>>(x, xq1, xq2, sx);

    // 2. quantize + transpose weights
    dim3 wgrid(32, 32), wblk(32, 8);
    for (int i = 0; i < 4; i++) {
        const size_t wo = (size_t)i * D_MODEL * D_MODEL;
        colmax_kernel<<<4, 256>>>(W[i], sw + i * D_MODEL);
        wquant_kernel<<<wgrid, wblk>>>(W[i], sw + i * D_MODEL, w1 + wo, w2 + wo);
    }

    // 3. Q/K/V projections (int8 tensor cores)
    dim3 ggrid(D_MODEL / 128, M_TOTAL / 128);   // (8, 256)
    const size_t WS = (size_t)D_MODEL * D_MODEL;
    gemm_i8<<<ggrid, 256, GEMM_SMEM>>>(xq1, xq2, sx, w1 + 0*WS, w2 + 0*WS, sw + 0*D_MODEL, bq, pQ);
    gemm_i8<<<ggrid, 256, GEMM_SMEM>>>(xq1, xq2, sx, w1 + 1*WS, w2 + 1*WS, sw + 1*D_MODEL, bk, pK);
    gemm_i8<<<ggrid, 256, GEMM_SMEM>>>(xq1, xq2, sx, w1 + 2*WS, w2 + 2*WS, sw + 2*D_MODEL, bv, pV);

    // 4. attention (fp32 -> g_A)
    dim3 agrid(NUM_HEADS, NBLK);
    attn_kernel<<<agrid, 256, attn_smem>>>();

    // 5. quantize attention output, then O-projection
    rowquant_kernel<<<M_TOTAL / 8, 256>>>(pA, aq1, aq2, sa);
    gemm_i8<<<ggrid, 256, GEMM_SMEM>>>(aq1, aq2, sa, w1 + 3*WS, w2 + 3*WS, sw + 3*D_MODEL, bo, out);
}

// round 5
// speedup vs baseline: 2.1406x; 2.1406x over previous
#include <cuda_runtime.h>
#include <cuda_bf16.h>
#include <math_constants.h>
#include <cstdint>

#define D_MODEL   1024
#define NUM_HEADS 16
#define D_HEAD    64
#define PATCH     128
#define BATCH     4
#define SEQ       8192
#define M_TOTAL   (BATCH * SEQ)          // 32768 rows
#define NBLK      (M_TOTAL / PATCH)      // 256 patch blocks

// ---------------------------------------------------------------------------
// Scratch (static device globals — no runtime allocation)
// ---------------------------------------------------------------------------
__device__ __nv_bfloat16 g_xh[(size_t)M_TOTAL * D_MODEL];
__device__ __nv_bfloat16 g_xl[(size_t)M_TOTAL * D_MODEL];
__device__ float         g_Q [(size_t)M_TOTAL * D_MODEL];
__device__ float         g_K [(size_t)M_TOTAL * D_MODEL];
__device__ float         g_V [(size_t)M_TOTAL * D_MODEL];
__device__ __nv_bfloat16 g_Ah[(size_t)M_TOTAL * D_MODEL];
__device__ __nv_bfloat16 g_Al[(size_t)M_TOTAL * D_MODEL];
// transposed+split weights (W^T: row n, col k) — bf16 hi/lo
__device__ __nv_bfloat16 g_wqh[D_MODEL * D_MODEL];
__device__ __nv_bfloat16 g_wql[D_MODEL * D_MODEL];
__device__ __nv_bfloat16 g_wkh[D_MODEL * D_MODEL];
__device__ __nv_bfloat16 g_wkl[D_MODEL * D_MODEL];
__device__ __nv_bfloat16 g_wvh[D_MODEL * D_MODEL];
__device__ __nv_bfloat16 g_wvl[D_MODEL * D_MODEL];
__device__ __nv_bfloat16 g_woh[D_MODEL * D_MODEL];
__device__ __nv_bfloat16 g_wol[D_MODEL * D_MODEL];

// ---------------------------------------------------------------------------
// PTX helpers (base ISA only — no sm_103a-specific features)
// ---------------------------------------------------------------------------
__device__ __forceinline__ uint32_t smem_u32(const void* p) {
    uint32_t a;
    asm("{ .reg .u64 t; cvta.to.shared.u64 t, %1; cvt.u32.u64 %0, t; }" : "=r"(a) : "l"(p));
    return a;
}
__device__ __forceinline__ void cp16(uint32_t dst, const void* src) {
    asm volatile("cp.async.cg.shared.global [%0], [%1], 16;" :: "r"(dst), "l"(src));
}
#define CP_COMMIT() asm volatile("cp.async.commit_group;" ::: "memory")
#define CP_WAIT1()  asm volatile("cp.async.wait_group 1;" ::: "memory")

#define LDSM4(r0, r1, r2, r3, addr) \
    asm volatile("ldmatrix.sync.aligned.m8n8.x4.shared.b16 {%0,%1,%2,%3}, [%4];" \
        : "=r"(r0), "=r"(r1), "=r"(r2), "=r"(r3) : "r"(addr))

#define MMA16816(c, a, b0, b1) \
    asm volatile("mma.sync.aligned.m16n8k16.row.col.f32.bf16.bf16.f32 " \
        "{%0,%1,%2,%3}, {%4,%5,%6,%7}, {%8,%9}, {%0,%1,%2,%3};" \
        : "+f"((c)[0]), "+f"((c)[1]), "+f"((c)[2]), "+f"((c)[3]) \
        : "r"((a)[0]), "r"((a)[1]), "r"((a)[2]), "r"((a)[3]), "r"(b0), "r"(b1))

// ---------------------------------------------------------------------------
// Split fp32 -> bf16 hi/lo (vectorized, grid-stride)
// ---------------------------------------------------------------------------
__global__ void fsplit_kernel(const float4* __restrict__ in,
                              __nv_bfloat162* __restrict__ hi,
                              __nv_bfloat162* __restrict__ lo, int n4)
{
    for (int i = blockIdx.x * blockDim.x + threadIdx.x; i < n4; i += gridDim.x * blockDim.x) {
        float4 v = in[i];
        __nv_bfloat16 hx = __float2bfloat16_rn(v.x);
        __nv_bfloat16 hy = __float2bfloat16_rn(v.y);
        __nv_bfloat16 hz = __float2bfloat16_rn(v.z);
        __nv_bfloat16 hw = __float2bfloat16_rn(v.w);
        __nv_bfloat162 h0; h0.x = hx; h0.y = hy;
        __nv_bfloat162 h1; h1.x = hz; h1.y = hw;
        __nv_bfloat162 l0, l1;
        l0.x = __float2bfloat16_rn(v.x - __bfloat162float(hx));
        l0.y = __float2bfloat16_rn(v.y - __bfloat162float(hy));
        l1.x = __float2bfloat16_rn(v.z - __bfloat162float(hz));
        l1.y = __float2bfloat16_rn(v.w - __bfloat162float(hw));
        hi[i * 2 + 0] = h0; hi[i * 2 + 1] = h1;
        lo[i * 2 + 0] = l0; lo[i * 2 + 1] = l1;
    }
}

// ---------------------------------------------------------------------------
// Transpose + split W[1024][1024] -> Wt hi/lo (Wt[n][k] = W[k][n])
// ---------------------------------------------------------------------------
__global__ void wsplit_kernel(const float* __restrict__ W,
                              __nv_bfloat16* __restrict__ Th,
                              __nv_bfloat16* __restrict__ Tl)
{
    __shared__ float t[32][33];
    int bx = blockIdx.x * 32, by = blockIdx.y * 32;
    int x = threadIdx.x, y = threadIdx.y;
    #pragma unroll
    for (int d = 0; d < 32; d += 8)
        t[y + d][x] = W[(size_t)(by + y + d) * D_MODEL + bx + x];
    __syncthreads();
    #pragma unroll
    for (int d = 0; d < 32; d += 8) {
        float v = t[x][y + d];
        __nv_bfloat16 h = __float2bfloat16_rn(v);
        __nv_bfloat16 l = __float2bfloat16_rn(v - __bfloat162float(h));
        size_t o = (size_t)(bx + y + d) * D_MODEL + by + x;
        Th[o] = h; Tl[o] = l;
    }
}

// ---------------------------------------------------------------------------
// Split-bf16 GEMM via mma.sync: C[M,1024] = (Ah+Al) @ (Bh+Bl)^T + bias
// CTA tile 128x256, BK=32, 3-stage cp.async pipeline, ONE sync per chunk.
// 8 warps, warp tile 64x64 (2x4 warp grid; mt=4 x nt=8 of m16n8).
// smem/stage: A hi/lo 2x(128x80) + B hi/lo 2x(256x80) = 61440 B; 3 stages.
// ---------------------------------------------------------------------------
#define STAGE_B   61440
#define A_PLANE   10240
#define B_PLANE   20480
#define GEMM_SMEM (3 * STAGE_B)
#define KCHUNKS   32

__global__ __launch_bounds__(256, 1)
void gemm_bf16_mma(const __nv_bfloat16* __restrict__ Ah, const __nv_bfloat16* __restrict__ Al,
                   const __nv_bfloat16* __restrict__ Bh, const __nv_bfloat16* __restrict__ Bl,
                   const float* __restrict__ bias, float* __restrict__ C)
{
    extern __shared__ char smem_raw[];
    const uint32_t sbase = smem_u32(smem_raw);

    const int tid    = threadIdx.x;
    const int wid    = tid >> 5;
    const int lane   = tid & 31;
    const int warp_m = (wid >> 2) * 64;   // 0 or 64
    const int warp_n = (wid & 3) * 64;    // 0,64,128,192
    const size_t m0  = (size_t)blockIdx.y * 128;
    const size_t n0  = (size_t)blockIdx.x * 256;

    const char* sAh = (const char*)(Ah + m0 * D_MODEL);
    const char* sAl = (const char*)(Al + m0 * D_MODEL);
    const char* sBh = (const char*)(Bh + n0 * D_MODEL);
    const char* sBl = (const char*)(Bl + n0 * D_MODEL);

    // fill one stage: A planes 128 rows, B planes 256 rows; 64B data @80B stride
    auto fill = [&](int stage, int kc) {
        const uint32_t st = sbase + stage * STAGE_B;
        const size_t ko = (size_t)kc * 64;
        #pragma unroll
        for (int i = 0; i < 2; i++) {       // A hi: c in [0,512)
            int c = tid + i * 256, row = c >> 2, col = c & 3;
            cp16(st + row * 80 + col * 16, sAh + (size_t)row * 2048 + ko + col * 16);
        }
        #pragma unroll
        for (int i = 0; i < 2; i++) {       // A lo
            int c = tid + i * 256, row = c >> 2, col = c & 3;
            cp16(st + A_PLANE + row * 80 + col * 16, sAl + (size_t)row * 2048 + ko + col * 16);
        }
        #pragma unroll
        for (int i = 0; i < 4; i++) {       // B hi: 256 rows
            int c = tid + i * 256, row = c >> 2, col = c & 3;
            cp16(st + 2 * A_PLANE + row * 80 + col * 16, sBh + (size_t)row * 2048 + ko + col * 16);
        }
        #pragma unroll
        for (int i = 0; i < 4; i++) {       // B lo
            int c = tid + i * 256, row = c >> 2, col = c & 3;
            cp16(st + 2 * A_PLANE + B_PLANE + row * 80 + col * 16,
                 sBl + (size_t)row * 2048 + ko + col * 16);
        }
        CP_COMMIT();
    };

    float acc[4][8][4];
    #pragma unroll
    for (int i = 0; i < 4; i++)
        #pragma unroll
        for (int j = 0; j < 8; j++)
            #pragma unroll
            for (int q = 0; q < 4; q++) acc[i][j][q] = 0.f;

    fill(0, 0);
    fill(1, 1);

    // per-lane ldmatrix offsets (proven mapping from round 3)
    const int lr = lane & 7, g = lane >> 3;
    const uint32_t a_loff = (uint32_t)((lr + (g & 1) * 8) * 80 + (g >> 1) * 16);
    const uint32_t b_loff = (uint32_t)((lr + (g >> 1) * 8) * 80 + (g & 1) * 16);

    for (int j = 0; j < KCHUNKS; j++) {
        CP_WAIT1();              // stage j ready (stage j+1 may be in flight)
        __syncthreads();         // also: everyone done reading stage j-1
        if (j + 2 < KCHUNKS) fill((j + 2) % 3, j + 2);
        else CP_COMMIT();        // keep group counting uniform

        const uint32_t st = sbase + (j % 3) * STAGE_B;
        const uint32_t aH = st +                       warp_m * 80 + a_loff;
        const uint32_t aL = st + A_PLANE +             warp_m * 80 + a_loff;
        const uint32_t bH = st + 2 * A_PLANE +         warp_n * 80 + b_loff;
        const uint32_t bL = st + 2 * A_PLANE + B_PLANE + warp_n * 80 + b_loff;

        #pragma unroll
        for (int ks = 0; ks < 2; ks++) {
            const uint32_t ko = ks * 32;    // 16 bf16 = 32B per k16 step
            uint32_t ah_r[4][4], al_r[4][4], bh_r[16], bl_r[16];

            // issue ALL fragment loads first — MMA stream hides LDSM latency
            #pragma unroll
            for (int mt = 0; mt < 4; mt++)
                LDSM4(ah_r[mt][0], ah_r[mt][1], ah_r[mt][2], ah_r[mt][3],
                      aH + mt * (16 * 80) + ko);
            #pragma unroll
            for (int p = 0; p < 4; p++)
                LDSM4(bh_r[p*4+0], bh_r[p*4+1], bh_r[p*4+2], bh_r[p*4+3],
                      bH + p * (16 * 80) + ko);
            #pragma unroll
            for (int p = 0; p < 4; p++)
                LDSM4(bl_r[p*4+0], bl_r[p*4+1], bl_r[p*4+2], bl_r[p*4+3],
                      bL + p * (16 * 80) + ko);
            #pragma unroll
            for (int mt = 0; mt < 4; mt++)
                LDSM4(al_r[mt][0], al_r[mt][1], al_r[mt][2], al_r[mt][3],
                      aL + mt * (16 * 80) + ko);

            #pragma unroll
            for (int mt = 0; mt < 4; mt++)
                #pragma unroll
                for (int nt = 0; nt < 8; nt++)
                    MMA16816(acc[mt][nt], ah_r[mt], bh_r[nt*2], bh_r[nt*2+1]);
            #pragma unroll
            for (int mt = 0; mt < 4; mt++)
                #pragma unroll
                for (int nt = 0; nt < 8; nt++)
                    MMA16816(acc[mt][nt], ah_r[mt], bl_r[nt*2], bl_r[nt*2+1]);
            #pragma unroll
            for (int mt = 0; mt < 4; mt++)
                #pragma unroll
                for (int nt = 0; nt < 8; nt++)
                    MMA16816(acc[mt][nt], al_r[mt], bh_r[nt*2], bh_r[nt*2+1]);
        }
    }

    // epilogue: acc + bias -> C (fp32)
    #pragma unroll
    for (int mt = 0; mt < 4; mt++) {
        #pragma unroll
        for (int nt = 0; nt < 8; nt++) {
            int row0 = (int)m0 + warp_m + mt * 16 + (lane >> 2);
            int colg = (int)n0 + warp_n + nt * 8 + (lane & 3) * 2;
            float2 bv = *reinterpret_cast<const float2*>(bias + colg);
            float2 o0, o1;
            o0.x = acc[mt][nt][0] + bv.x; o0.y = acc[mt][nt][1] + bv.y;
            o1.x = acc[mt][nt][2] + bv.x; o1.y = acc[mt][nt][3] + bv.y;
            *reinterpret_cast<float2*>(C + (size_t)row0 * D_MODEL + colg) = o0;
            *reinterpret_cast<float2*>(C + (size_t)(row0 + 8) * D_MODEL + colg) = o1;
        }
    }
}

// ---------------------------------------------------------------------------
// Fused patch attention (fp32), outputs bf16 hi/lo for the O-projection.
// grid = (NUM_HEADS, NBLK), 256 threads. smem 131584 B.
// ---------------------------------------------------------------------------
__global__ __launch_bounds__(256, 1)
void attn_kernel()
{
    extern __shared__ float sm[];
    float* Ks = sm;
    float* Vs = Ks + 128 * 64;
    float* S  = Vs + 128 * 64;       // [128][129]

    const int h   = blockIdx.x;
    const int pb  = blockIdx.y;
    const int tid = threadIdx.x;
    const size_t base = (size_t)pb * 128 * D_MODEL + (size_t)h * D_HEAD;

    for (int i = tid; i < 128 * 16; i += 256) {
        int row = i >> 4;
        int c   = i & 15;
        size_t gidx = base + (size_t)row * D_MODEL + c * 4;
        *reinterpret_cast<float4*>(&Ks[row * 64 + c * 4]) =
            *reinterpret_cast<const float4*>(&g_K[gidx]);
        *reinterpret_cast<float4*>(&Vs[row * 64 + c * 4]) =
            *reinterpret_cast<const float4*>(&g_V[gidx]);
    }
    __syncthreads();

    const int r    = tid >> 1;
    const int half = tid & 1;

    float q[64];
    {
        const float* qp = &g_Q[base + (size_t)r * D_MODEL];
        #pragma unroll
        for (int c = 0; c < 16; c++) {
            float4 v = *reinterpret_cast<const float4*>(qp + c * 4);
            q[c * 4 + 0] = v.x * 0.125f;
            q[c * 4 + 1] = v.y * 0.125f;
            q[c * 4 + 2] = v.z * 0.125f;
            q[c * 4 + 3] = v.w * 0.125f;
        }
    }

    #pragma unroll 1
    for (int j0 = 0; j0 < 64; j0++) {
        int j = half * 64 + j0;
        const float* kp = &Ks[j * 64];
        float s0 = 0.f, s1 = 0.f, s2 = 0.f, s3 = 0.f;
        #pragma unroll
        for (int c = 0; c < 16; c++) {
            float4 kv = *reinterpret_cast<const float4*>(kp + c * 4);
            s0 += q[c * 4 + 0] * kv.x;
            s1 += q[c * 4 + 1] * kv.y;
            s2 += q[c * 4 + 2] * kv.z;
            s3 += q[c * 4 + 3] * kv.w;
        }
        S[r * 129 + j] = (s0 + s1) + (s2 + s3);
    }
    __syncthreads();

    float mx = -CUDART_INF_F;
    #pragma unroll 4
    for (int j0 = 0; j0 < 64; j0++)
        mx = fmaxf(mx, S[r * 129 + half * 64 + j0]);
    mx = fmaxf(mx, __shfl_xor_sync(0xffffffffu, mx, 1));

    float l = 0.f;
    #pragma unroll 4
    for (int j0 = 0; j0 < 64; j0++) {
        float e = __expf(S[r * 129 + half * 64 + j0] - mx);
        S[r * 129 + half * 64 + j0] = e;
        l += e;
    }
    l += __shfl_xor_sync(0xffffffffu, l, 1);
    float inv = 1.0f / l;
    __syncthreads();

    float acc[32];
    #pragma unroll
    for (int c = 0; c < 32; c++) acc[c] = 0.f;

    #pragma unroll 1
    for (int j = 0; j < 128; j++) {
        float w = S[r * 129 + j];
        const float* vp = &Vs[j * 64 + half * 32];
        #pragma unroll
        for (int c = 0; c < 8; c++) {
            float4 vv = *reinterpret_cast<const float4*>(vp + c * 4);
            acc[c * 4 + 0] += w * vv.x;
            acc[c * 4 + 1] += w * vv.y;
            acc[c * 4 + 2] += w * vv.z;
            acc[c * 4 + 3] += w * vv.w;
        }
    }

    size_t obase = base + (size_t)r * D_MODEL + half * 32;
    __nv_bfloat162* oh = reinterpret_cast<__nv_bfloat162*>(&g_Ah[obase]);
    __nv_bfloat162* ol = reinterpret_cast<__nv_bfloat162*>(&g_Al[obase]);
    #pragma unroll
    for (int c = 0; c < 16; c++) {
        float o0 = acc[c * 2 + 0] * inv;
        float o1 = acc[c * 2 + 1] * inv;
        __nv_bfloat16 h0 = __float2bfloat16_rn(o0);
        __nv_bfloat16 h1 = __float2bfloat16_rn(o1);
        __nv_bfloat162 hp; hp.x = h0; hp.y = h1;
        __nv_bfloat162 lp;
        lp.x = __float2bfloat16_rn(o0 - __bfloat162float(h0));
        lp.y = __float2bfloat16_rn(o1 - __bfloat162float(h1));
        oh[c] = hp;
        ol[c] = lp;
    }
}

// ---------------------------------------------------------------------------
extern "C" void kernel_launch(void* const* d_in, const int* in_sizes, int n_in,
                              void* d_out, int out_size)
{
    const float* x  = (const float*)d_in[0];
    // d_in[1] = coords (unused by reference)
    const float* Wq = (const float*)d_in[2];
    const float* bq = (const float*)d_in[3];
    const float* Wk = (const float*)d_in[4];
    const float* bk = (const float*)d_in[5];
    const float* Wv = (const float*)d_in[6];
    const float* bv = (const float*)d_in[7];
    const float* Wo = (const float*)d_in[8];
    const float* bo = (const float*)d_in[9];
    float* out = (float*)d_out;

    __nv_bfloat16 *xh, *xl, *Ah, *Al;
    __nv_bfloat16 *wqh, *wql, *wkh, *wkl, *wvh, *wvl, *woh, *wol;
    float *pQ, *pK, *pV;
    cudaGetSymbolAddress((void**)&xh,  g_xh);
    cudaGetSymbolAddress((void**)&xl,  g_xl);
    cudaGetSymbolAddress((void**)&Ah,  g_Ah);
    cudaGetSymbolAddress((void**)&Al,  g_Al);
    cudaGetSymbolAddress((void**)&pQ,  g_Q);
    cudaGetSymbolAddress((void**)&pK,  g_K);
    cudaGetSymbolAddress((void**)&pV,  g_V);
    cudaGetSymbolAddress((void**)&wqh, g_wqh);
    cudaGetSymbolAddress((void**)&wql, g_wql);
    cudaGetSymbolAddress((void**)&wkh, g_wkh);
    cudaGetSymbolAddress((void**)&wkl, g_wkl);
    cudaGetSymbolAddress((void**)&wvh, g_wvh);
    cudaGetSymbolAddress((void**)&wvl, g_wvl);
    cudaGetSymbolAddress((void**)&woh, g_woh);
    cudaGetSymbolAddress((void**)&wol, g_wol);

    cudaFuncSetAttribute(gemm_bf16_mma, cudaFuncAttributeMaxDynamicSharedMemorySize, GEMM_SMEM);
    static const size_t attn_smem = (128 * 64 * 2 + 128 * 129) * sizeof(float);
    cudaFuncSetAttribute(attn_kernel, cudaFuncAttributeMaxDynamicSharedMemorySize, (int)attn_smem);

    // 1. split x -> bf16 hi/lo
    fsplit_kernel<<<8192, 256>>>((const float4*)x, (__nv_bfloat162*)xh, (__nv_bfloat162*)xl,
                                 M_TOTAL * D_MODEL / 4);
    // 2. transpose + split weights
    dim3 wgrid(32, 32), wblk(32, 8);
    wsplit_kernel<<<wgrid, wblk>>>(Wq, wqh, wql);
    wsplit_kernel<<<wgrid, wblk>>>(Wk, wkh, wkl);
    wsplit_kernel<<<wgrid, wblk>>>(Wv, wvh, wvl);
    wsplit_kernel<<<wgrid, wblk>>>(Wo, woh, wol);

    // 3. Q/K/V projections (tensor cores)
    dim3 ggrid(D_MODEL / 256, M_TOTAL / 128);   // (4, 256)
    gemm_bf16_mma<<<ggrid, 256, GEMM_SMEM>>>(xh, xl, wqh, wql, bq, pQ);
    gemm_bf16_mma<<<ggrid, 256, GEMM_SMEM>>>(xh, xl, wkh, wkl, bk, pK);
    gemm_bf16_mma<<<ggrid, 256, GEMM_SMEM>>>(xh, xl, wvh, wvl, bv, pV);

    // 4. attention (writes bf16 hi/lo)
    dim3 agrid(NUM_HEADS, NBLK);
    attn_kernel<<<agrid, 256, attn_smem>>>();

    // 5. output projection
    gemm_bf16_mma<<<ggrid, 256, GEMM_SMEM>>>(Ah, Al, woh, wol, bo, out);
}

// round 6
// speedup vs baseline: 2.8936x; 1.3517x over previous
#include <cuda_runtime.h>
#include <cuda_bf16.h>
#include <math_constants.h>
#include <cstdint>

#define D_MODEL   1024
#define NUM_HEADS 16
#define D_HEAD    64
#define PATCH     128
#define BATCH     4
#define SEQ       8192
#define M_TOTAL   (BATCH * SEQ)          // 32768 rows
#define NBLK      (M_TOTAL / PATCH)      // 256 patch blocks

// ---------------------------------------------------------------------------
// Scratch (static device globals — no runtime allocation)
// ---------------------------------------------------------------------------
__device__ __nv_bfloat16 g_xh[(size_t)M_TOTAL * D_MODEL];
__device__ __nv_bfloat16 g_xl[(size_t)M_TOTAL * D_MODEL];
__device__ __nv_bfloat16 g_Qh[(size_t)M_TOTAL * D_MODEL];
__device__ __nv_bfloat16 g_Ql[(size_t)M_TOTAL * D_MODEL];
__device__ __nv_bfloat16 g_Kh[(size_t)M_TOTAL * D_MODEL];
__device__ __nv_bfloat16 g_Kl[(size_t)M_TOTAL * D_MODEL];
__device__ __nv_bfloat16 g_Vh[(size_t)M_TOTAL * D_MODEL];
__device__ __nv_bfloat16 g_Vl[(size_t)M_TOTAL * D_MODEL];
__device__ __nv_bfloat16 g_Ah[(size_t)M_TOTAL * D_MODEL];
__device__ __nv_bfloat16 g_Al[(size_t)M_TOTAL * D_MODEL];
// transposed+split weights (W^T: row n, col k) — bf16 hi/lo
__device__ __nv_bfloat16 g_wqh[D_MODEL * D_MODEL];
__device__ __nv_bfloat16 g_wql[D_MODEL * D_MODEL];
__device__ __nv_bfloat16 g_wkh[D_MODEL * D_MODEL];
__device__ __nv_bfloat16 g_wkl[D_MODEL * D_MODEL];
__device__ __nv_bfloat16 g_wvh[D_MODEL * D_MODEL];
__device__ __nv_bfloat16 g_wvl[D_MODEL * D_MODEL];
__device__ __nv_bfloat16 g_woh[D_MODEL * D_MODEL];
__device__ __nv_bfloat16 g_wol[D_MODEL * D_MODEL];

// ---------------------------------------------------------------------------
// PTX helpers (base ISA only)
// ---------------------------------------------------------------------------
__device__ __forceinline__ uint32_t smem_u32(const void* p) {
    uint32_t a;
    asm("{ .reg .u64 t; cvta.to.shared.u64 t, %1; cvt.u32.u64 %0, t; }" : "=r"(a) : "l"(p));
    return a;
}
__device__ __forceinline__ void cp16(uint32_t dst, const void* src) {
    asm volatile("cp.async.cg.shared.global [%0], [%1], 16;" :: "r"(dst), "l"(src));
}
#define CP_COMMIT() asm volatile("cp.async.commit_group;" ::: "memory")
#define CP_WAIT1()  asm volatile("cp.async.wait_group 1;" ::: "memory")
#define CP_WAIT0()  asm volatile("cp.async.wait_group 0;" ::: "memory")

#define LDSM4(r0, r1, r2, r3, addr) \
    asm volatile("ldmatrix.sync.aligned.m8n8.x4.shared.b16 {%0,%1,%2,%3}, [%4];" \
        : "=r"(r0), "=r"(r1), "=r"(r2), "=r"(r3) : "r"(addr))

#define MMA16816(c, a, b0, b1) \
    asm volatile("mma.sync.aligned.m16n8k16.row.col.f32.bf16.bf16.f32 " \
        "{%0,%1,%2,%3}, {%4,%5,%6,%7}, {%8,%9}, {%0,%1,%2,%3};" \
        : "+f"((c)[0]), "+f"((c)[1]), "+f"((c)[2]), "+f"((c)[3]) \
        : "r"((a)[0]), "r"((a)[1]), "r"((a)[2]), "r"((a)[3]), "r"(b0), "r"(b1))

// split a float pair into packed bf16x2 hi and lo words
__device__ __forceinline__ void packsplit(float x, float y, uint32_t& hi, uint32_t& lo) {
    __nv_bfloat16 hx = __float2bfloat16_rn(x);
    __nv_bfloat16 hy = __float2bfloat16_rn(y);
    __nv_bfloat16 lx = __float2bfloat16_rn(x - __bfloat162float(hx));
    __nv_bfloat16 ly = __float2bfloat16_rn(y - __bfloat162float(hy));
    hi = (uint32_t)__bfloat16_as_ushort(hx) | ((uint32_t)__bfloat16_as_ushort(hy) << 16);
    lo = (uint32_t)__bfloat16_as_ushort(lx) | ((uint32_t)__bfloat16_as_ushort(ly) << 16);
}

// fast exp2 on FMA pipe (t <= 0), rel err ~1e-6
__device__ __forceinline__ float fexp2(float t) {
    t = fmaxf(t, -100.f);
    float fi = floorf(t);
    float f  = t - fi;
    float p  = 1.0178086e-5f;
    p = fmaf(p, f, 1.5403530e-4f);
    p = fmaf(p, f, 1.3333558e-3f);
    p = fmaf(p, f, 9.6181291e-3f);
    p = fmaf(p, f, 5.5504109e-2f);
    p = fmaf(p, f, 2.4022651e-1f);
    p = fmaf(p, f, 6.9314718e-1f);
    p = fmaf(p, f, 1.0f);
    return p * __int_as_float(((int)fi + 127) << 23);
}

// ---------------------------------------------------------------------------
// Split fp32 -> bf16 hi/lo (vectorized, grid-stride)
// ---------------------------------------------------------------------------
__global__ void fsplit_kernel(const float4* __restrict__ in,
                              __nv_bfloat162* __restrict__ hi,
                              __nv_bfloat162* __restrict__ lo, int n4)
{
    for (int i = blockIdx.x * blockDim.x + threadIdx.x; i < n4; i += gridDim.x * blockDim.x) {
        float4 v = in[i];
        uint32_t h0, l0, h1, l1;
        packsplit(v.x, v.y, h0, l0);
        packsplit(v.z, v.w, h1, l1);
        reinterpret_cast<uint32_t*>(hi)[i * 2 + 0] = h0;
        reinterpret_cast<uint32_t*>(hi)[i * 2 + 1] = h1;
        reinterpret_cast<uint32_t*>(lo)[i * 2 + 0] = l0;
        reinterpret_cast<uint32_t*>(lo)[i * 2 + 1] = l1;
    }
}

// ---------------------------------------------------------------------------
// Transpose + split W[1024][1024] -> Wt hi/lo (Wt[n][k] = W[k][n])
// ---------------------------------------------------------------------------
__global__ void wsplit_kernel(const float* __restrict__ W,
                              __nv_bfloat16* __restrict__ Th,
                              __nv_bfloat16* __restrict__ Tl)
{
    __shared__ float t[32][33];
    int bx = blockIdx.x * 32, by = blockIdx.y * 32;
    int x = threadIdx.x, y = threadIdx.y;
    #pragma unroll
    for (int d = 0; d < 32; d += 8)
        t[y + d][x] = W[(size_t)(by + y + d) * D_MODEL + bx + x];
    __syncthreads();
    #pragma unroll
    for (int d = 0; d < 32; d += 8) {
        float v = t[x][y + d];
        __nv_bfloat16 h = __float2bfloat16_rn(v);
        __nv_bfloat16 l = __float2bfloat16_rn(v - __bfloat162float(h));
        size_t o = (size_t)(bx + y + d) * D_MODEL + by + x;
        Th[o] = h; Tl[o] = l;
    }
}

// ---------------------------------------------------------------------------
// Split-bf16 GEMM: C = (Ah+Al)(Bh+Bl)^T + bias.  CTA 128x256, BK=32, 3 stages.
// SPLIT=true  -> writes bf16 hi/lo planes (for Q/K/V)
// SPLIT=false -> writes fp32 (final output)
// ---------------------------------------------------------------------------
#define STAGE_B   61440
#define A_PLANE   10240
#define B_PLANE   20480
#define GEMM_SMEM (3 * STAGE_B)
#define KCHUNKS   32

template<bool SPLIT>
__global__ __launch_bounds__(256, 1)
void gemm_bf16_mma(const __nv_bfloat16* __restrict__ Ah, const __nv_bfloat16* __restrict__ Al,
                   const __nv_bfloat16* __restrict__ Bh, const __nv_bfloat16* __restrict__ Bl,
                   const float* __restrict__ bias,
                   float* __restrict__ C,
                   __nv_bfloat16* __restrict__ Ch, __nv_bfloat16* __restrict__ Cl)
{
    extern __shared__ char smem_raw[];
    const uint32_t sbase = smem_u32(smem_raw);

    const int tid    = threadIdx.x;
    const int wid    = tid >> 5;
    const int lane   = tid & 31;
    const int warp_m = (wid >> 2) * 64;
    const int warp_n = (wid & 3) * 64;
    const size_t m0  = (size_t)blockIdx.y * 128;
    const size_t n0  = (size_t)blockIdx.x * 256;

    const char* sAh = (const char*)(Ah + m0 * D_MODEL);
    const char* sAl = (const char*)(Al + m0 * D_MODEL);
    const char* sBh = (const char*)(Bh + n0 * D_MODEL);
    const char* sBl = (const char*)(Bl + n0 * D_MODEL);

    auto fill = [&](int stage, int kc) {
        const uint32_t st = sbase + stage * STAGE_B;
        const size_t ko = (size_t)kc * 64;
        #pragma unroll
        for (int i = 0; i < 2; i++) {
            int c = tid + i * 256, row = c >> 2, col = c & 3;
            cp16(st + row * 80 + col * 16, sAh + (size_t)row * 2048 + ko + col * 16);
        }
        #pragma unroll
        for (int i = 0; i < 2; i++) {
            int c = tid + i * 256, row = c >> 2, col = c & 3;
            cp16(st + A_PLANE + row * 80 + col * 16, sAl + (size_t)row * 2048 + ko + col * 16);
        }
        #pragma unroll
        for (int i = 0; i < 4; i++) {
            int c = tid + i * 256, row = c >> 2, col = c & 3;
            cp16(st + 2 * A_PLANE + row * 80 + col * 16, sBh + (size_t)row * 2048 + ko + col * 16);
        }
        #pragma unroll
        for (int i = 0; i < 4; i++) {
            int c = tid + i * 256, row = c >> 2, col = c & 3;
            cp16(st + 2 * A_PLANE + B_PLANE + row * 80 + col * 16,
                 sBl + (size_t)row * 2048 + ko + col * 16);
        }
        CP_COMMIT();
    };

    float acc[4][8][4];
    #pragma unroll
    for (int i = 0; i < 4; i++)
        #pragma unroll
        for (int j = 0; j < 8; j++)
            #pragma unroll
            for (int q = 0; q < 4; q++) acc[i][j][q] = 0.f;

    fill(0, 0);
    fill(1, 1);

    const int lr = lane & 7, g = lane >> 3;
    const uint32_t a_loff = (uint32_t)((lr + (g & 1) * 8) * 80 + (g >> 1) * 16);
    const uint32_t b_loff = (uint32_t)((lr + (g >> 1) * 8) * 80 + (g & 1) * 16);

    for (int j = 0; j < KCHUNKS; j++) {
        CP_WAIT1();
        __syncthreads();
        if (j + 2 < KCHUNKS) fill((j + 2) % 3, j + 2);
        else CP_COMMIT();

        const uint32_t st = sbase + (j % 3) * STAGE_B;
        const uint32_t aH = st +                         warp_m * 80 + a_loff;
        const uint32_t aL = st + A_PLANE +               warp_m * 80 + a_loff;
        const uint32_t bH = st + 2 * A_PLANE +           warp_n * 80 + b_loff;
        const uint32_t bL = st + 2 * A_PLANE + B_PLANE + warp_n * 80 + b_loff;

        #pragma unroll
        for (int ks = 0; ks < 2; ks++) {
            const uint32_t ko = ks * 32;
            uint32_t ah_r[4][4], al_r[4][4], bh_r[16], bl_r[16];

            #pragma unroll
            for (int mt = 0; mt < 4; mt++)
                LDSM4(ah_r[mt][0], ah_r[mt][1], ah_r[mt][2], ah_r[mt][3],
                      aH + mt * (16 * 80) + ko);
            #pragma unroll
            for (int p = 0; p < 4; p++)
                LDSM4(bh_r[p*4+0], bh_r[p*4+1], bh_r[p*4+2], bh_r[p*4+3],
                      bH + p * (16 * 80) + ko);
            #pragma unroll
            for (int p = 0; p < 4; p++)
                LDSM4(bl_r[p*4+0], bl_r[p*4+1], bl_r[p*4+2], bl_r[p*4+3],
                      bL + p * (16 * 80) + ko);
            #pragma unroll
            for (int mt = 0; mt < 4; mt++)
                LDSM4(al_r[mt][0], al_r[mt][1], al_r[mt][2], al_r[mt][3],
                      aL + mt * (16 * 80) + ko);

            #pragma unroll
            for (int mt = 0; mt < 4; mt++)
                #pragma unroll
                for (int nt = 0; nt < 8; nt++)
                    MMA16816(acc[mt][nt], ah_r[mt], bh_r[nt*2], bh_r[nt*2+1]);
            #pragma unroll
            for (int mt = 0; mt < 4; mt++)
                #pragma unroll
                for (int nt = 0; nt < 8; nt++)
                    MMA16816(acc[mt][nt], ah_r[mt], bl_r[nt*2], bl_r[nt*2+1]);
            #pragma unroll
            for (int mt = 0; mt < 4; mt++)
                #pragma unroll
                for (int nt = 0; nt < 8; nt++)
                    MMA16816(acc[mt][nt], al_r[mt], bh_r[nt*2], bh_r[nt*2+1]);
        }
    }

    #pragma unroll
    for (int mt = 0; mt < 4; mt++) {
        #pragma unroll
        for (int nt = 0; nt < 8; nt++) {
            int row0 = (int)m0 + warp_m + mt * 16 + (lane >> 2);
            int colg = (int)n0 + warp_n + nt * 8 + (lane & 3) * 2;
            float2 bv = *reinterpret_cast<const float2*>(bias + colg);
            float o00 = acc[mt][nt][0] + bv.x, o01 = acc[mt][nt][1] + bv.y;
            float o10 = acc[mt][nt][2] + bv.x, o11 = acc[mt][nt][3] + bv.y;
            size_t off0 = (size_t)row0 * D_MODEL + colg;
            size_t off1 = off0 + 8 * D_MODEL;
            if constexpr (SPLIT) {
                uint32_t hw, lw;
                packsplit(o00, o01, hw, lw);
                *reinterpret_cast<uint32_t*>(Ch + off0) = hw;
                *reinterpret_cast<uint32_t*>(Cl + off0) = lw;
                packsplit(o10, o11, hw, lw);
                *reinterpret_cast<uint32_t*>(Ch + off1) = hw;
                *reinterpret_cast<uint32_t*>(Cl + off1) = lw;
            } else {
                float2 a{o00, o01}, b{o10, o11};
                *reinterpret_cast<float2*>(C + off0) = a;
                *reinterpret_cast<float2*>(C + off1) = b;
            }
        }
    }
}

// ---------------------------------------------------------------------------
// Tensor-core patch attention (split-bf16, fragment softmax, poly exp).
// grid = (NUM_HEADS, NBLK), 256 threads (8 warps; warp w owns rows 16w..16w+15).
// smem: Qh,Ql,Kh,Kl [128][72] bf16 + Vth,Vtl [64][136] bf16 = 108544 B.
// ---------------------------------------------------------------------------
#define QK_STRIDE_B 144          // 72 bf16
#define VT_STRIDE_B 272          // 136 bf16
#define OFF_QH 0
#define OFF_QL 18432
#define OFF_KH 36864
#define OFF_KL 55296
#define OFF_VH 73728
#define OFF_VL 91136
#define ATTN_SMEM 108544

__global__ __launch_bounds__(256, 2)
void attn_mma_kernel()
{
    extern __shared__ char smc[];
    const uint32_t sb = smem_u32(smc);

    const int h   = blockIdx.x;
    const int pb  = blockIdx.y;
    const int tid = threadIdx.x;
    const int wid = tid >> 5;
    const int lane = tid & 31;
    const size_t base = (size_t)pb * 128 * D_MODEL + (size_t)h * D_HEAD;

    // stage Q,K hi/lo via cp.async (rows of 64 bf16 = 128B = 8 x 16B)
    {
        const char* gp[4] = {
            (const char*)(g_Qh + base), (const char*)(g_Ql + base),
            (const char*)(g_Kh + base), (const char*)(g_Kl + base) };
        const uint32_t sp[4] = { sb + OFF_QH, sb + OFF_QL, sb + OFF_KH, sb + OFF_KL };
        #pragma unroll
        for (int pl = 0; pl < 4; pl++)
            #pragma unroll
            for (int i = 0; i < 4; i++) {
                int idx = tid + i * 256;
                int row = idx >> 3, ch = idx & 7;
                cp16(sp[pl] + row * QK_STRIDE_B + ch * 16,
                     gp[pl] + (size_t)row * 2048 + ch * 16);
            }
        CP_COMMIT();
    }
    // V transpose into smem: Vt[d][kv]
    for (int i = tid; i < 128 * 64; i += 256) {
        int kv = i >> 6, d = i & 63;
        size_t go = base + (size_t)kv * D_MODEL + d;
        *reinterpret_cast<__nv_bfloat16*>(smc + OFF_VH + d * VT_STRIDE_B + kv * 2) = g_Vh[go];
        *reinterpret_cast<__nv_bfloat16*>(smc + OFF_VL + d * VT_STRIDE_B + kv * 2) = g_Vl[go];
    }
    CP_WAIT0();
    __syncthreads();

    const int lr = lane & 7, g = lane >> 3;
    const uint32_t a_off = (uint32_t)((lr + (g & 1) * 8) * QK_STRIDE_B + (g >> 1) * 16);
    const uint32_t b_off = (uint32_t)((lr + (g >> 1) * 8) * QK_STRIDE_B + (g & 1) * 16);
    const uint32_t v_off = (uint32_t)((lr + (g >> 1) * 8) * VT_STRIDE_B + (g & 1) * 16);

    // ---- S = Q K^T (split bf16, 3 passes) ----
    float cf[16][4];
    #pragma unroll
    for (int i = 0; i < 16; i++)
        #pragma unroll
        for (int q = 0; q < 4; q++) cf[i][q] = 0.f;

    const uint32_t qh0 = sb + OFF_QH + wid * (16 * QK_STRIDE_B) + a_off;
    const uint32_t ql0 = sb + OFF_QL + wid * (16 * QK_STRIDE_B) + a_off;

    #pragma unroll
    for (int ks = 0; ks < 4; ks++) {
        const uint32_t ko = ks * 32;
        uint32_t aq[4], bq[4];
        LDSM4(aq[0], aq[1], aq[2], aq[3], qh0 + ko);
        LDSM4(bq[0], bq[1], bq[2], bq[3], ql0 + ko);
        #pragma unroll
        for (int p = 0; p < 8; p++) {
            uint32_t kh[4], kl[4];
            LDSM4(kh[0], kh[1], kh[2], kh[3], sb + OFF_KH + p * (16 * QK_STRIDE_B) + b_off + ko);
            LDSM4(kl[0], kl[1], kl[2], kl[3], sb + OFF_KL + p * (16 * QK_STRIDE_B) + b_off + ko);
            MMA16816(cf[2*p],   aq, kh[0], kh[1]);
            MMA16816(cf[2*p+1], aq, kh[2], kh[3]);
            MMA16816(cf[2*p],   aq, kl[0], kl[1]);
            MMA16816(cf[2*p+1], aq, kl[2], kl[3]);
            MMA16816(cf[2*p],   bq, kh[0], kh[1]);
            MMA16816(cf[2*p+1], bq, kh[2], kh[3]);
        }
    }

    // ---- fragment softmax ----
    float mx0 = -CUDART_INF_F, mx1 = -CUDART_INF_F;
    #pragma unroll
    for (int nt = 0; nt < 16; nt++) {
        mx0 = fmaxf(mx0, fmaxf(cf[nt][0], cf[nt][1]));
        mx1 = fmaxf(mx1, fmaxf(cf[nt][2], cf[nt][3]));
    }
    mx0 = fmaxf(mx0, __shfl_xor_sync(0xffffffffu, mx0, 1));
    mx0 = fmaxf(mx0, __shfl_xor_sync(0xffffffffu, mx0, 2));
    mx1 = fmaxf(mx1, __shfl_xor_sync(0xffffffffu, mx1, 1));
    mx1 = fmaxf(mx1, __shfl_xor_sync(0xffffffffu, mx1, 2));

    const float CS = 0.125f * 1.4426950408889634f;   // log2(e)/sqrt(64)
    float l0 = 0.f, l1 = 0.f;
    #pragma unroll
    for (int nt = 0; nt < 16; nt++) {
        float p0 = fexp2((cf[nt][0] - mx0) * CS);
        float p1 = fexp2((cf[nt][1] - mx0) * CS);
        float p2 = fexp2((cf[nt][2] - mx1) * CS);
        float p3 = fexp2((cf[nt][3] - mx1) * CS);
        cf[nt][0] = p0; cf[nt][1] = p1; cf[nt][2] = p2; cf[nt][3] = p3;
        l0 += p0 + p1; l1 += p2 + p3;
    }
    l0 += __shfl_xor_sync(0xffffffffu, l0, 1);
    l0 += __shfl_xor_sync(0xffffffffu, l0, 2);
    l1 += __shfl_xor_sync(0xffffffffu, l1, 1);
    l1 += __shfl_xor_sync(0xffffffffu, l1, 2);
    const float inv0 = 1.f / l0, inv1 = 1.f / l1;

    // ---- O = P V (split bf16, 3 passes) ----
    float of[8][4];
    #pragma unroll
    for (int i = 0; i < 8; i++)
        #pragma unroll
        for (int q = 0; q < 4; q++) of[i][q] = 0.f;

    #pragma unroll
    for (int kt = 0; kt < 8; kt++) {
        uint32_t ah[4], al[4];
        packsplit(cf[2*kt][0],   cf[2*kt][1],   ah[0], al[0]);
        packsplit(cf[2*kt][2],   cf[2*kt][3],   ah[1], al[1]);
        packsplit(cf[2*kt+1][0], cf[2*kt+1][1], ah[2], al[2]);
        packsplit(cf[2*kt+1][2], cf[2*kt+1][3], ah[3], al[3]);
        const uint32_t ko = kt * 32;
        #pragma unroll
        for (int np = 0; np < 4; np++) {
            uint32_t vh[4], vl[4];
            LDSM4(vh[0], vh[1], vh[2], vh[3], sb + OFF_VH + np * (16 * VT_STRIDE_B) + v_off + ko);
            LDSM4(vl[0], vl[1], vl[2], vl[3], sb + OFF_VL + np * (16 * VT_STRIDE_B) + v_off + ko);
            MMA16816(of[2*np],   ah, vh[0], vh[1]);
            MMA16816(of[2*np+1], ah, vh[2], vh[3]);
            MMA16816(of[2*np],   ah, vl[0], vl[1]);
            MMA16816(of[2*np+1], ah, vl[2], vl[3]);
            MMA16816(of[2*np],   al, vh[0], vh[1]);
            MMA16816(of[2*np+1], al, vh[2], vh[3]);
        }
    }

    // ---- write A = softmax(S)V as bf16 hi/lo ----
    const int row  = pb * 128 + wid * 16 + (lane >> 2);
    const int colb = h * 64 + (lane & 3) * 2;
    #pragma unroll
    for (int nt = 0; nt < 8; nt++) {
        size_t off0 = (size_t)row * D_MODEL + colb + nt * 8;
        size_t off1 = off0 + 8 * D_MODEL;
        uint32_t hw, lw;
        packsplit(of[nt][0] * inv0, of[nt][1] * inv0, hw, lw);
        *reinterpret_cast<uint32_t*>(g_Ah + off0) = hw;
        *reinterpret_cast<uint32_t*>(g_Al + off0) = lw;
        packsplit(of[nt][2] * inv1, of[nt][3] * inv1, hw, lw);
        *reinterpret_cast<uint32_t*>(g_Ah + off1) = hw;
        *reinterpret_cast<uint32_t*>(g_Al + off1) = lw;
    }
}

// ---------------------------------------------------------------------------
extern "C" void kernel_launch(void* const* d_in, const int* in_sizes, int n_in,
                              void* d_out, int out_size)
{
    const float* x  = (const float*)d_in[0];
    // d_in[1] = coords (unused by reference)
    const float* Wq = (const float*)d_in[2];
    const float* bq = (const float*)d_in[3];
    const float* Wk = (const float*)d_in[4];
    const float* bk = (const float*)d_in[5];
    const float* Wv = (const float*)d_in[6];
    const float* bv = (const float*)d_in[7];
    const float* Wo = (const float*)d_in[8];
    const float* bo = (const float*)d_in[9];
    float* out = (float*)d_out;

    __nv_bfloat16 *xh, *xl, *Qh, *Ql, *Kh, *Kl, *Vh, *Vl, *Ah, *Al;
    __nv_bfloat16 *wqh, *wql, *wkh, *wkl, *wvh, *wvl, *woh, *wol;
    cudaGetSymbolAddress((void**)&xh,  g_xh);
    cudaGetSymbolAddress((void**)&xl,  g_xl);
    cudaGetSymbolAddress((void**)&Qh,  g_Qh);
    cudaGetSymbolAddress((void**)&Ql,  g_Ql);
    cudaGetSymbolAddress((void**)&Kh,  g_Kh);
    cudaGetSymbolAddress((void**)&Kl,  g_Kl);
    cudaGetSymbolAddress((void**)&Vh,  g_Vh);
    cudaGetSymbolAddress((void**)&Vl,  g_Vl);
    cudaGetSymbolAddress((void**)&Ah,  g_Ah);
    cudaGetSymbolAddress((void**)&Al,  g_Al);
    cudaGetSymbolAddress((void**)&wqh, g_wqh);
    cudaGetSymbolAddress((void**)&wql, g_wql);
    cudaGetSymbolAddress((void**)&wkh, g_wkh);
    cudaGetSymbolAddress((void**)&wkl, g_wkl);
    cudaGetSymbolAddress((void**)&wvh, g_wvh);
    cudaGetSymbolAddress((void**)&wvl, g_wvl);
    cudaGetSymbolAddress((void**)&woh, g_woh);
    cudaGetSymbolAddress((void**)&wol, g_wol);

    cudaFuncSetAttribute(gemm_bf16_mma<true>,  cudaFuncAttributeMaxDynamicSharedMemorySize, GEMM_SMEM);
    cudaFuncSetAttribute(gemm_bf16_mma<false>, cudaFuncAttributeMaxDynamicSharedMemorySize, GEMM_SMEM);
    cudaFuncSetAttribute(attn_mma_kernel, cudaFuncAttributeMaxDynamicSharedMemorySize, ATTN_SMEM);

    // 1. split x -> bf16 hi/lo
    fsplit_kernel<<<8192, 256>>>((const float4*)x, (__nv_bfloat162*)xh, (__nv_bfloat162*)xl,
                                 M_TOTAL * D_MODEL / 4);
    // 2. transpose + split weights
    dim3 wgrid(32, 32), wblk(32, 8);
    wsplit_kernel<<<wgrid, wblk>>>(Wq, wqh, wql);
    wsplit_kernel<<<wgrid, wblk>>>(Wk, wkh, wkl);
    wsplit_kernel<<<wgrid, wblk>>>(Wv, wvh, wvl);
    wsplit_kernel<<<wgrid, wblk>>>(Wo, woh, wol);

    // 3. Q/K/V projections — epilogue emits bf16 hi/lo
    dim3 ggrid(D_MODEL / 256, M_TOTAL / 128);   // (4, 256)
    gemm_bf16_mma<true><<<ggrid, 256, GEMM_SMEM>>>(xh, xl, wqh, wql, bq, nullptr, Qh, Ql);
    gemm_bf16_mma<true><<<ggrid, 256, GEMM_SMEM>>>(xh, xl, wkh, wkl, bk, nullptr, Kh, Kl);
    gemm_bf16_mma<true><<<ggrid, 256, GEMM_SMEM>>>(xh, xl, wvh, wvl, bv, nullptr, Vh, Vl);

    // 4. tensor-core attention (writes bf16 hi/lo A)
    dim3 agrid(NUM_HEADS, NBLK);
    attn_mma_kernel<<<agrid, 256, ATTN_SMEM>>>();

    // 5. output projection (fp32 out)
    gemm_bf16_mma<false><<<ggrid, 256, GEMM_SMEM>>>(Ah, Al, woh, wol, bo, out, nullptr, nullptr);
}

// round 7
// speedup vs baseline: 2.9082x; 1.0051x over previous
#include <cuda_runtime.h>
#include <cuda_fp16.h>
#include <math_constants.h>
#include <cstdint>

#define D_MODEL   1024
#define NUM_HEADS 16
#define D_HEAD    64
#define PATCH     128
#define BATCH     4
#define SEQ       8192
#define M_TOTAL   (BATCH * SEQ)          // 32768 rows
#define NBLK      (M_TOTAL / PATCH)      // 256 patch blocks

// ---------------------------------------------------------------------------
// Scratch (static device globals — no runtime allocation)
// ---------------------------------------------------------------------------
__device__ __half g_xh[(size_t)M_TOTAL * D_MODEL];
__device__ __half g_xl[(size_t)M_TOTAL * D_MODEL];
__device__ __half g_Qh[(size_t)M_TOTAL * D_MODEL];
__device__ __half g_Ql[(size_t)M_TOTAL * D_MODEL];
__device__ __half g_Kh[(size_t)M_TOTAL * D_MODEL];
__device__ __half g_Kl[(size_t)M_TOTAL * D_MODEL];
__device__ __half g_Vh[(size_t)M_TOTAL * D_MODEL];
__device__ __half g_Vl[(size_t)M_TOTAL * D_MODEL];
__device__ __half g_Ah[(size_t)M_TOTAL * D_MODEL];
__device__ __half g_Al[(size_t)M_TOTAL * D_MODEL];
// transposed+split weights (W^T: row n, col k) — fp16 hi/lo
__device__ __half g_wqh[D_MODEL * D_MODEL];
__device__ __half g_wql[D_MODEL * D_MODEL];
__device__ __half g_wkh[D_MODEL * D_MODEL];
__device__ __half g_wkl[D_MODEL * D_MODEL];
__device__ __half g_wvh[D_MODEL * D_MODEL];
__device__ __half g_wvl[D_MODEL * D_MODEL];
__device__ __half g_woh[D_MODEL * D_MODEL];
__device__ __half g_wol[D_MODEL * D_MODEL];

// ---------------------------------------------------------------------------
// PTX helpers (base ISA only)
// ---------------------------------------------------------------------------
__device__ __forceinline__ uint32_t smem_u32(const void* p) {
    uint32_t a;
    asm("{ .reg .u64 t; cvta.to.shared.u64 t, %1; cvt.u32.u64 %0, t; }" : "=r"(a) : "l"(p));
    return a;
}
__device__ __forceinline__ void cp16(uint32_t dst, const void* src) {
    asm volatile("cp.async.cg.shared.global [%0], [%1], 16;" :: "r"(dst), "l"(src));
}
#define CP_COMMIT() asm volatile("cp.async.commit_group;" ::: "memory")
#define CP_WAIT1()  asm volatile("cp.async.wait_group 1;" ::: "memory")
#define CP_WAIT0()  asm volatile("cp.async.wait_group 0;" ::: "memory")

#define LDSM4(r0, r1, r2, r3, addr) \
    asm volatile("ldmatrix.sync.aligned.m8n8.x4.shared.b16 {%0,%1,%2,%3}, [%4];" \
        : "=r"(r0), "=r"(r1), "=r"(r2), "=r"(r3) : "r"(addr))

// fp16 inputs, fp32 accumulator
#define MMA_F32(c, a, b0, b1) \
    asm volatile("mma.sync.aligned.m16n8k16.row.col.f32.f16.f16.f32 " \
        "{%0,%1,%2,%3}, {%4,%5,%6,%7}, {%8,%9}, {%0,%1,%2,%3};" \
        : "+f"((c)[0]), "+f"((c)[1]), "+f"((c)[2]), "+f"((c)[3]) \
        : "r"((a)[0]), "r"((a)[1]), "r"((a)[2]), "r"((a)[3]), "r"(b0), "r"(b1))

// fp16 inputs, fp16 accumulator (corrections)
#define MMA_F16(c2, a, b0, b1) \
    asm volatile("mma.sync.aligned.m16n8k16.row.col.f16.f16.f16.f16 " \
        "{%0,%1}, {%2,%3,%4,%5}, {%6,%7}, {%0,%1};" \
        : "+r"((c2)[0]), "+r"((c2)[1]) \
        : "r"((a)[0]), "r"((a)[1]), "r"((a)[2]), "r"((a)[3]), "r"(b0), "r"(b1))

// split a float pair into packed fp16x2 hi and lo words
__device__ __forceinline__ void packsplit(float x, float y, uint32_t& hi, uint32_t& lo) {
    __half hx = __float2half_rn(x);
    __half hy = __float2half_rn(y);
    __half lx = __float2half_rn(x - __half2float(hx));
    __half ly = __float2half_rn(y - __half2float(hy));
    hi = (uint32_t)__half_as_ushort(hx) | ((uint32_t)__half_as_ushort(hy) << 16);
    lo = (uint32_t)__half_as_ushort(lx) | ((uint32_t)__half_as_ushort(ly) << 16);
}

// fast exp2 on FMA pipe (t <= 0), rel err ~1e-6
__device__ __forceinline__ float fexp2(float t) {
    t = fmaxf(t, -100.f);
    float fi = floorf(t);
    float f  = t - fi;
    float p  = 1.0178086e-5f;
    p = fmaf(p, f, 1.5403530e-4f);
    p = fmaf(p, f, 1.3333558e-3f);
    p = fmaf(p, f, 9.6181291e-3f);
    p = fmaf(p, f, 5.5504109e-2f);
    p = fmaf(p, f, 2.4022651e-1f);
    p = fmaf(p, f, 6.9314718e-1f);
    p = fmaf(p, f, 1.0f);
    return p * __int_as_float(((int)fi + 127) << 23);
}

// ---------------------------------------------------------------------------
// Split fp32 -> fp16 hi/lo (vectorized, grid-stride)
// ---------------------------------------------------------------------------
__global__ void fsplit_kernel(const float4* __restrict__ in,
                              uint32_t* __restrict__ hi,
                              uint32_t* __restrict__ lo, int n4)
{
    for (int i = blockIdx.x * blockDim.x + threadIdx.x; i < n4; i += gridDim.x * blockDim.x) {
        float4 v = in[i];
        uint32_t h0, l0, h1, l1;
        packsplit(v.x, v.y, h0, l0);
        packsplit(v.z, v.w, h1, l1);
        hi[i * 2 + 0] = h0; hi[i * 2 + 1] = h1;
        lo[i * 2 + 0] = l0; lo[i * 2 + 1] = l1;
    }
}

// ---------------------------------------------------------------------------
// Transpose + split W[1024][1024] -> Wt hi/lo (Wt[n][k] = W[k][n])
// ---------------------------------------------------------------------------
__global__ void wsplit_kernel(const float* __restrict__ W,
                              __half* __restrict__ Th,
                              __half* __restrict__ Tl)
{
    __shared__ float t[32][33];
    int bx = blockIdx.x * 32, by = blockIdx.y * 32;
    int x = threadIdx.x, y = threadIdx.y;
    #pragma unroll
    for (int d = 0; d < 32; d += 8)
        t[y + d][x] = W[(size_t)(by + y + d) * D_MODEL + bx + x];
    __syncthreads();
    #pragma unroll
    for (int d = 0; d < 32; d += 8) {
        float v = t[x][y + d];
        __half h = __float2half_rn(v);
        __half l = __float2half_rn(v - __half2float(h));
        size_t o = (size_t)(bx + y + d) * D_MODEL + by + x;
        Th[o] = h; Tl[o] = l;
    }
}

// ---------------------------------------------------------------------------
// Split-fp16 GEMM: C = (Ah+Al)(Bh+Bl)^T + bias.  CTA 128x256, BK=32, 3 stages.
// Main pass hi*hi -> fp32 accum; corrections hi*lo + lo*hi -> shared fp16 accum.
// SPLIT=true  -> writes fp16 hi/lo planes (for Q/K/V); else fp32 out.
// ---------------------------------------------------------------------------
#define STAGE_B   61440
#define A_PLANE   10240
#define B_PLANE   20480
#define GEMM_SMEM (3 * STAGE_B)
#define KCHUNKS   32

template<bool SPLIT>
__global__ __launch_bounds__(256)
void gemm_f16_mma(const __half* __restrict__ Ah, const __half* __restrict__ Al,
                  const __half* __restrict__ Bh, const __half* __restrict__ Bl,
                  const float* __restrict__ bias,
                  float* __restrict__ C,
                  __half* __restrict__ Ch, __half* __restrict__ Cl)
{
    extern __shared__ char smem_raw[];
    const uint32_t sbase = smem_u32(smem_raw);

    const int tid    = threadIdx.x;
    const int wid    = tid >> 5;
    const int lane   = tid & 31;
    const int warp_m = (wid >> 2) * 64;
    const int warp_n = (wid & 3) * 64;
    const size_t m0  = (size_t)blockIdx.y * 128;
    const size_t n0  = (size_t)blockIdx.x * 256;

    const char* sAh = (const char*)(Ah + m0 * D_MODEL);
    const char* sAl = (const char*)(Al + m0 * D_MODEL);
    const char* sBh = (const char*)(Bh + n0 * D_MODEL);
    const char* sBl = (const char*)(Bl + n0 * D_MODEL);

    auto fill = [&](int stage, int kc) {
        const uint32_t st = sbase + stage * STAGE_B;
        const size_t ko = (size_t)kc * 64;
        #pragma unroll
        for (int i = 0; i < 2; i++) {
            int c = tid + i * 256, row = c >> 2, col = c & 3;
            cp16(st + row * 80 + col * 16, sAh + (size_t)row * 2048 + ko + col * 16);
        }
        #pragma unroll
        for (int i = 0; i < 2; i++) {
            int c = tid + i * 256, row = c >> 2, col = c & 3;
            cp16(st + A_PLANE + row * 80 + col * 16, sAl + (size_t)row * 2048 + ko + col * 16);
        }
        #pragma unroll
        for (int i = 0; i < 4; i++) {
            int c = tid + i * 256, row = c >> 2, col = c & 3;
            cp16(st + 2 * A_PLANE + row * 80 + col * 16, sBh + (size_t)row * 2048 + ko + col * 16);
        }
        #pragma unroll
        for (int i = 0; i < 4; i++) {
            int c = tid + i * 256, row = c >> 2, col = c & 3;
            cp16(st + 2 * A_PLANE + B_PLANE + row * 80 + col * 16,
                 sBl + (size_t)row * 2048 + ko + col * 16);
        }
        CP_COMMIT();
    };

    float acc[4][8][4];
    uint32_t corr[4][8][2];
    #pragma unroll
    for (int i = 0; i < 4; i++)
        #pragma unroll
        for (int j = 0; j < 8; j++) {
            #pragma unroll
            for (int q = 0; q < 4; q++) acc[i][j][q] = 0.f;
            corr[i][j][0] = 0u; corr[i][j][1] = 0u;
        }

    fill(0, 0);
    fill(1, 1);

    const int lr = lane & 7, g = lane >> 3;
    const uint32_t a_loff = (uint32_t)((lr + (g & 1) * 8) * 80 + (g >> 1) * 16);
    const uint32_t b_loff = (uint32_t)((lr + (g >> 1) * 8) * 80 + (g & 1) * 16);

    for (int j = 0; j < KCHUNKS; j++) {
        CP_WAIT1();
        __syncthreads();
        if (j + 2 < KCHUNKS) fill((j + 2) % 3, j + 2);
        else CP_COMMIT();

        const uint32_t st = sbase + (j % 3) * STAGE_B;
        const uint32_t aH = st +                         warp_m * 80 + a_loff;
        const uint32_t aL = st + A_PLANE +               warp_m * 80 + a_loff;
        const uint32_t bH = st + 2 * A_PLANE +           warp_n * 80 + b_loff;
        const uint32_t bL = st + 2 * A_PLANE + B_PLANE + warp_n * 80 + b_loff;

        #pragma unroll
        for (int ks = 0; ks < 2; ks++) {
            const uint32_t ko = ks * 32;
            uint32_t ah_r[4][4], al_r[4][4];

            #pragma unroll
            for (int mt = 0; mt < 4; mt++)
                LDSM4(ah_r[mt][0], ah_r[mt][1], ah_r[mt][2], ah_r[mt][3],
                      aH + mt * (16 * 80) + ko);
            #pragma unroll
            for (int mt = 0; mt < 4; mt++)
                LDSM4(al_r[mt][0], al_r[mt][1], al_r[mt][2], al_r[mt][3],
                      aL + mt * (16 * 80) + ko);

            // process B in two 32-col halves to bound register pressure
            #pragma unroll
            for (int bh2 = 0; bh2 < 2; bh2++) {
                uint32_t bh_r[8], bl_r[8];
                #pragma unroll
                for (int p = 0; p < 2; p++)
                    LDSM4(bh_r[p*4+0], bh_r[p*4+1], bh_r[p*4+2], bh_r[p*4+3],
                          bH + (bh2 * 2 + p) * (16 * 80) + ko);
                #pragma unroll
                for (int p = 0; p < 2; p++)
                    LDSM4(bl_r[p*4+0], bl_r[p*4+1], bl_r[p*4+2], bl_r[p*4+3],
                          bL + (bh2 * 2 + p) * (16 * 80) + ko);

                #pragma unroll
                for (int mt = 0; mt < 4; mt++)
                    #pragma unroll
                    for (int ntl = 0; ntl < 4; ntl++)
                        MMA_F32(acc[mt][bh2*4+ntl], ah_r[mt], bh_r[ntl*2], bh_r[ntl*2+1]);
                #pragma unroll
                for (int mt = 0; mt < 4; mt++)
                    #pragma unroll
                    for (int ntl = 0; ntl < 4; ntl++)
                        MMA_F16(corr[mt][bh2*4+ntl], ah_r[mt], bl_r[ntl*2], bl_r[ntl*2+1]);
                #pragma unroll
                for (int mt = 0; mt < 4; mt++)
                    #pragma unroll
                    for (int ntl = 0; ntl < 4; ntl++)
                        MMA_F16(corr[mt][bh2*4+ntl], al_r[mt], bh_r[ntl*2], bh_r[ntl*2+1]);
            }
        }
    }

    #pragma unroll
    for (int mt = 0; mt < 4; mt++) {
        #pragma unroll
        for (int nt = 0; nt < 8; nt++) {
            int row0 = (int)m0 + warp_m + mt * 16 + (lane >> 2);
            int colg = (int)n0 + warp_n + nt * 8 + (lane & 3) * 2;
            float2 bv = *reinterpret_cast<const float2*>(bias + colg);
            float2 c0 = __half22float2(*reinterpret_cast<__half2*>(&corr[mt][nt][0]));
            float2 c1 = __half22float2(*reinterpret_cast<__half2*>(&corr[mt][nt][1]));
            float o00 = acc[mt][nt][0] + c0.x + bv.x, o01 = acc[mt][nt][1] + c0.y + bv.y;
            float o10 = acc[mt][nt][2] + c1.x + bv.x, o11 = acc[mt][nt][3] + c1.y + bv.y;
            size_t off0 = (size_t)row0 * D_MODEL + colg;
            size_t off1 = off0 + 8 * D_MODEL;
            if constexpr (SPLIT) {
                uint32_t hw, lw;
                packsplit(o00, o01, hw, lw);
                *reinterpret_cast<uint32_t*>(Ch + off0) = hw;
                *reinterpret_cast<uint32_t*>(Cl + off0) = lw;
                packsplit(o10, o11, hw, lw);
                *reinterpret_cast<uint32_t*>(Ch + off1) = hw;
                *reinterpret_cast<uint32_t*>(Cl + off1) = lw;
            } else {
                float2 a{o00, o01}, b{o10, o11};
                *reinterpret_cast<float2*>(C + off0) = a;
                *reinterpret_cast<float2*>(C + off1) = b;
            }
        }
    }
}

// ---------------------------------------------------------------------------
// Tensor-core patch attention (split-fp16, fragment softmax, poly exp).
// grid = (NUM_HEADS, NBLK), 256 threads (8 warps; warp w owns rows 16w..16w+15).
// smem: Qh,Ql,Kh,Kl [128][72] fp16 + Vth,Vtl [64][136] fp16 = 108544 B.
// ---------------------------------------------------------------------------
#define QK_STRIDE_B 144          // 72 fp16
#define VT_STRIDE_B 272          // 136 fp16
#define OFF_QH 0
#define OFF_QL 18432
#define OFF_KH 36864
#define OFF_KL 55296
#define OFF_VH 73728
#define OFF_VL 91136
#define ATTN_SMEM 108544

__global__ __launch_bounds__(256, 2)
void attn_mma_kernel()
{
    extern __shared__ char smc[];
    const uint32_t sb = smem_u32(smc);

    const int h   = blockIdx.x;
    const int pb  = blockIdx.y;
    const int tid = threadIdx.x;
    const int wid = tid >> 5;
    const int lane = tid & 31;
    const size_t base = (size_t)pb * 128 * D_MODEL + (size_t)h * D_HEAD;

    {
        const char* gp[4] = {
            (const char*)(g_Qh + base), (const char*)(g_Ql + base),
            (const char*)(g_Kh + base), (const char*)(g_Kl + base) };
        const uint32_t sp[4] = { sb + OFF_QH, sb + OFF_QL, sb + OFF_KH, sb + OFF_KL };
        #pragma unroll
        for (int pl = 0; pl < 4; pl++)
            #pragma unroll
            for (int i = 0; i < 4; i++) {
                int idx = tid + i * 256;
                int row = idx >> 3, ch = idx & 7;
                cp16(sp[pl] + row * QK_STRIDE_B + ch * 16,
                     gp[pl] + (size_t)row * 2048 + ch * 16);
            }
        CP_COMMIT();
    }
    for (int i = tid; i < 128 * 64; i += 256) {
        int kv = i >> 6, d = i & 63;
        size_t go = base + (size_t)kv * D_MODEL + d;
        *reinterpret_cast<__half*>(smc + OFF_VH + d * VT_STRIDE_B + kv * 2) = g_Vh[go];
        *reinterpret_cast<__half*>(smc + OFF_VL + d * VT_STRIDE_B + kv * 2) = g_Vl[go];
    }
    CP_WAIT0();
    __syncthreads();

    const int lr = lane & 7, g = lane >> 3;
    const uint32_t a_off = (uint32_t)((lr + (g & 1) * 8) * QK_STRIDE_B + (g >> 1) * 16);
    const uint32_t b_off = (uint32_t)((lr + (g >> 1) * 8) * QK_STRIDE_B + (g & 1) * 16);
    const uint32_t v_off = (uint32_t)((lr + (g >> 1) * 8) * VT_STRIDE_B + (g & 1) * 16);

    // ---- S = Q K^T (split fp16: hi*hi f32, corrections f16) ----
    float cf[16][4];
    uint32_t sc[16][2];
    #pragma unroll
    for (int i = 0; i < 16; i++) {
        #pragma unroll
        for (int q = 0; q < 4; q++) cf[i][q] = 0.f;
        sc[i][0] = 0u; sc[i][1] = 0u;
    }

    const uint32_t qh0 = sb + OFF_QH + wid * (16 * QK_STRIDE_B) + a_off;
    const uint32_t ql0 = sb + OFF_QL + wid * (16 * QK_STRIDE_B) + a_off;

    #pragma unroll
    for (int ks = 0; ks < 4; ks++) {
        const uint32_t ko = ks * 32;
        uint32_t aq[4], bq[4];
        LDSM4(aq[0], aq[1], aq[2], aq[3], qh0 + ko);
        LDSM4(bq[0], bq[1], bq[2], bq[3], ql0 + ko);
        #pragma unroll
        for (int p = 0; p < 8; p++) {
            uint32_t kh[4], kl[4];
            LDSM4(kh[0], kh[1], kh[2], kh[3], sb + OFF_KH + p * (16 * QK_STRIDE_B) + b_off + ko);
            LDSM4(kl[0], kl[1], kl[2], kl[3], sb + OFF_KL + p * (16 * QK_STRIDE_B) + b_off + ko);
            MMA_F32(cf[2*p],   aq, kh[0], kh[1]);
            MMA_F32(cf[2*p+1], aq, kh[2], kh[3]);
            MMA_F16(sc[2*p],   aq, kl[0], kl[1]);
            MMA_F16(sc[2*p+1], aq, kl[2], kl[3]);
            MMA_F16(sc[2*p],   bq, kh[0], kh[1]);
            MMA_F16(sc[2*p+1], bq, kh[2], kh[3]);
        }
    }
    #pragma unroll
    for (int i = 0; i < 16; i++) {
        float2 c0 = __half22float2(*reinterpret_cast<__half2*>(&sc[i][0]));
        float2 c1 = __half22float2(*reinterpret_cast<__half2*>(&sc[i][1]));
        cf[i][0] += c0.x; cf[i][1] += c0.y; cf[i][2] += c1.x; cf[i][3] += c1.y;
    }

    // ---- fragment softmax ----
    float mx0 = -CUDART_INF_F, mx1 = -CUDART_INF_F;
    #pragma unroll
    for (int nt = 0; nt < 16; nt++) {
        mx0 = fmaxf(mx0, fmaxf(cf[nt][0], cf[nt][1]));
        mx1 = fmaxf(mx1, fmaxf(cf[nt][2], cf[nt][3]));
    }
    mx0 = fmaxf(mx0, __shfl_xor_sync(0xffffffffu, mx0, 1));
    mx0 = fmaxf(mx0, __shfl_xor_sync(0xffffffffu, mx0, 2));
    mx1 = fmaxf(mx1, __shfl_xor_sync(0xffffffffu, mx1, 1));
    mx1 = fmaxf(mx1, __shfl_xor_sync(0xffffffffu, mx1, 2));

    const float CS = 0.125f * 1.4426950408889634f;   // log2(e)/sqrt(64)
    float l0 = 0.f, l1 = 0.f;
    #pragma unroll
    for (int nt = 0; nt < 16; nt++) {
        float p0 = fexp2((cf[nt][0] - mx0) * CS);
        float p1 = fexp2((cf[nt][1] - mx0) * CS);
        float p2 = fexp2((cf[nt][2] - mx1) * CS);
        float p3 = fexp2((cf[nt][3] - mx1) * CS);
        cf[nt][0] = p0; cf[nt][1] = p1; cf[nt][2] = p2; cf[nt][3] = p3;
        l0 += p0 + p1; l1 += p2 + p3;
    }
    l0 += __shfl_xor_sync(0xffffffffu, l0, 1);
    l0 += __shfl_xor_sync(0xffffffffu, l0, 2);
    l1 += __shfl_xor_sync(0xffffffffu, l1, 1);
    l1 += __shfl_xor_sync(0xffffffffu, l1, 2);
    const float inv0 = 1.f / l0, inv1 = 1.f / l1;

    // ---- O = P V (split fp16: hi*hi f32, corrections f16) ----
    float of[8][4];
    uint32_t oc[8][2];
    #pragma unroll
    for (int i = 0; i < 8; i++) {
        #pragma unroll
        for (int q = 0; q < 4; q++) of[i][q] = 0.f;
        oc[i][0] = 0u; oc[i][1] = 0u;
    }

    #pragma unroll
    for (int kt = 0; kt < 8; kt++) {
        uint32_t ah[4], al[4];
        packsplit(cf[2*kt][0],   cf[2*kt][1],   ah[0], al[0]);
        packsplit(cf[2*kt][2],   cf[2*kt][3],   ah[1], al[1]);
        packsplit(cf[2*kt+1][0], cf[2*kt+1][1], ah[2], al[2]);
        packsplit(cf[2*kt+1][2], cf[2*kt+1][3], ah[3], al[3]);
        const uint32_t ko = kt * 32;
        #pragma unroll
        for (int np = 0; np < 4; np++) {
            uint32_t vh[4], vl[4];
            LDSM4(vh[0], vh[1], vh[2], vh[3], sb + OFF_VH + np * (16 * VT_STRIDE_B) + v_off + ko);
            LDSM4(vl[0], vl[1], vl[2], vl[3], sb + OFF_VL + np * (16 * VT_STRIDE_B) + v_off + ko);
            MMA_F32(of[2*np],   ah, vh[0], vh[1]);
            MMA_F32(of[2*np+1], ah, vh[2], vh[3]);
            MMA_F16(oc[2*np],   ah, vl[0], vl[1]);
            MMA_F16(oc[2*np+1], ah, vl[2], vl[3]);
            MMA_F16(oc[2*np],   al, vh[0], vh[1]);
            MMA_F16(oc[2*np+1], al, vh[2], vh[3]);
        }
    }

    // ---- write A = softmax(S)V as fp16 hi/lo ----
    const int row  = pb * 128 + wid * 16 + (lane >> 2);
    const int colb = h * 64 + (lane & 3) * 2;
    #pragma unroll
    for (int nt = 0; nt < 8; nt++) {
        float2 c0 = __half22float2(*reinterpret_cast<__half2*>(&oc[nt][0]));
        float2 c1 = __half22float2(*reinterpret_cast<__half2*>(&oc[nt][1]));
        size_t off0 = (size_t)row * D_MODEL + colb + nt * 8;
        size_t off1 = off0 + 8 * D_MODEL;
        uint32_t hw, lw;
        packsplit((of[nt][0] + c0.x) * inv0, (of[nt][1] + c0.y) * inv0, hw, lw);
        *reinterpret_cast<uint32_t*>(g_Ah + off0) = hw;
        *reinterpret_cast<uint32_t*>(g_Al + off0) = lw;
        packsplit((of[nt][2] + c1.x) * inv1, (of[nt][3] + c1.y) * inv1, hw, lw);
        *reinterpret_cast<uint32_t*>(g_Ah + off1) = hw;
        *reinterpret_cast<uint32_t*>(g_Al + off1) = lw;
    }
}

// ---------------------------------------------------------------------------
extern "C" void kernel_launch(void* const* d_in, const int* in_sizes, int n_in,
                              void* d_out, int out_size)
{
    const float* x  = (const float*)d_in[0];
    // d_in[1] = coords (unused by reference)
    const float* Wq = (const float*)d_in[2];
    const float* bq = (const float*)d_in[3];
    const float* Wk = (const float*)d_in[4];
    const float* bk = (const float*)d_in[5];
    const float* Wv = (const float*)d_in[6];
    const float* bv = (const float*)d_in[7];
    const float* Wo = (const float*)d_in[8];
    const float* bo = (const float*)d_in[9];
    float* out = (float*)d_out;

    __half *xh, *xl, *Qh, *Ql, *Kh, *Kl, *Vh, *Vl, *Ah, *Al;
    __half *wqh, *wql, *wkh, *wkl, *wvh, *wvl, *woh, *wol;
    cudaGetSymbolAddress((void**)&xh,  g_xh);
    cudaGetSymbolAddress((void**)&xl,  g_xl);
    cudaGetSymbolAddress((void**)&Qh,  g_Qh);
    cudaGetSymbolAddress((void**)&Ql,  g_Ql);
    cudaGetSymbolAddress((void**)&Kh,  g_Kh);
    cudaGetSymbolAddress((void**)&Kl,  g_Kl);
    cudaGetSymbolAddress((void**)&Vh,  g_Vh);
    cudaGetSymbolAddress((void**)&Vl,  g_Vl);
    cudaGetSymbolAddress((void**)&Ah,  g_Ah);
    cudaGetSymbolAddress((void**)&Al,  g_Al);
    cudaGetSymbolAddress((void**)&wqh, g_wqh);
    cudaGetSymbolAddress((void**)&wql, g_wql);
    cudaGetSymbolAddress((void**)&wkh, g_wkh);
    cudaGetSymbolAddress((void**)&wkl, g_wkl);
    cudaGetSymbolAddress((void**)&wvh, g_wvh);
    cudaGetSymbolAddress((void**)&wvl, g_wvl);
    cudaGetSymbolAddress((void**)&woh, g_woh);
    cudaGetSymbolAddress((void**)&wol, g_wol);

    cudaFuncSetAttribute(gemm_f16_mma<true>,  cudaFuncAttributeMaxDynamicSharedMemorySize, GEMM_SMEM);
    cudaFuncSetAttribute(gemm_f16_mma<false>, cudaFuncAttributeMaxDynamicSharedMemorySize, GEMM_SMEM);
    cudaFuncSetAttribute(attn_mma_kernel, cudaFuncAttributeMaxDynamicSharedMemorySize, ATTN_SMEM);

    // launches 1-4: transpose + split weights  (ncu -s 5 then captures launch 6 = GEMM)
    dim3 wgrid(32, 32), wblk(32, 8);
    wsplit_kernel<<<wgrid, wblk>>>(Wq, wqh, wql);
    wsplit_kernel<<<wgrid, wblk>>>(Wk, wkh, wkl);
    wsplit_kernel<<<wgrid, wblk>>>(Wv, wvh, wvl);
    wsplit_kernel<<<wgrid, wblk>>>(Wo, woh, wol);
    // launch 5: split x -> fp16 hi/lo
    fsplit_kernel<<<8192, 256>>>((const float4*)x, (uint32_t*)xh, (uint32_t*)xl,
                                 M_TOTAL * D_MODEL / 4);

    // launches 6-8: Q/K/V projections — epilogue emits fp16 hi/lo
    dim3 ggrid(D_MODEL / 256, M_TOTAL / 128);   // (4, 256)
    gemm_f16_mma<true><<<ggrid, 256, GEMM_SMEM>>>(xh, xl, wqh, wql, bq, nullptr, Qh, Ql);
    gemm_f16_mma<true><<<ggrid, 256, GEMM_SMEM>>>(xh, xl, wkh, wkl, bk, nullptr, Kh, Kl);
    gemm_f16_mma<true><<<ggrid, 256, GEMM_SMEM>>>(xh, xl, wvh, wvl, bv, nullptr, Vh, Vl);

    // launch 9: tensor-core attention (writes fp16 hi/lo A)
    dim3 agrid(NUM_HEADS, NBLK);
    attn_mma_kernel<<<agrid, 256, ATTN_SMEM>>>();

    // launch 10: output projection (fp32 out)
    gemm_f16_mma<false><<<ggrid, 256, GEMM_SMEM>>>(Ah, Al, woh, wol, bo, out, nullptr, nullptr);
}

// round 8
// speedup vs baseline: 6.4461x; 2.2165x over previous
#include <cuda_runtime.h>
#include <cuda_fp16.h>
#include <math_constants.h>
#include <cstdint>

#define D_MODEL   1024
#define NUM_HEADS 16
#define D_HEAD    64
#define PATCH     128
#define BATCH     4
#define SEQ       8192
#define M_TOTAL   (BATCH * SEQ)          // 32768 rows
#define NBLK      (M_TOTAL / PATCH)      // 256 patch blocks

// ---------------------------------------------------------------------------
// Scratch (static device globals — no runtime allocation)
// ---------------------------------------------------------------------------
__device__ __half g_x[(size_t)M_TOTAL * D_MODEL];
__device__ __half g_Q[(size_t)M_TOTAL * D_MODEL];
__device__ __half g_K[(size_t)M_TOTAL * D_MODEL];
__device__ __half g_V[(size_t)M_TOTAL * D_MODEL];
__device__ __half g_A[(size_t)M_TOTAL * D_MODEL];
// transposed weights (W^T: row n, col k) — fp16
__device__ __half g_wq[D_MODEL * D_MODEL];
__device__ __half g_wk[D_MODEL * D_MODEL];
__device__ __half g_wv[D_MODEL * D_MODEL];
__device__ __half g_wo[D_MODEL * D_MODEL];

// ---------------------------------------------------------------------------
// PTX helpers (base ISA only)
// ---------------------------------------------------------------------------
__device__ __forceinline__ uint32_t smem_u32(const void* p) {
    uint32_t a;
    asm("{ .reg .u64 t; cvta.to.shared.u64 t, %1; cvt.u32.u64 %0, t; }" : "=r"(a) : "l"(p));
    return a;
}
__device__ __forceinline__ void cp16(uint32_t dst, const void* src) {
    asm volatile("cp.async.cg.shared.global [%0], [%1], 16;" :: "r"(dst), "l"(src));
}
#define CP_COMMIT() asm volatile("cp.async.commit_group;" ::: "memory")
#define CP_WAIT1()  asm volatile("cp.async.wait_group 1;" ::: "memory")
#define CP_WAIT0()  asm volatile("cp.async.wait_group 0;" ::: "memory")

#define LDSM4(r0, r1, r2, r3, addr) \
    asm volatile("ldmatrix.sync.aligned.m8n8.x4.shared.b16 {%0,%1,%2,%3}, [%4];" \
        : "=r"(r0), "=r"(r1), "=r"(r2), "=r"(r3) : "r"(addr))

#define MMA_F32(c, a, b0, b1) \
    asm volatile("mma.sync.aligned.m16n8k16.row.col.f32.f16.f16.f32 " \
        "{%0,%1,%2,%3}, {%4,%5,%6,%7}, {%8,%9}, {%0,%1,%2,%3};" \
        : "+f"((c)[0]), "+f"((c)[1]), "+f"((c)[2]), "+f"((c)[3]) \
        : "r"((a)[0]), "r"((a)[1]), "r"((a)[2]), "r"((a)[3]), "r"(b0), "r"(b1))

__device__ __forceinline__ uint32_t packh2(float x, float y) {
    __half2 h = __floats2half2_rn(x, y);
    return *reinterpret_cast<uint32_t*>(&h);
}

// fast exp2 on FMA pipe (t <= 0), rel err ~1e-6
__device__ __forceinline__ float fexp2(float t) {
    t = fmaxf(t, -100.f);
    float fi = floorf(t);
    float f  = t - fi;
    float p  = 1.0178086e-5f;
    p = fmaf(p, f, 1.5403530e-4f);
    p = fmaf(p, f, 1.3333558e-3f);
    p = fmaf(p, f, 9.6181291e-3f);
    p = fmaf(p, f, 5.5504109e-2f);
    p = fmaf(p, f, 2.4022651e-1f);
    p = fmaf(p, f, 6.9314718e-1f);
    p = fmaf(p, f, 1.0f);
    return p * __int_as_float(((int)fi + 127) << 23);
}

// ---------------------------------------------------------------------------
// Convert fp32 -> fp16 (vectorized, grid-stride)
// ---------------------------------------------------------------------------
__global__ void fconv_kernel(const float4* __restrict__ in,
                             uint32_t* __restrict__ out, int n4)
{
    for (int i = blockIdx.x * blockDim.x + threadIdx.x; i < n4; i += gridDim.x * blockDim.x) {
        float4 v = in[i];
        out[i * 2 + 0] = packh2(v.x, v.y);
        out[i * 2 + 1] = packh2(v.z, v.w);
    }
}

// ---------------------------------------------------------------------------
// Transpose + convert W[1024][1024] -> Wt fp16 (Wt[n][k] = W[k][n])
// ---------------------------------------------------------------------------
__global__ void wconv_kernel(const float* __restrict__ W, __half* __restrict__ T)
{
    __shared__ float t[32][33];
    int bx = blockIdx.x * 32, by = blockIdx.y * 32;
    int x = threadIdx.x, y = threadIdx.y;
    #pragma unroll
    for (int d = 0; d < 32; d += 8)
        t[y + d][x] = W[(size_t)(by + y + d) * D_MODEL + bx + x];
    __syncthreads();
    #pragma unroll
    for (int d = 0; d < 32; d += 8)
        T[(size_t)(bx + y + d) * D_MODEL + by + x] = __float2half_rn(t[x][y + d]);
}

// ---------------------------------------------------------------------------
// fp16 GEMM: C = A B^T + bias.  CTA 128x256, BK=32, 3-stage cp.async pipeline.
// 8 warps, warp tile 64x64.  F32OUT: fp32 C; else fp16 C.
// smem/stage: A 128x80B + B 256x80B = 30720 B; 3 stages = 92160 B.
// ---------------------------------------------------------------------------
#define A_PLANE   10240
#define B_PLANE   20480
#define STAGE_B   30720
#define GEMM_SMEM (3 * STAGE_B)
#define KCHUNKS   32

template<bool F32OUT>
__global__ __launch_bounds__(256)
void gemm_f16(const __half* __restrict__ A, const __half* __restrict__ B,
              const float* __restrict__ bias,
              float* __restrict__ C, __half* __restrict__ Ch)
{
    extern __shared__ char smem_raw[];
    const uint32_t sbase = smem_u32(smem_raw);

    const int tid    = threadIdx.x;
    const int wid    = tid >> 5;
    const int lane   = tid & 31;
    const int warp_m = (wid >> 2) * 64;
    const int warp_n = (wid & 3) * 64;
    const size_t m0  = (size_t)blockIdx.y * 128;
    const size_t n0  = (size_t)blockIdx.x * 256;

    const char* sA = (const char*)(A + m0 * D_MODEL);
    const char* sB = (const char*)(B + n0 * D_MODEL);

    auto fill = [&](int stage, int kc) {
        const uint32_t st = sbase + stage * STAGE_B;
        const size_t ko = (size_t)kc * 64;
        #pragma unroll
        for (int i = 0; i < 2; i++) {
            int c = tid + i * 256, row = c >> 2, col = c & 3;
            cp16(st + row * 80 + col * 16, sA + (size_t)row * 2048 + ko + col * 16);
        }
        #pragma unroll
        for (int i = 0; i < 4; i++) {
            int c = tid + i * 256, row = c >> 2, col = c & 3;
            cp16(st + A_PLANE + row * 80 + col * 16, sB + (size_t)row * 2048 + ko + col * 16);
        }
        CP_COMMIT();
    };

    float acc[4][8][4];
    #pragma unroll
    for (int i = 0; i < 4; i++)
        #pragma unroll
        for (int j = 0; j < 8; j++)
            #pragma unroll
            for (int q = 0; q < 4; q++) acc[i][j][q] = 0.f;

    fill(0, 0);
    fill(1, 1);

    const int lr = lane & 7, g = lane >> 3;
    const uint32_t a_loff = (uint32_t)((lr + (g & 1) * 8) * 80 + (g >> 1) * 16);
    const uint32_t b_loff = (uint32_t)((lr + (g >> 1) * 8) * 80 + (g & 1) * 16);

    for (int j = 0; j < KCHUNKS; j++) {
        CP_WAIT1();
        __syncthreads();
        if (j + 2 < KCHUNKS) fill((j + 2) % 3, j + 2);
        else CP_COMMIT();

        const uint32_t st = sbase + (j % 3) * STAGE_B;
        const uint32_t aP = st +           warp_m * 80 + a_loff;
        const uint32_t bP = st + A_PLANE + warp_n * 80 + b_loff;

        #pragma unroll
        for (int ks = 0; ks < 2; ks++) {
            const uint32_t ko = ks * 32;
            uint32_t a_r[4][4], b_r[16];

            #pragma unroll
            for (int mt = 0; mt < 4; mt++)
                LDSM4(a_r[mt][0], a_r[mt][1], a_r[mt][2], a_r[mt][3],
                      aP + mt * (16 * 80) + ko);
            #pragma unroll
            for (int p = 0; p < 4; p++)
                LDSM4(b_r[p*4+0], b_r[p*4+1], b_r[p*4+2], b_r[p*4+3],
                      bP + p * (16 * 80) + ko);

            #pragma unroll
            for (int mt = 0; mt < 4; mt++)
                #pragma unroll
                for (int nt = 0; nt < 8; nt++)
                    MMA_F32(acc[mt][nt], a_r[mt], b_r[nt*2], b_r[nt*2+1]);
        }
    }

    #pragma unroll
    for (int mt = 0; mt < 4; mt++) {
        #pragma unroll
        for (int nt = 0; nt < 8; nt++) {
            int row0 = (int)m0 + warp_m + mt * 16 + (lane >> 2);
            int colg = (int)n0 + warp_n + nt * 8 + (lane & 3) * 2;
            float2 bv = *reinterpret_cast<const float2*>(bias + colg);
            float o00 = acc[mt][nt][0] + bv.x, o01 = acc[mt][nt][1] + bv.y;
            float o10 = acc[mt][nt][2] + bv.x, o11 = acc[mt][nt][3] + bv.y;
            size_t off0 = (size_t)row0 * D_MODEL + colg;
            size_t off1 = off0 + 8 * D_MODEL;
            if constexpr (F32OUT) {
                float2 a{o00, o01}, b{o10, o11};
                *reinterpret_cast<float2*>(C + off0) = a;
                *reinterpret_cast<float2*>(C + off1) = b;
            } else {
                *reinterpret_cast<uint32_t*>(Ch + off0) = packh2(o00, o01);
                *reinterpret_cast<uint32_t*>(Ch + off1) = packh2(o10, o11);
            }
        }
    }
}

// ---------------------------------------------------------------------------
// Tensor-core patch attention (fp16, fragment softmax, poly exp).
// grid = (NUM_HEADS, NBLK), 256 threads (8 warps; warp w owns rows 16w..16w+15).
// smem: Q,K [128][72] fp16 + Vt [64][136] fp16 = 54272 B.
// ---------------------------------------------------------------------------
#define QK_STRIDE_B 144          // 72 fp16
#define VT_STRIDE_B 272          // 136 fp16
#define OFF_Q 0
#define OFF_K 18432
#define OFF_V 36864
#define ATTN_SMEM 54272

__global__ __launch_bounds__(256, 2)
void attn_mma_kernel()
{
    extern __shared__ char smc[];
    const uint32_t sb = smem_u32(smc);

    const int h   = blockIdx.x;
    const int pb  = blockIdx.y;
    const int tid = threadIdx.x;
    const int wid = tid >> 5;
    const int lane = tid & 31;
    const size_t base = (size_t)pb * 128 * D_MODEL + (size_t)h * D_HEAD;

    // stage Q,K via cp.async (rows of 64 fp16 = 128 B = 8 x 16B)
    {
        const char* gq = (const char*)(g_Q + base);
        const char* gk = (const char*)(g_K + base);
        #pragma unroll
        for (int i = 0; i < 4; i++) {
            int idx = tid + i * 256;
            int row = idx >> 3, ch = idx & 7;
            cp16(sb + OFF_Q + row * QK_STRIDE_B + ch * 16, gq + (size_t)row * 2048 + ch * 16);
            cp16(sb + OFF_K + row * QK_STRIDE_B + ch * 16, gk + (size_t)row * 2048 + ch * 16);
        }
        CP_COMMIT();
    }
    // V transpose into smem: Vt[d][kv]
    for (int i = tid; i < 128 * 64; i += 256) {
        int kv = i >> 6, d = i & 63;
        *reinterpret_cast<__half*>(smc + OFF_V + d * VT_STRIDE_B + kv * 2) =
            g_V[base + (size_t)kv * D_MODEL + d];
    }
    CP_WAIT0();
    __syncthreads();

    const int lr = lane & 7, g = lane >> 3;
    const uint32_t a_off = (uint32_t)((lr + (g & 1) * 8) * QK_STRIDE_B + (g >> 1) * 16);
    const uint32_t b_off = (uint32_t)((lr + (g >> 1) * 8) * QK_STRIDE_B + (g & 1) * 16);
    const uint32_t v_off = (uint32_t)((lr + (g >> 1) * 8) * VT_STRIDE_B + (g & 1) * 16);

    // ---- S = Q K^T ----
    float cf[16][4];
    #pragma unroll
    for (int i = 0; i < 16; i++)
        #pragma unroll
        for (int q = 0; q < 4; q++) cf[i][q] = 0.f;

    const uint32_t q0 = sb + OFF_Q + wid * (16 * QK_STRIDE_B) + a_off;

    #pragma unroll
    for (int ks = 0; ks < 4; ks++) {
        const uint32_t ko = ks * 32;
        uint32_t aq[4];
        LDSM4(aq[0], aq[1], aq[2], aq[3], q0 + ko);
        #pragma unroll
        for (int p = 0; p < 8; p++) {
            uint32_t kh[4];
            LDSM4(kh[0], kh[1], kh[2], kh[3], sb + OFF_K + p * (16 * QK_STRIDE_B) + b_off + ko);
            MMA_F32(cf[2*p],   aq, kh[0], kh[1]);
            MMA_F32(cf[2*p+1], aq, kh[2], kh[3]);
        }
    }

    // ---- fragment softmax ----
    float mx0 = -CUDART_INF_F, mx1 = -CUDART_INF_F;
    #pragma unroll
    for (int nt = 0; nt < 16; nt++) {
        mx0 = fmaxf(mx0, fmaxf(cf[nt][0], cf[nt][1]));
        mx1 = fmaxf(mx1, fmaxf(cf[nt][2], cf[nt][3]));
    }
    mx0 = fmaxf(mx0, __shfl_xor_sync(0xffffffffu, mx0, 1));
    mx0 = fmaxf(mx0, __shfl_xor_sync(0xffffffffu, mx0, 2));
    mx1 = fmaxf(mx1, __shfl_xor_sync(0xffffffffu, mx1, 1));
    mx1 = fmaxf(mx1, __shfl_xor_sync(0xffffffffu, mx1, 2));

    const float CS = 0.125f * 1.4426950408889634f;   // log2(e)/sqrt(64)
    float l0 = 0.f, l1 = 0.f;
    #pragma unroll
    for (int nt = 0; nt < 16; nt++) {
        float p0 = fexp2((cf[nt][0] - mx0) * CS);
        float p1 = fexp2((cf[nt][1] - mx0) * CS);
        float p2 = fexp2((cf[nt][2] - mx1) * CS);
        float p3 = fexp2((cf[nt][3] - mx1) * CS);
        cf[nt][0] = p0; cf[nt][1] = p1; cf[nt][2] = p2; cf[nt][3] = p3;
        l0 += p0 + p1; l1 += p2 + p3;
    }
    l0 += __shfl_xor_sync(0xffffffffu, l0, 1);
    l0 += __shfl_xor_sync(0xffffffffu, l0, 2);
    l1 += __shfl_xor_sync(0xffffffffu, l1, 1);
    l1 += __shfl_xor_sync(0xffffffffu, l1, 2);
    const float inv0 = 1.f / l0, inv1 = 1.f / l1;

    // ---- O = P V ----
    float of[8][4];
    #pragma unroll
    for (int i = 0; i < 8; i++)
        #pragma unroll
        for (int q = 0; q < 4; q++) of[i][q] = 0.f;

    #pragma unroll
    for (int kt = 0; kt < 8; kt++) {
        uint32_t ah[4];
        ah[0] = packh2(cf[2*kt][0],   cf[2*kt][1]);
        ah[1] = packh2(cf[2*kt][2],   cf[2*kt][3]);
        ah[2] = packh2(cf[2*kt+1][0], cf[2*kt+1][1]);
        ah[3] = packh2(cf[2*kt+1][2], cf[2*kt+1][3]);
        const uint32_t ko = kt * 32;
        #pragma unroll
        for (int np = 0; np < 4; np++) {
            uint32_t vh[4];
            LDSM4(vh[0], vh[1], vh[2], vh[3], sb + OFF_V + np * (16 * VT_STRIDE_B) + v_off + ko);
            MMA_F32(of[2*np],   ah, vh[0], vh[1]);
            MMA_F32(of[2*np+1], ah, vh[2], vh[3]);
        }
    }

    // ---- write A = softmax(S)V as fp16 ----
    const int row  = pb * 128 + wid * 16 + (lane >> 2);
    const int colb = h * 64 + (lane & 3) * 2;
    #pragma unroll
    for (int nt = 0; nt < 8; nt++) {
        size_t off0 = (size_t)row * D_MODEL + colb + nt * 8;
        size_t off1 = off0 + 8 * D_MODEL;
        *reinterpret_cast<uint32_t*>(g_A + off0) = packh2(of[nt][0] * inv0, of[nt][1] * inv0);
        *reinterpret_cast<uint32_t*>(g_A + off1) = packh2(of[nt][2] * inv1, of[nt][3] * inv1);
    }
}

// ---------------------------------------------------------------------------
extern "C" void kernel_launch(void* const* d_in, const int* in_sizes, int n_in,
                              void* d_out, int out_size)
{
    const float* x  = (const float*)d_in[0];
    // d_in[1] = coords (unused by reference)
    const float* Wq = (const float*)d_in[2];
    const float* bq = (const float*)d_in[3];
    const float* Wk = (const float*)d_in[4];
    const float* bk = (const float*)d_in[5];
    const float* Wv = (const float*)d_in[6];
    const float* bv = (const float*)d_in[7];
    const float* Wo = (const float*)d_in[8];
    const float* bo = (const float*)d_in[9];
    float* out = (float*)d_out;

    __half *xh, *Qp, *Kp, *Vp, *Ap, *wq, *wk, *wv, *wo;
    cudaGetSymbolAddress((void**)&xh, g_x);
    cudaGetSymbolAddress((void**)&Qp, g_Q);
    cudaGetSymbolAddress((void**)&Kp, g_K);
    cudaGetSymbolAddress((void**)&Vp, g_V);
    cudaGetSymbolAddress((void**)&Ap, g_A);
    cudaGetSymbolAddress((void**)&wq, g_wq);
    cudaGetSymbolAddress((void**)&wk, g_wk);
    cudaGetSymbolAddress((void**)&wv, g_wv);
    cudaGetSymbolAddress((void**)&wo, g_wo);

    cudaFuncSetAttribute(gemm_f16<true>,  cudaFuncAttributeMaxDynamicSharedMemorySize, GEMM_SMEM);
    cudaFuncSetAttribute(gemm_f16<false>, cudaFuncAttributeMaxDynamicSharedMemorySize, GEMM_SMEM);
    cudaFuncSetAttribute(attn_mma_kernel, cudaFuncAttributeMaxDynamicSharedMemorySize, ATTN_SMEM);

    // launches 1-4: transpose + convert weights
    dim3 wgrid(32, 32), wblk(32, 8);
    wconv_kernel<<<wgrid, wblk>>>(Wq, wq);
    wconv_kernel<<<wgrid, wblk>>>(Wk, wk);
    wconv_kernel<<<wgrid, wblk>>>(Wv, wv);
    wconv_kernel<<<wgrid, wblk>>>(Wo, wo);
    // launch 5: convert x -> fp16
    fconv_kernel<<<8192, 256>>>((const float4*)x, (uint32_t*)xh, M_TOTAL * D_MODEL / 4);

    // launches 6-8: Q/K/V projections (fp16 out)
    dim3 ggrid(D_MODEL / 256, M_TOTAL / 128);   // (4, 256)
    gemm_f16<false><<<ggrid, 256, GEMM_SMEM>>>(xh, wq, bq, nullptr, Qp);
    gemm_f16<false><<<ggrid, 256, GEMM_SMEM>>>(xh, wk, bk, nullptr, Kp);
    gemm_f16<false><<<ggrid, 256, GEMM_SMEM>>>(xh, wv, bv, nullptr, Vp);

    // launch 9: tensor-core attention (fp16 A)
    dim3 agrid(NUM_HEADS, NBLK);
    attn_mma_kernel<<<agrid, 256, ATTN_SMEM>>>();

    // launch 10: output projection (fp32 out)
    gemm_f16<true><<<ggrid, 256, GEMM_SMEM>>>(Ap, wo, bo, out, nullptr);
}

// round 9
// speedup vs baseline: 6.8124x; 1.0568x over previous
#include <cuda_runtime.h>
#include <cuda_fp16.h>
#include <math_constants.h>
#include <cstdint>

#define D_MODEL   1024
#define NUM_HEADS 16
#define D_HEAD    64
#define PATCH     128
#define BATCH     4
#define SEQ       8192
#define M_TOTAL   (BATCH * SEQ)          // 32768 rows
#define NBLK      (M_TOTAL / PATCH)      // 256 patch blocks

// ---------------------------------------------------------------------------
// Scratch (static device globals — no runtime allocation)
// ---------------------------------------------------------------------------
__device__ __half g_x[(size_t)M_TOTAL * D_MODEL];
__device__ __half g_Q[(size_t)M_TOTAL * D_MODEL];
__device__ __half g_K[(size_t)M_TOTAL * D_MODEL];
__device__ __half g_V[(size_t)M_TOTAL * D_MODEL];
__device__ __half g_A[(size_t)M_TOTAL * D_MODEL];
// transposed weights (W^T: row n, col k) — fp16
__device__ __half g_wq[D_MODEL * D_MODEL];
__device__ __half g_wk[D_MODEL * D_MODEL];
__device__ __half g_wv[D_MODEL * D_MODEL];
__device__ __half g_wo[D_MODEL * D_MODEL];

// ---------------------------------------------------------------------------
// PTX helpers (base ISA only)
// ---------------------------------------------------------------------------
__device__ __forceinline__ uint32_t smem_u32(const void* p) {
    uint32_t a;
    asm("{ .reg .u64 t; cvta.to.shared.u64 t, %1; cvt.u32.u64 %0, t; }" : "=r"(a) : "l"(p));
    return a;
}
__device__ __forceinline__ void cp16(uint32_t dst, const void* src) {
    asm volatile("cp.async.cg.shared.global [%0], [%1], 16;" :: "r"(dst), "l"(src));
}
#define CP_COMMIT() asm volatile("cp.async.commit_group;" ::: "memory")
#define CP_WAIT1()  asm volatile("cp.async.wait_group 1;" ::: "memory")
#define CP_WAIT0()  asm volatile("cp.async.wait_group 0;" ::: "memory")

#define LDSM4(r0, r1, r2, r3, addr) \
    asm volatile("ldmatrix.sync.aligned.m8n8.x4.shared.b16 {%0,%1,%2,%3}, [%4];" \
        : "=r"(r0), "=r"(r1), "=r"(r2), "=r"(r3) : "r"(addr))

#define LDSM4T(r0, r1, r2, r3, addr) \
    asm volatile("ldmatrix.sync.aligned.m8n8.x4.trans.shared.b16 {%0,%1,%2,%3}, [%4];" \
        : "=r"(r0), "=r"(r1), "=r"(r2), "=r"(r3) : "r"(addr))

#define MMA_F32(c, a, b0, b1) \
    asm volatile("mma.sync.aligned.m16n8k16.row.col.f32.f16.f16.f32 " \
        "{%0,%1,%2,%3}, {%4,%5,%6,%7}, {%8,%9}, {%0,%1,%2,%3};" \
        : "+f"((c)[0]), "+f"((c)[1]), "+f"((c)[2]), "+f"((c)[3]) \
        : "r"((a)[0]), "r"((a)[1]), "r"((a)[2]), "r"((a)[3]), "r"(b0), "r"(b1))

__device__ __forceinline__ uint32_t packh2(float x, float y) {
    __half2 h = __floats2half2_rn(x, y);
    return *reinterpret_cast<uint32_t*>(&h);
}

// fast exp2 on FMA pipe (t <= 0), rel err ~1e-6
__device__ __forceinline__ float fexp2(float t) {
    t = fmaxf(t, -100.f);
    float fi = floorf(t);
    float f  = t - fi;
    float p  = 1.0178086e-5f;
    p = fmaf(p, f, 1.5403530e-4f);
    p = fmaf(p, f, 1.3333558e-3f);
    p = fmaf(p, f, 9.6181291e-3f);
    p = fmaf(p, f, 5.5504109e-2f);
    p = fmaf(p, f, 2.4022651e-1f);
    p = fmaf(p, f, 6.9314718e-1f);
    p = fmaf(p, f, 1.0f);
    return p * __int_as_float(((int)fi + 127) << 23);
}

// ---------------------------------------------------------------------------
// Convert fp32 -> fp16 (vectorized, grid-stride)
// ---------------------------------------------------------------------------
__global__ void fconv_kernel(const float4* __restrict__ in,
                             uint32_t* __restrict__ out, int n4)
{
    for (int i = blockIdx.x * blockDim.x + threadIdx.x; i < n4; i += gridDim.x * blockDim.x) {
        float4 v = in[i];
        out[i * 2 + 0] = packh2(v.x, v.y);
        out[i * 2 + 1] = packh2(v.z, v.w);
    }
}

// ---------------------------------------------------------------------------
// Transpose + convert W[1024][1024] -> Wt fp16 (Wt[n][k] = W[k][n])
// ---------------------------------------------------------------------------
__global__ void wconv_kernel(const float* __restrict__ W, __half* __restrict__ T)
{
    __shared__ float t[32][33];
    int bx = blockIdx.x * 32, by = blockIdx.y * 32;
    int x = threadIdx.x, y = threadIdx.y;
    #pragma unroll
    for (int d = 0; d < 32; d += 8)
        t[y + d][x] = W[(size_t)(by + y + d) * D_MODEL + bx + x];
    __syncthreads();
    #pragma unroll
    for (int d = 0; d < 32; d += 8)
        T[(size_t)(bx + y + d) * D_MODEL + by + x] = __float2half_rn(t[x][y + d]);
}

// ---------------------------------------------------------------------------
// fp16 GEMM: C = A B^T + bias.  CTA 128x256, BK=32, 3-stage cp.async pipeline.
// 8 warps, warp tile 64x64.  F32OUT: fp32 C; else fp16 C.
// smem/stage: A 128x80B + B 256x80B = 30720 B; 3 stages = 92160 B.
// ---------------------------------------------------------------------------
#define A_PLANE   10240
#define B_PLANE   20480
#define STAGE_B   30720
#define GEMM_SMEM (3 * STAGE_B)
#define KCHUNKS   32

template<bool F32OUT>
__global__ __launch_bounds__(256)
void gemm_f16(const __half* __restrict__ A, const __half* __restrict__ B,
              const float* __restrict__ bias,
              float* __restrict__ C, __half* __restrict__ Ch)
{
    extern __shared__ char smem_raw[];
    const uint32_t sbase = smem_u32(smem_raw);

    const int tid    = threadIdx.x;
    const int wid    = tid >> 5;
    const int lane   = tid & 31;
    const int warp_m = (wid >> 2) * 64;
    const int warp_n = (wid & 3) * 64;
    const size_t m0  = (size_t)blockIdx.y * 128;
    const size_t n0  = (size_t)blockIdx.x * 256;

    const char* sA = (const char*)(A + m0 * D_MODEL);
    const char* sB = (const char*)(B + n0 * D_MODEL);

    auto fill = [&](int stage, int kc) {
        const uint32_t st = sbase + stage * STAGE_B;
        const size_t ko = (size_t)kc * 64;
        #pragma unroll
        for (int i = 0; i < 2; i++) {
            int c = tid + i * 256, row = c >> 2, col = c & 3;
            cp16(st + row * 80 + col * 16, sA + (size_t)row * 2048 + ko + col * 16);
        }
        #pragma unroll
        for (int i = 0; i < 4; i++) {
            int c = tid + i * 256, row = c >> 2, col = c & 3;
            cp16(st + A_PLANE + row * 80 + col * 16, sB + (size_t)row * 2048 + ko + col * 16);
        }
        CP_COMMIT();
    };

    float acc[4][8][4];
    #pragma unroll
    for (int i = 0; i < 4; i++)
        #pragma unroll
        for (int j = 0; j < 8; j++)
            #pragma unroll
            for (int q = 0; q < 4; q++) acc[i][j][q] = 0.f;

    fill(0, 0);
    fill(1, 1);

    const int lr = lane & 7, g = lane >> 3;
    const uint32_t a_loff = (uint32_t)((lr + (g & 1) * 8) * 80 + (g >> 1) * 16);
    const uint32_t b_loff = (uint32_t)((lr + (g >> 1) * 8) * 80 + (g & 1) * 16);

    for (int j = 0; j < KCHUNKS; j++) {
        CP_WAIT1();
        __syncthreads();
        if (j + 2 < KCHUNKS) fill((j + 2) % 3, j + 2);
        else CP_COMMIT();

        const uint32_t st = sbase + (j % 3) * STAGE_B;
        const uint32_t aP = st +           warp_m * 80 + a_loff;
        const uint32_t bP = st + A_PLANE + warp_n * 80 + b_loff;

        #pragma unroll
        for (int ks = 0; ks < 2; ks++) {
            const uint32_t ko = ks * 32;
            uint32_t a_r[4][4], b_r[16];

            #pragma unroll
            for (int mt = 0; mt < 4; mt++)
                LDSM4(a_r[mt][0], a_r[mt][1], a_r[mt][2], a_r[mt][3],
                      aP + mt * (16 * 80) + ko);
            #pragma unroll
            for (int p = 0; p < 4; p++)
                LDSM4(b_r[p*4+0], b_r[p*4+1], b_r[p*4+2], b_r[p*4+3],
                      bP + p * (16 * 80) + ko);

            #pragma unroll
            for (int mt = 0; mt < 4; mt++)
                #pragma unroll
                for (int nt = 0; nt < 8; nt++)
                    MMA_F32(acc[mt][nt], a_r[mt], b_r[nt*2], b_r[nt*2+1]);
        }
    }

    #pragma unroll
    for (int mt = 0; mt < 4; mt++) {
        #pragma unroll
        for (int nt = 0; nt < 8; nt++) {
            int row0 = (int)m0 + warp_m + mt * 16 + (lane >> 2);
            int colg = (int)n0 + warp_n + nt * 8 + (lane & 3) * 2;
            float2 bv = *reinterpret_cast<const float2*>(bias + colg);
            float o00 = acc[mt][nt][0] + bv.x, o01 = acc[mt][nt][1] + bv.y;
            float o10 = acc[mt][nt][2] + bv.x, o11 = acc[mt][nt][3] + bv.y;
            size_t off0 = (size_t)row0 * D_MODEL + colg;
            size_t off1 = off0 + 8 * D_MODEL;
            if constexpr (F32OUT) {
                float2 a{o00, o01}, b{o10, o11};
                *reinterpret_cast<float2*>(C + off0) = a;
                *reinterpret_cast<float2*>(C + off1) = b;
            } else {
                *reinterpret_cast<uint32_t*>(Ch + off0) = packh2(o00, o01);
                *reinterpret_cast<uint32_t*>(Ch + off1) = packh2(o10, o11);
            }
        }
    }
}

// ---------------------------------------------------------------------------
// Tensor-core patch attention (fp16, fragment softmax, poly exp, trans-LDSM V).
// grid = (NUM_HEADS, NBLK), 256 threads (8 warps; warp w owns rows 16w..16w+15).
// smem: Q,K,V each [128][72] fp16 (144B stride) = 55296 B.
// ---------------------------------------------------------------------------
#define QK_STRIDE_B 144          // 72 fp16
#define OFF_Q 0
#define OFF_K 18432
#define OFF_V 36864
#define ATTN_SMEM 55296

__global__ __launch_bounds__(256, 2)
void attn_mma_kernel()
{
    extern __shared__ char smc[];
    const uint32_t sb = smem_u32(smc);

    const int h   = blockIdx.x;
    const int pb  = blockIdx.y;
    const int tid = threadIdx.x;
    const int wid = tid >> 5;
    const int lane = tid & 31;
    const size_t base = (size_t)pb * 128 * D_MODEL + (size_t)h * D_HEAD;

    // stage Q, K, V via cp.async (rows of 64 fp16 = 128 B = 8 x 16B, 144B stride)
    {
        const char* gq = (const char*)(g_Q + base);
        const char* gk = (const char*)(g_K + base);
        const char* gv = (const char*)(g_V + base);
        #pragma unroll
        for (int i = 0; i < 4; i++) {
            int idx = tid + i * 256;
            int row = idx >> 3, ch = idx & 7;
            uint32_t so = row * QK_STRIDE_B + ch * 16;
            size_t  go = (size_t)row * 2048 + ch * 16;
            cp16(sb + OFF_Q + so, gq + go);
            cp16(sb + OFF_K + so, gk + go);
            cp16(sb + OFF_V + so, gv + go);
        }
        CP_COMMIT();
    }
    CP_WAIT0();
    __syncthreads();

    const int lr = lane & 7, g = lane >> 3;
    const uint32_t a_off = (uint32_t)((lr + (g & 1) * 8) * QK_STRIDE_B + (g >> 1) * 16);
    const uint32_t b_off = (uint32_t)((lr + (g >> 1) * 8) * QK_STRIDE_B + (g & 1) * 16);
    // trans-LDSM for V: lanes 0-15 -> rows kv0..15 (col group d0), lanes 16-31 -> col group d0+8
    const uint32_t v_off = (uint32_t)((lane & 15) * QK_STRIDE_B + (lane >> 4) * 16);

    // ---- S = Q K^T ----
    float cf[16][4];
    #pragma unroll
    for (int i = 0; i < 16; i++)
        #pragma unroll
        for (int q = 0; q < 4; q++) cf[i][q] = 0.f;

    const uint32_t q0 = sb + OFF_Q + wid * (16 * QK_STRIDE_B) + a_off;

    #pragma unroll
    for (int ks = 0; ks < 4; ks++) {
        const uint32_t ko = ks * 32;
        uint32_t aq[4];
        LDSM4(aq[0], aq[1], aq[2], aq[3], q0 + ko);
        #pragma unroll
        for (int p = 0; p < 8; p++) {
            uint32_t kh[4];
            LDSM4(kh[0], kh[1], kh[2], kh[3], sb + OFF_K + p * (16 * QK_STRIDE_B) + b_off + ko);
            MMA_F32(cf[2*p],   aq, kh[0], kh[1]);
            MMA_F32(cf[2*p+1], aq, kh[2], kh[3]);
        }
    }

    // ---- fragment softmax ----
    float mx0 = -CUDART_INF_F, mx1 = -CUDART_INF_F;
    #pragma unroll
    for (int nt = 0; nt < 16; nt++) {
        mx0 = fmaxf(mx0, fmaxf(cf[nt][0], cf[nt][1]));
        mx1 = fmaxf(mx1, fmaxf(cf[nt][2], cf[nt][3]));
    }
    mx0 = fmaxf(mx0, __shfl_xor_sync(0xffffffffu, mx0, 1));
    mx0 = fmaxf(mx0, __shfl_xor_sync(0xffffffffu, mx0, 2));
    mx1 = fmaxf(mx1, __shfl_xor_sync(0xffffffffu, mx1, 1));
    mx1 = fmaxf(mx1, __shfl_xor_sync(0xffffffffu, mx1, 2));

    const float CS = 0.125f * 1.4426950408889634f;   // log2(e)/sqrt(64)
    float l0 = 0.f, l1 = 0.f;
    #pragma unroll
    for (int nt = 0; nt < 16; nt++) {
        float p0 = fexp2((cf[nt][0] - mx0) * CS);
        float p1 = fexp2((cf[nt][1] - mx0) * CS);
        float p2 = fexp2((cf[nt][2] - mx1) * CS);
        float p3 = fexp2((cf[nt][3] - mx1) * CS);
        cf[nt][0] = p0; cf[nt][1] = p1; cf[nt][2] = p2; cf[nt][3] = p3;
        l0 += p0 + p1; l1 += p2 + p3;
    }
    l0 += __shfl_xor_sync(0xffffffffu, l0, 1);
    l0 += __shfl_xor_sync(0xffffffffu, l0, 2);
    l1 += __shfl_xor_sync(0xffffffffu, l1, 1);
    l1 += __shfl_xor_sync(0xffffffffu, l1, 2);
    const float inv0 = 1.f / l0, inv1 = 1.f / l1;

    // ---- O = P V (B-frags via ldmatrix.trans from row-major V) ----
    float of[8][4];
    #pragma unroll
    for (int i = 0; i < 8; i++)
        #pragma unroll
        for (int q = 0; q < 4; q++) of[i][q] = 0.f;

    #pragma unroll
    for (int kt = 0; kt < 8; kt++) {
        uint32_t ah[4];
        ah[0] = packh2(cf[2*kt][0],   cf[2*kt][1]);
        ah[1] = packh2(cf[2*kt][2],   cf[2*kt][3]);
        ah[2] = packh2(cf[2*kt+1][0], cf[2*kt+1][1]);
        ah[3] = packh2(cf[2*kt+1][2], cf[2*kt+1][3]);
        const uint32_t vrow = sb + OFF_V + kt * (16 * QK_STRIDE_B) + v_off;
        #pragma unroll
        for (int np = 0; np < 4; np++) {
            uint32_t vh[4];
            LDSM4T(vh[0], vh[1], vh[2], vh[3], vrow + np * 32);
            MMA_F32(of[2*np],   ah, vh[0], vh[1]);
            MMA_F32(of[2*np+1], ah, vh[2], vh[3]);
        }
    }

    // ---- write A = softmax(S)V as fp16 ----
    const int row  = pb * 128 + wid * 16 + (lane >> 2);
    const int colb = h * 64 + (lane & 3) * 2;
    #pragma unroll
    for (int nt = 0; nt < 8; nt++) {
        size_t off0 = (size_t)row * D_MODEL + colb + nt * 8;
        size_t off1 = off0 + 8 * D_MODEL;
        *reinterpret_cast<uint32_t*>(g_A + off0) = packh2(of[nt][0] * inv0, of[nt][1] * inv0);
        *reinterpret_cast<uint32_t*>(g_A + off1) = packh2(of[nt][2] * inv1, of[nt][3] * inv1);
    }
}

// ---------------------------------------------------------------------------
extern "C" void kernel_launch(void* const* d_in, const int* in_sizes, int n_in,
                              void* d_out, int out_size)
{
    const float* x  = (const float*)d_in[0];
    // d_in[1] = coords (unused by reference)
    const float* Wq = (const float*)d_in[2];
    const float* bq = (const float*)d_in[3];
    const float* Wk = (const float*)d_in[4];
    const float* bk = (const float*)d_in[5];
    const float* Wv = (const float*)d_in[6];
    const float* bv = (const float*)d_in[7];
    const float* Wo = (const float*)d_in[8];
    const float* bo = (const float*)d_in[9];
    float* out = (float*)d_out;

    __half *xh, *Qp, *Kp, *Vp, *Ap, *wq, *wk, *wv, *wo;
    cudaGetSymbolAddress((void**)&xh, g_x);
    cudaGetSymbolAddress((void**)&Qp, g_Q);
    cudaGetSymbolAddress((void**)&Kp, g_K);
    cudaGetSymbolAddress((void**)&Vp, g_V);
    cudaGetSymbolAddress((void**)&Ap, g_A);
    cudaGetSymbolAddress((void**)&wq, g_wq);
    cudaGetSymbolAddress((void**)&wk, g_wk);
    cudaGetSymbolAddress((void**)&wv, g_wv);
    cudaGetSymbolAddress((void**)&wo, g_wo);

    cudaFuncSetAttribute(gemm_f16<true>,  cudaFuncAttributeMaxDynamicSharedMemorySize, GEMM_SMEM);
    cudaFuncSetAttribute(gemm_f16<false>, cudaFuncAttributeMaxDynamicSharedMemorySize, GEMM_SMEM);
    cudaFuncSetAttribute(attn_mma_kernel, cudaFuncAttributeMaxDynamicSharedMemorySize, ATTN_SMEM);

    // launches 1-4: transpose + convert weights
    dim3 wgrid(32, 32), wblk(32, 8);
    wconv_kernel<<<wgrid, wblk>>>(Wq, wq);
    wconv_kernel<<<wgrid, wblk>>>(Wk, wk);
    wconv_kernel<<<wgrid, wblk>>>(Wv, wv);
    wconv_kernel<<<wgrid, wblk>>>(Wo, wo);
    // launch 5: convert x -> fp16
    fconv_kernel<<<8192, 256>>>((const float4*)x, (uint32_t*)xh, M_TOTAL * D_MODEL / 4);

    // launches 6-8: Q/K/V projections (fp16 out)
    dim3 ggrid(D_MODEL / 256, M_TOTAL / 128);   // (4, 256)
    gemm_f16<false><<<ggrid, 256, GEMM_SMEM>>>(xh, wq, bq, nullptr, Qp);
    gemm_f16<false><<<ggrid, 256, GEMM_SMEM>>>(xh, wk, bk, nullptr, Kp);
    gemm_f16<false><<<ggrid, 256, GEMM_SMEM>>>(xh, wv, bv, nullptr, Vp);

    // launch 9: tensor-core attention (fp16 A)
    dim3 agrid(NUM_HEADS, NBLK);
    attn_mma_kernel<<<agrid, 256, ATTN_SMEM>>>();

    // launch 10: output projection (fp32 out)
    gemm_f16<true><<<ggrid, 256, GEMM_SMEM>>>(Ap, wo, bo, out, nullptr);
}

// round 10
// speedup vs baseline: 7.0130x; 1.0294x over previous
#include <cuda_runtime.h>
#include <cuda_fp16.h>
#include <math_constants.h>
#include <cstdint>

#define D_MODEL   1024
#define NUM_HEADS 16
#define D_HEAD    64
#define PATCH     128
#define BATCH     4
#define SEQ       8192
#define M_TOTAL   (BATCH * SEQ)          // 32768 rows
#define NBLK      (M_TOTAL / PATCH)      // 256 patch blocks

// ---------------------------------------------------------------------------
// Scratch (static device globals — no runtime allocation)
// ---------------------------------------------------------------------------
__device__ __half g_x[(size_t)M_TOTAL * D_MODEL];
__device__ __half g_Q[(size_t)M_TOTAL * D_MODEL];
__device__ __half g_K[(size_t)M_TOTAL * D_MODEL];
__device__ __half g_V[(size_t)M_TOTAL * D_MODEL];
__device__ __half g_A[(size_t)M_TOTAL * D_MODEL];
// transposed weights, 4 planes: 0=Wq^T,1=Wk^T,2=Wv^T,3=Wo^T (row n, col k)
__device__ __half g_w[(size_t)4 * D_MODEL * D_MODEL];

// ---------------------------------------------------------------------------
// PTX helpers (base ISA only)
// ---------------------------------------------------------------------------
__device__ __forceinline__ uint32_t smem_u32(const void* p) {
    uint32_t a;
    asm("{ .reg .u64 t; cvta.to.shared.u64 t, %1; cvt.u32.u64 %0, t; }" : "=r"(a) : "l"(p));
    return a;
}
__device__ __forceinline__ void cp16(uint32_t dst, const void* src) {
    asm volatile("cp.async.cg.shared.global [%0], [%1], 16;" :: "r"(dst), "l"(src));
}
#define CP_COMMIT() asm volatile("cp.async.commit_group;" ::: "memory")
#define CP_WAIT1()  asm volatile("cp.async.wait_group 1;" ::: "memory")
#define CP_WAIT0()  asm volatile("cp.async.wait_group 0;" ::: "memory")

#define LDSM4(r0, r1, r2, r3, addr) \
    asm volatile("ldmatrix.sync.aligned.m8n8.x4.shared.b16 {%0,%1,%2,%3}, [%4];" \
        : "=r"(r0), "=r"(r1), "=r"(r2), "=r"(r3) : "r"(addr))

#define LDSM4T(r0, r1, r2, r3, addr) \
    asm volatile("ldmatrix.sync.aligned.m8n8.x4.trans.shared.b16 {%0,%1,%2,%3}, [%4];" \
        : "=r"(r0), "=r"(r1), "=r"(r2), "=r"(r3) : "r"(addr))

#define MMA_F32(c, a, b0, b1) \
    asm volatile("mma.sync.aligned.m16n8k16.row.col.f32.f16.f16.f32 " \
        "{%0,%1,%2,%3}, {%4,%5,%6,%7}, {%8,%9}, {%0,%1,%2,%3};" \
        : "+f"((c)[0]), "+f"((c)[1]), "+f"((c)[2]), "+f"((c)[3]) \
        : "r"((a)[0]), "r"((a)[1]), "r"((a)[2]), "r"((a)[3]), "r"(b0), "r"(b1))

__device__ __forceinline__ uint32_t packh2(float x, float y) {
    __half2 h = __floats2half2_rn(x, y);
    return *reinterpret_cast<uint32_t*>(&h);
}
// single-MUFU exp2 (inputs <= 0 here; approx err ~2^-22)
__device__ __forceinline__ float ex2f(float x) {
    float r;
    asm("ex2.approx.f32 %0, %1;" : "=f"(r) : "f"(x));
    return r;
}

// ---------------------------------------------------------------------------
// Convert fp32 -> fp16 (vectorized, grid-stride)
// ---------------------------------------------------------------------------
__global__ void fconv_kernel(const float4* __restrict__ in,
                             uint32_t* __restrict__ out, int n4)
{
    for (int i = blockIdx.x * blockDim.x + threadIdx.x; i < n4; i += gridDim.x * blockDim.x) {
        float4 v = in[i];
        out[i * 2 + 0] = packh2(v.x, v.y);
        out[i * 2 + 1] = packh2(v.z, v.w);
    }
}

// ---------------------------------------------------------------------------
// Transpose + convert all 4 weights in one launch: grid (32,32,4).
// ---------------------------------------------------------------------------
__global__ void wconv_kernel(const float* __restrict__ W0, const float* __restrict__ W1,
                             const float* __restrict__ W2, const float* __restrict__ W3)
{
    __shared__ float t[32][33];
    const float* W = blockIdx.z == 0 ? W0 : blockIdx.z == 1 ? W1 : blockIdx.z == 2 ? W2 : W3;
    __half* T = g_w + (size_t)blockIdx.z * D_MODEL * D_MODEL;
    int bx = blockIdx.x * 32, by = blockIdx.y * 32;
    int x = threadIdx.x, y = threadIdx.y;
    #pragma unroll
    for (int d = 0; d < 32; d += 8)
        t[y + d][x] = W[(size_t)(by + y + d) * D_MODEL + bx + x];
    __syncthreads();
    #pragma unroll
    for (int d = 0; d < 32; d += 8)
        T[(size_t)(bx + y + d) * D_MODEL + by + x] = __float2half_rn(t[x][y + d]);
}

// ---------------------------------------------------------------------------
// fp16 GEMM: out_plane = A @ Bplane^T + bias_plane.  CTA 128x256, BK=32,
// 3-stage cp.async pipeline, 8 warps, warp tile 64x64.
// B has grid.x/4 planes of 1024 rows; plane = blockIdx.x>>2 selects
// bias (b0/b1/b2) and output (o0/o1/o2).  F32OUT: fp32 into C (plane 0 only).
// ---------------------------------------------------------------------------
#define A_PLANE   10240
#define STAGE_B   30720
#define GEMM_SMEM (3 * STAGE_B)
#define KCHUNKS   32

template<bool F32OUT>
__global__ __launch_bounds__(256)
void gemm_f16(const __half* __restrict__ A, const __half* __restrict__ B,
              const float* __restrict__ b0, const float* __restrict__ b1,
              const float* __restrict__ b2,
              float* __restrict__ C,
              __half* __restrict__ o0, __half* __restrict__ o1,
              __half* __restrict__ o2)
{
    extern __shared__ char smem_raw[];
    const uint32_t sbase = smem_u32(smem_raw);

    const int tid    = threadIdx.x;
    const int wid    = tid >> 5;
    const int lane   = tid & 31;
    const int warp_m = (wid >> 2) * 64;
    const int warp_n = (wid & 3) * 64;
    const size_t m0  = (size_t)blockIdx.y * 128;
    const size_t n0  = (size_t)blockIdx.x * 256;     // row in (possibly multi-plane) B
    const int plane  = blockIdx.x >> 2;
    const int col0   = (blockIdx.x & 3) * 256;       // column within output plane

    const float* bias = plane == 0 ? b0 : plane == 1 ? b1 : b2;
    __half* Ch        = plane == 0 ? o0 : plane == 1 ? o1 : o2;

    const char* sA = (const char*)(A + m0 * D_MODEL);
    const char* sB = (const char*)(B + n0 * D_MODEL);

    auto fill = [&](int stage, int kc) {
        const uint32_t st = sbase + stage * STAGE_B;
        const size_t ko = (size_t)kc * 64;
        #pragma unroll
        for (int i = 0; i < 2; i++) {
            int c = tid + i * 256, row = c >> 2, col = c & 3;
            cp16(st + row * 80 + col * 16, sA + (size_t)row * 2048 + ko + col * 16);
        }
        #pragma unroll
        for (int i = 0; i < 4; i++) {
            int c = tid + i * 256, row = c >> 2, col = c & 3;
            cp16(st + A_PLANE + row * 80 + col * 16, sB + (size_t)row * 2048 + ko + col * 16);
        }
        CP_COMMIT();
    };

    float acc[4][8][4];
    #pragma unroll
    for (int i = 0; i < 4; i++)
        #pragma unroll
        for (int j = 0; j < 8; j++)
            #pragma unroll
            for (int q = 0; q < 4; q++) acc[i][j][q] = 0.f;

    fill(0, 0);
    fill(1, 1);

    const int lr = lane & 7, g = lane >> 3;
    const uint32_t a_loff = (uint32_t)((lr + (g & 1) * 8) * 80 + (g >> 1) * 16);
    const uint32_t b_loff = (uint32_t)((lr + (g >> 1) * 8) * 80 + (g & 1) * 16);

    for (int j = 0; j < KCHUNKS; j++) {
        CP_WAIT1();
        __syncthreads();
        if (j + 2 < KCHUNKS) fill((j + 2) % 3, j + 2);
        else CP_COMMIT();

        const uint32_t st = sbase + (j % 3) * STAGE_B;
        const uint32_t aP = st +           warp_m * 80 + a_loff;
        const uint32_t bP = st + A_PLANE + warp_n * 80 + b_loff;

        #pragma unroll
        for (int ks = 0; ks < 2; ks++) {
            const uint32_t ko = ks * 32;
            uint32_t a_r[4][4], b_r[16];

            #pragma unroll
            for (int mt = 0; mt < 4; mt++)
                LDSM4(a_r[mt][0], a_r[mt][1], a_r[mt][2], a_r[mt][3],
                      aP + mt * (16 * 80) + ko);
            #pragma unroll
            for (int p = 0; p < 4; p++)
                LDSM4(b_r[p*4+0], b_r[p*4+1], b_r[p*4+2], b_r[p*4+3],
                      bP + p * (16 * 80) + ko);

            #pragma unroll
            for (int mt = 0; mt < 4; mt++)
                #pragma unroll
                for (int nt = 0; nt < 8; nt++)
                    MMA_F32(acc[mt][nt], a_r[mt], b_r[nt*2], b_r[nt*2+1]);
        }
    }

    #pragma unroll
    for (int mt = 0; mt < 4; mt++) {
        #pragma unroll
        for (int nt = 0; nt < 8; nt++) {
            int row0 = (int)m0 + warp_m + mt * 16 + (lane >> 2);
            int colg = col0 + warp_n + nt * 8 + (lane & 3) * 2;
            float2 bv = *reinterpret_cast<const float2*>(bias + colg);
            float o00 = acc[mt][nt][0] + bv.x, o01 = acc[mt][nt][1] + bv.y;
            float o10 = acc[mt][nt][2] + bv.x, o11 = acc[mt][nt][3] + bv.y;
            size_t off0 = (size_t)row0 * D_MODEL + colg;
            size_t off1 = off0 + 8 * D_MODEL;
            if constexpr (F32OUT) {
                float2 a{o00, o01}, b{o10, o11};
                *reinterpret_cast<float2*>(C + off0) = a;
                *reinterpret_cast<float2*>(C + off1) = b;
            } else {
                *reinterpret_cast<uint32_t*>(Ch + off0) = packh2(o00, o01);
                *reinterpret_cast<uint32_t*>(Ch + off1) = packh2(o10, o11);
            }
        }
    }
}

// ---------------------------------------------------------------------------
// Tensor-core patch attention (fp16, fragment softmax, MUFU ex2, trans-LDSM V).
// grid = (NUM_HEADS, NBLK), 256 threads (8 warps; warp w owns rows 16w..16w+15).
// smem: Q,K,V each [128][72] fp16 (144B stride) = 55296 B.
// ---------------------------------------------------------------------------
#define QK_STRIDE_B 144          // 72 fp16
#define OFF_Q 0
#define OFF_K 18432
#define OFF_V 36864
#define ATTN_SMEM 55296

__global__ __launch_bounds__(256, 2)
void attn_mma_kernel()
{
    extern __shared__ char smc[];
    const uint32_t sb = smem_u32(smc);

    const int h   = blockIdx.x;
    const int pb  = blockIdx.y;
    const int tid = threadIdx.x;
    const int wid = tid >> 5;
    const int lane = tid & 31;
    const size_t base = (size_t)pb * 128 * D_MODEL + (size_t)h * D_HEAD;

    // stage Q, K, V via cp.async (rows of 64 fp16 = 128 B = 8 x 16B, 144B stride)
    {
        const char* gq = (const char*)(g_Q + base);
        const char* gk = (const char*)(g_K + base);
        const char* gv = (const char*)(g_V + base);
        #pragma unroll
        for (int i = 0; i < 4; i++) {
            int idx = tid + i * 256;
            int row = idx >> 3, ch = idx & 7;
            uint32_t so = row * QK_STRIDE_B + ch * 16;
            size_t  go = (size_t)row * 2048 + ch * 16;
            cp16(sb + OFF_Q + so, gq + go);
            cp16(sb + OFF_K + so, gk + go);
            cp16(sb + OFF_V + so, gv + go);
        }
        CP_COMMIT();
    }
    CP_WAIT0();
    __syncthreads();

    const int lr = lane & 7, g = lane >> 3;
    const uint32_t a_off = (uint32_t)((lr + (g & 1) * 8) * QK_STRIDE_B + (g >> 1) * 16);
    const uint32_t b_off = (uint32_t)((lr + (g >> 1) * 8) * QK_STRIDE_B + (g & 1) * 16);
    const uint32_t v_off = (uint32_t)((lane & 15) * QK_STRIDE_B + (lane >> 4) * 16);

    // ---- S = Q K^T ----
    float cf[16][4];
    #pragma unroll
    for (int i = 0; i < 16; i++)
        #pragma unroll
        for (int q = 0; q < 4; q++) cf[i][q] = 0.f;

    const uint32_t q0 = sb + OFF_Q + wid * (16 * QK_STRIDE_B) + a_off;

    #pragma unroll
    for (int ks = 0; ks < 4; ks++) {
        const uint32_t ko = ks * 32;
        uint32_t aq[4];
        LDSM4(aq[0], aq[1], aq[2], aq[3], q0 + ko);
        #pragma unroll
        for (int p = 0; p < 8; p++) {
            uint32_t kh[4];
            LDSM4(kh[0], kh[1], kh[2], kh[3], sb + OFF_K + p * (16 * QK_STRIDE_B) + b_off + ko);
            MMA_F32(cf[2*p],   aq, kh[0], kh[1]);
            MMA_F32(cf[2*p+1], aq, kh[2], kh[3]);
        }
    }

    // ---- fragment softmax (MUFU exp2) ----
    float mx0 = -CUDART_INF_F, mx1 = -CUDART_INF_F;
    #pragma unroll
    for (int nt = 0; nt < 16; nt++) {
        mx0 = fmaxf(mx0, fmaxf(cf[nt][0], cf[nt][1]));
        mx1 = fmaxf(mx1, fmaxf(cf[nt][2], cf[nt][3]));
    }
    mx0 = fmaxf(mx0, __shfl_xor_sync(0xffffffffu, mx0, 1));
    mx0 = fmaxf(mx0, __shfl_xor_sync(0xffffffffu, mx0, 2));
    mx1 = fmaxf(mx1, __shfl_xor_sync(0xffffffffu, mx1, 1));
    mx1 = fmaxf(mx1, __shfl_xor_sync(0xffffffffu, mx1, 2));

    const float CS = 0.125f * 1.4426950408889634f;   // log2(e)/sqrt(64)
    float l0 = 0.f, l1 = 0.f;
    #pragma unroll
    for (int nt = 0; nt < 16; nt++) {
        float p0 = ex2f((cf[nt][0] - mx0) * CS);
        float p1 = ex2f((cf[nt][1] - mx0) * CS);
        float p2 = ex2f((cf[nt][2] - mx1) * CS);
        float p3 = ex2f((cf[nt][3] - mx1) * CS);
        cf[nt][0] = p0; cf[nt][1] = p1; cf[nt][2] = p2; cf[nt][3] = p3;
        l0 += p0 + p1; l1 += p2 + p3;
    }
    l0 += __shfl_xor_sync(0xffffffffu, l0, 1);
    l0 += __shfl_xor_sync(0xffffffffu, l0, 2);
    l1 += __shfl_xor_sync(0xffffffffu, l1, 1);
    l1 += __shfl_xor_sync(0xffffffffu, l1, 2);
    const float inv0 = 1.f / l0, inv1 = 1.f / l1;

    // ---- O = P V (B-frags via ldmatrix.trans from row-major V) ----
    float of[8][4];
    #pragma unroll
    for (int i = 0; i < 8; i++)
        #pragma unroll
        for (int q = 0; q < 4; q++) of[i][q] = 0.f;

    #pragma unroll
    for (int kt = 0; kt < 8; kt++) {
        uint32_t ah[4];
        ah[0] = packh2(cf[2*kt][0],   cf[2*kt][1]);
        ah[1] = packh2(cf[2*kt][2],   cf[2*kt][3]);
        ah[2] = packh2(cf[2*kt+1][0], cf[2*kt+1][1]);
        ah[3] = packh2(cf[2*kt+1][2], cf[2*kt+1][3]);
        const uint32_t vrow = sb + OFF_V + kt * (16 * QK_STRIDE_B) + v_off;
        #pragma unroll
        for (int np = 0; np < 4; np++) {
            uint32_t vh[4];
            LDSM4T(vh[0], vh[1], vh[2], vh[3], vrow + np * 32);
            MMA_F32(of[2*np],   ah, vh[0], vh[1]);
            MMA_F32(of[2*np+1], ah, vh[2], vh[3]);
        }
    }

    // ---- write A = softmax(S)V as fp16 ----
    const int row  = pb * 128 + wid * 16 + (lane >> 2);
    const int colb = h * 64 + (lane & 3) * 2;
    #pragma unroll
    for (int nt = 0; nt < 8; nt++) {
        size_t off0 = (size_t)row * D_MODEL + colb + nt * 8;
        size_t off1 = off0 + 8 * D_MODEL;
        *reinterpret_cast<uint32_t*>(g_A + off0) = packh2(of[nt][0] * inv0, of[nt][1] * inv0);
        *reinterpret_cast<uint32_t*>(g_A + off1) = packh2(of[nt][2] * inv1, of[nt][3] * inv1);
    }
}

// ---------------------------------------------------------------------------
extern "C" void kernel_launch(void* const* d_in, const int* in_sizes, int n_in,
                              void* d_out, int out_size)
{
    const float* x  = (const float*)d_in[0];
    // d_in[1] = coords (unused by reference)
    const float* Wq = (const float*)d_in[2];
    const float* bq = (const float*)d_in[3];
    const float* Wk = (const float*)d_in[4];
    const float* bk = (const float*)d_in[5];
    const float* Wv = (const float*)d_in[6];
    const float* bv = (const float*)d_in[7];
    const float* Wo = (const float*)d_in[8];
    const float* bo = (const float*)d_in[9];
    float* out = (float*)d_out;

    __half *xh, *Qp, *Kp, *Vp, *Ap, *wp;
    cudaGetSymbolAddress((void**)&xh, g_x);
    cudaGetSymbolAddress((void**)&Qp, g_Q);
    cudaGetSymbolAddress((void**)&Kp, g_K);
    cudaGetSymbolAddress((void**)&Vp, g_V);
    cudaGetSymbolAddress((void**)&Ap, g_A);
    cudaGetSymbolAddress((void**)&wp, g_w);

    cudaFuncSetAttribute(gemm_f16<true>,  cudaFuncAttributeMaxDynamicSharedMemorySize, GEMM_SMEM);
    cudaFuncSetAttribute(gemm_f16<false>, cudaFuncAttributeMaxDynamicSharedMemorySize, GEMM_SMEM);
    cudaFuncSetAttribute(attn_mma_kernel, cudaFuncAttributeMaxDynamicSharedMemorySize, ATTN_SMEM);

    // launch 1: transpose + convert all weights (planes 0-3 of g_w)
    dim3 wgrid(32, 32, 4), wblk(32, 8);
    wconv_kernel<<<wgrid, wblk>>>(Wq, Wk, Wv, Wo);
    // launch 2: convert x -> fp16
    fconv_kernel<<<8192, 256>>>((const float4*)x, (uint32_t*)xh, M_TOTAL * D_MODEL / 4);

    // launch 3: fused Q/K/V projection (planes 0-2 of g_w), fp16 out
    dim3 qkv_grid(12, M_TOTAL / 128);   // 3072 CTAs
    gemm_f16<false><<<qkv_grid, 256, GEMM_SMEM>>>(xh, wp, bq, bk, bv,
                                                  nullptr, Qp, Kp, Vp);

    // launch 4: tensor-core attention (fp16 A)
    dim3 agrid(NUM_HEADS, NBLK);
    attn_mma_kernel<<<agrid, 256, ATTN_SMEM>>>();

    // launch 5: output projection (plane 3 of g_w), fp32 out
    dim3 o_grid(4, M_TOTAL / 128);
    gemm_f16<true><<<o_grid, 256, GEMM_SMEM>>>(Ap, wp + (size_t)3 * D_MODEL * D_MODEL,
                                               bo, bo, bo, out, nullptr, nullptr, nullptr);
}

// round 11
// speedup vs baseline: 7.3766x; 1.0518x over previous
#include <cuda_runtime.h>
#include <cuda_fp16.h>
#include <math_constants.h>
#include <cstdint>

#define D_MODEL   1024
#define NUM_HEADS 16
#define D_HEAD    64
#define PATCH     128
#define BATCH     4
#define SEQ       8192
#define M_TOTAL   (BATCH * SEQ)          // 32768 rows
#define NBLK      (M_TOTAL / PATCH)      // 256 patch blocks

// ---------------------------------------------------------------------------
// Scratch (static device globals — no runtime allocation)
// ---------------------------------------------------------------------------
__device__ __half g_x[(size_t)M_TOTAL * D_MODEL];
__device__ __half g_Q[(size_t)M_TOTAL * D_MODEL];
__device__ __half g_K[(size_t)M_TOTAL * D_MODEL];
__device__ __half g_V[(size_t)M_TOTAL * D_MODEL];
__device__ __half g_A[(size_t)M_TOTAL * D_MODEL];
// transposed weights, 4 planes: 0=Wq^T,1=Wk^T,2=Wv^T,3=Wo^T (row n, col k)
__device__ __half g_w[(size_t)4 * D_MODEL * D_MODEL];

// ---------------------------------------------------------------------------
// PTX helpers (base ISA only)
// ---------------------------------------------------------------------------
__device__ __forceinline__ uint32_t smem_u32(const void* p) {
    uint32_t a;
    asm("{ .reg .u64 t; cvta.to.shared.u64 t, %1; cvt.u32.u64 %0, t; }" : "=r"(a) : "l"(p));
    return a;
}
__device__ __forceinline__ void cp16(uint32_t dst, const void* src) {
    asm volatile("cp.async.cg.shared.global [%0], [%1], 16;" :: "r"(dst), "l"(src));
}
#define CP_COMMIT() asm volatile("cp.async.commit_group;" ::: "memory")
#define CP_WAIT2()  asm volatile("cp.async.wait_group 2;" ::: "memory")
#define CP_WAIT0()  asm volatile("cp.async.wait_group 0;" ::: "memory")

#define LDSM4(r0, r1, r2, r3, addr) \
    asm volatile("ldmatrix.sync.aligned.m8n8.x4.shared.b16 {%0,%1,%2,%3}, [%4];" \
        : "=r"(r0), "=r"(r1), "=r"(r2), "=r"(r3) : "r"(addr))

#define LDSM4T(r0, r1, r2, r3, addr) \
    asm volatile("ldmatrix.sync.aligned.m8n8.x4.trans.shared.b16 {%0,%1,%2,%3}, [%4];" \
        : "=r"(r0), "=r"(r1), "=r"(r2), "=r"(r3) : "r"(addr))

#define MMA_F32(c, a, b0, b1) \
    asm volatile("mma.sync.aligned.m16n8k16.row.col.f32.f16.f16.f32 " \
        "{%0,%1,%2,%3}, {%4,%5,%6,%7}, {%8,%9}, {%0,%1,%2,%3};" \
        : "+f"((c)[0]), "+f"((c)[1]), "+f"((c)[2]), "+f"((c)[3]) \
        : "r"((a)[0]), "r"((a)[1]), "r"((a)[2]), "r"((a)[3]), "r"(b0), "r"(b1))

__device__ __forceinline__ uint32_t packh2(float x, float y) {
    __half2 h = __floats2half2_rn(x, y);
    return *reinterpret_cast<uint32_t*>(&h);
}
// single-MUFU exp2 (inputs <= 0 here; approx err ~2^-22)
__device__ __forceinline__ float ex2f(float x) {
    float r;
    asm("ex2.approx.f32 %0, %1;" : "=f"(r) : "f"(x));
    return r;
}

// ---------------------------------------------------------------------------
// Convert fp32 -> fp16 (vectorized, grid-stride)
// ---------------------------------------------------------------------------
__global__ void fconv_kernel(const float4* __restrict__ in,
                             uint32_t* __restrict__ out, int n4)
{
    for (int i = blockIdx.x * blockDim.x + threadIdx.x; i < n4; i += gridDim.x * blockDim.x) {
        float4 v = in[i];
        out[i * 2 + 0] = packh2(v.x, v.y);
        out[i * 2 + 1] = packh2(v.z, v.w);
    }
}

// ---------------------------------------------------------------------------
// Transpose + convert all 4 weights in one launch: grid (32,32,4).
// ---------------------------------------------------------------------------
__global__ void wconv_kernel(const float* __restrict__ W0, const float* __restrict__ W1,
                             const float* __restrict__ W2, const float* __restrict__ W3)
{
    __shared__ float t[32][33];
    const float* W = blockIdx.z == 0 ? W0 : blockIdx.z == 1 ? W1 : blockIdx.z == 2 ? W2 : W3;
    __half* T = g_w + (size_t)blockIdx.z * D_MODEL * D_MODEL;
    int bx = blockIdx.x * 32, by = blockIdx.y * 32;
    int x = threadIdx.x, y = threadIdx.y;
    #pragma unroll
    for (int d = 0; d < 32; d += 8)
        t[y + d][x] = W[(size_t)(by + y + d) * D_MODEL + bx + x];
    __syncthreads();
    #pragma unroll
    for (int d = 0; d < 32; d += 8)
        T[(size_t)(bx + y + d) * D_MODEL + by + x] = __float2half_rn(t[x][y + d]);
}

// ---------------------------------------------------------------------------
// fp16 GEMM: out_plane = A @ Bplane^T + bias_plane.  CTA 128x256, BK=32,
// 6-stage cp.async pipeline, 2 k-chunks per __syncthreads (16 barriers).
// 8 warps, warp tile 64x64.  plane = blockIdx.x>>2 selects bias/output.
// smem: 6 stages x 30720 B = 184320 B (1 CTA/SM).
// ---------------------------------------------------------------------------
#define A_PLANE   10240
#define STAGE_B   30720
#define N_STAGES  6
#define GEMM_SMEM (N_STAGES * STAGE_B)
#define KCHUNKS   32

template<bool F32OUT>
__global__ __launch_bounds__(256)
void gemm_f16(const __half* __restrict__ A, const __half* __restrict__ B,
              const float* __restrict__ b0, const float* __restrict__ b1,
              const float* __restrict__ b2,
              float* __restrict__ C,
              __half* __restrict__ o0, __half* __restrict__ o1,
              __half* __restrict__ o2)
{
    extern __shared__ char smem_raw[];
    const uint32_t sbase = smem_u32(smem_raw);

    const int tid    = threadIdx.x;
    const int wid    = tid >> 5;
    const int lane   = tid & 31;
    const int warp_m = (wid >> 2) * 64;
    const int warp_n = (wid & 3) * 64;
    const size_t m0  = (size_t)blockIdx.y * 128;
    const size_t n0  = (size_t)blockIdx.x * 256;     // row in (possibly multi-plane) B
    const int plane  = blockIdx.x >> 2;
    const int col0   = (blockIdx.x & 3) * 256;       // column within output plane

    const float* bias = plane == 0 ? b0 : plane == 1 ? b1 : b2;
    __half* Ch        = plane == 0 ? o0 : plane == 1 ? o1 : o2;

    const char* sA = (const char*)(A + m0 * D_MODEL);
    const char* sB = (const char*)(B + n0 * D_MODEL);

    auto fill = [&](int stage, int kc) {
        const uint32_t st = sbase + stage * STAGE_B;
        const size_t ko = (size_t)kc * 64;
        #pragma unroll
        for (int i = 0; i < 2; i++) {
            int c = tid + i * 256, row = c >> 2, col = c & 3;
            cp16(st + row * 80 + col * 16, sA + (size_t)row * 2048 + ko + col * 16);
        }
        #pragma unroll
        for (int i = 0; i < 4; i++) {
            int c = tid + i * 256, row = c >> 2, col = c & 3;
            cp16(st + A_PLANE + row * 80 + col * 16, sB + (size_t)row * 2048 + ko + col * 16);
        }
        CP_COMMIT();
    };

    float acc[4][8][4];
    #pragma unroll
    for (int i = 0; i < 4; i++)
        #pragma unroll
        for (int j = 0; j < 8; j++)
            #pragma unroll
            for (int q = 0; q < 4; q++) acc[i][j][q] = 0.f;

    // prologue: chunks 0..3 into stages 0..3 (4 groups)
    fill(0, 0); fill(1, 1); fill(2, 2); fill(3, 3);

    const int lr = lane & 7, g = lane >> 3;
    const uint32_t a_loff = (uint32_t)((lr + (g & 1) * 8) * 80 + (g >> 1) * 16);
    const uint32_t b_loff = (uint32_t)((lr + (g >> 1) * 8) * 80 + (g & 1) * 16);

    auto compute = [&](int chunk) {
        const uint32_t st = sbase + (chunk % N_STAGES) * STAGE_B;
        const uint32_t aP = st +           warp_m * 80 + a_loff;
        const uint32_t bP = st + A_PLANE + warp_n * 80 + b_loff;
        #pragma unroll
        for (int ks = 0; ks < 2; ks++) {
            const uint32_t ko = ks * 32;
            uint32_t a_r[4][4], b_r[16];
            #pragma unroll
            for (int mt = 0; mt < 4; mt++)
                LDSM4(a_r[mt][0], a_r[mt][1], a_r[mt][2], a_r[mt][3],
                      aP + mt * (16 * 80) + ko);
            #pragma unroll
            for (int p = 0; p < 4; p++)
                LDSM4(b_r[p*4+0], b_r[p*4+1], b_r[p*4+2], b_r[p*4+3],
                      bP + p * (16 * 80) + ko);
            #pragma unroll
            for (int mt = 0; mt < 4; mt++)
                #pragma unroll
                for (int nt = 0; nt < 8; nt++)
                    MMA_F32(acc[mt][nt], a_r[mt], b_r[nt*2], b_r[nt*2+1]);
        }
    };

    #pragma unroll 1
    for (int it = 0; it < KCHUNKS / 2; it++) {
        CP_WAIT2();              // chunks <= 2it+1 resident
        __syncthreads();         // everyone done with stages being overwritten below
        int c0 = 2 * it + 4, c1 = 2 * it + 5;
        if (c0 < KCHUNKS) fill(c0 % N_STAGES, c0); else CP_COMMIT();
        if (c1 < KCHUNKS) fill(c1 % N_STAGES, c1); else CP_COMMIT();
        compute(2 * it);
        compute(2 * it + 1);
    }

    #pragma unroll
    for (int mt = 0; mt < 4; mt++) {
        #pragma unroll
        for (int nt = 0; nt < 8; nt++) {
            int row0 = (int)m0 + warp_m + mt * 16 + (lane >> 2);
            int colg = col0 + warp_n + nt * 8 + (lane & 3) * 2;
            float2 bv = *reinterpret_cast<const float2*>(bias + colg);
            float o00 = acc[mt][nt][0] + bv.x, o01 = acc[mt][nt][1] + bv.y;
            float o10 = acc[mt][nt][2] + bv.x, o11 = acc[mt][nt][3] + bv.y;
            size_t off0 = (size_t)row0 * D_MODEL + colg;
            size_t off1 = off0 + 8 * D_MODEL;
            if constexpr (F32OUT) {
                float2 a{o00, o01}, b{o10, o11};
                *reinterpret_cast<float2*>(C + off0) = a;
                *reinterpret_cast<float2*>(C + off1) = b;
            } else {
                *reinterpret_cast<uint32_t*>(Ch + off0) = packh2(o00, o01);
                *reinterpret_cast<uint32_t*>(Ch + off1) = packh2(o10, o11);
            }
        }
    }
}

// ---------------------------------------------------------------------------
// Tensor-core patch attention (fp16, fragment softmax, MUFU ex2, trans-LDSM V).
// grid = (NUM_HEADS, NBLK), 256 threads (8 warps; warp w owns rows 16w..16w+15).
// smem: Q,K,V each [128][72] fp16 (144B stride) = 55296 B.
// ---------------------------------------------------------------------------
#define QK_STRIDE_B 144          // 72 fp16
#define OFF_Q 0
#define OFF_K 18432
#define OFF_V 36864
#define ATTN_SMEM 55296

__global__ __launch_bounds__(256, 2)
void attn_mma_kernel()
{
    extern __shared__ char smc[];
    const uint32_t sb = smem_u32(smc);

    const int h   = blockIdx.x;
    const int pb  = blockIdx.y;
    const int tid = threadIdx.x;
    const int wid = tid >> 5;
    const int lane = tid & 31;
    const size_t base = (size_t)pb * 128 * D_MODEL + (size_t)h * D_HEAD;

    // stage Q, K, V via cp.async (rows of 64 fp16 = 128 B = 8 x 16B, 144B stride)
    {
        const char* gq = (const char*)(g_Q + base);
        const char* gk = (const char*)(g_K + base);
        const char* gv = (const char*)(g_V + base);
        #pragma unroll
        for (int i = 0; i < 4; i++) {
            int idx = tid + i * 256;
            int row = idx >> 3, ch = idx & 7;
            uint32_t so = row * QK_STRIDE_B + ch * 16;
            size_t  go = (size_t)row * 2048 + ch * 16;
            cp16(sb + OFF_Q + so, gq + go);
            cp16(sb + OFF_K + so, gk + go);
            cp16(sb + OFF_V + so, gv + go);
        }
        CP_COMMIT();
    }
    CP_WAIT0();
    __syncthreads();

    const int lr = lane & 7, g = lane >> 3;
    const uint32_t a_off = (uint32_t)((lr + (g & 1) * 8) * QK_STRIDE_B + (g >> 1) * 16);
    const uint32_t b_off = (uint32_t)((lr + (g >> 1) * 8) * QK_STRIDE_B + (g & 1) * 16);
    const uint32_t v_off = (uint32_t)((lane & 15) * QK_STRIDE_B + (lane >> 4) * 16);

    // ---- S = Q K^T ----
    float cf[16][4];
    #pragma unroll
    for (int i = 0; i < 16; i++)
        #pragma unroll
        for (int q = 0; q < 4; q++) cf[i][q] = 0.f;

    const uint32_t q0 = sb + OFF_Q + wid * (16 * QK_STRIDE_B) + a_off;

    #pragma unroll
    for (int ks = 0; ks < 4; ks++) {
        const uint32_t ko = ks * 32;
        uint32_t aq[4];
        LDSM4(aq[0], aq[1], aq[2], aq[3], q0 + ko);
        #pragma unroll
        for (int p = 0; p < 8; p++) {
            uint32_t kh[4];
            LDSM4(kh[0], kh[1], kh[2], kh[3], sb + OFF_K + p * (16 * QK_STRIDE_B) + b_off + ko);
            MMA_F32(cf[2*p],   aq, kh[0], kh[1]);
            MMA_F32(cf[2*p+1], aq, kh[2], kh[3]);
        }
    }

    // ---- fragment softmax (MUFU exp2) ----
    float mx0 = -CUDART_INF_F, mx1 = -CUDART_INF_F;
    #pragma unroll
    for (int nt = 0; nt < 16; nt++) {
        mx0 = fmaxf(mx0, fmaxf(cf[nt][0], cf[nt][1]));
        mx1 = fmaxf(mx1, fmaxf(cf[nt][2], cf[nt][3]));
    }
    mx0 = fmaxf(mx0, __shfl_xor_sync(0xffffffffu, mx0, 1));
    mx0 = fmaxf(mx0, __shfl_xor_sync(0xffffffffu, mx0, 2));
    mx1 = fmaxf(mx1, __shfl_xor_sync(0xffffffffu, mx1, 1));
    mx1 = fmaxf(mx1, __shfl_xor_sync(0xffffffffu, mx1, 2));

    const float CS = 0.125f * 1.4426950408889634f;   // log2(e)/sqrt(64)
    float l0 = 0.f, l1 = 0.f;
    #pragma unroll
    for (int nt = 0; nt < 16; nt++) {
        float p0 = ex2f((cf[nt][0] - mx0) * CS);
        float p1 = ex2f((cf[nt][1] - mx0) * CS);
        float p2 = ex2f((cf[nt][2] - mx1) * CS);
        float p3 = ex2f((cf[nt][3] - mx1) * CS);
        cf[nt][0] = p0; cf[nt][1] = p1; cf[nt][2] = p2; cf[nt][3] = p3;
        l0 += p0 + p1; l1 += p2 + p3;
    }
    l0 += __shfl_xor_sync(0xffffffffu, l0, 1);
    l0 += __shfl_xor_sync(0xffffffffu, l0, 2);
    l1 += __shfl_xor_sync(0xffffffffu, l1, 1);
    l1 += __shfl_xor_sync(0xffffffffu, l1, 2);
    const float inv0 = 1.f / l0, inv1 = 1.f / l1;

    // ---- O = P V (B-frags via ldmatrix.trans from row-major V) ----
    float of[8][4];
    #pragma unroll
    for (int i = 0; i < 8; i++)
        #pragma unroll
        for (int q = 0; q < 4; q++) of[i][q] = 0.f;

    #pragma unroll
    for (int kt = 0; kt < 8; kt++) {
        uint32_t ah[4];
        ah[0] = packh2(cf[2*kt][0],   cf[2*kt][1]);
        ah[1] = packh2(cf[2*kt][2],   cf[2*kt][3]);
        ah[2] = packh2(cf[2*kt+1][0], cf[2*kt+1][1]);
        ah[3] = packh2(cf[2*kt+1][2], cf[2*kt+1][3]);
        const uint32_t vrow = sb + OFF_V + kt * (16 * QK_STRIDE_B) + v_off;
        #pragma unroll
        for (int np = 0; np < 4; np++) {
            uint32_t vh[4];
            LDSM4T(vh[0], vh[1], vh[2], vh[3], vrow + np * 32);
            MMA_F32(of[2*np],   ah, vh[0], vh[1]);
            MMA_F32(of[2*np+1], ah, vh[2], vh[3]);
        }
    }

    // ---- write A = softmax(S)V as fp16 ----
    const int row  = pb * 128 + wid * 16 + (lane >> 2);
    const int colb = h * 64 + (lane & 3) * 2;
    #pragma unroll
    for (int nt = 0; nt < 8; nt++) {
        size_t off0 = (size_t)row * D_MODEL + colb + nt * 8;
        size_t off1 = off0 + 8 * D_MODEL;
        *reinterpret_cast<uint32_t*>(g_A + off0) = packh2(of[nt][0] * inv0, of[nt][1] * inv0);
        *reinterpret_cast<uint32_t*>(g_A + off1) = packh2(of[nt][2] * inv1, of[nt][3] * inv1);
    }
}

// ---------------------------------------------------------------------------
extern "C" void kernel_launch(void* const* d_in, const int* in_sizes, int n_in,
                              void* d_out, int out_size)
{
    const float* x  = (const float*)d_in[0];
    // d_in[1] = coords (unused by reference)
    const float* Wq = (const float*)d_in[2];
    const float* bq = (const float*)d_in[3];
    const float* Wk = (const float*)d_in[4];
    const float* bk = (const float*)d_in[5];
    const float* Wv = (const float*)d_in[6];
    const float* bv = (const float*)d_in[7];
    const float* Wo = (const float*)d_in[8];
    const float* bo = (const float*)d_in[9];
    float* out = (float*)d_out;

    __half *xh, *Qp, *Kp, *Vp, *Ap, *wp;
    cudaGetSymbolAddress((void**)&xh, g_x);
    cudaGetSymbolAddress((void**)&Qp, g_Q);
    cudaGetSymbolAddress((void**)&Kp, g_K);
    cudaGetSymbolAddress((void**)&Vp, g_V);
    cudaGetSymbolAddress((void**)&Ap, g_A);
    cudaGetSymbolAddress((void**)&wp, g_w);

    cudaFuncSetAttribute(gemm_f16<true>,  cudaFuncAttributeMaxDynamicSharedMemorySize, GEMM_SMEM);
    cudaFuncSetAttribute(gemm_f16<false>, cudaFuncAttributeMaxDynamicSharedMemorySize, GEMM_SMEM);
    cudaFuncSetAttribute(attn_mma_kernel, cudaFuncAttributeMaxDynamicSharedMemorySize, ATTN_SMEM);

    // launch 1: transpose + convert all weights (planes 0-3 of g_w)
    dim3 wgrid(32, 32, 4), wblk(32, 8);
    wconv_kernel<<<wgrid, wblk>>>(Wq, Wk, Wv, Wo);
    // launch 2: convert x -> fp16
    fconv_kernel<<<8192, 256>>>((const float4*)x, (uint32_t*)xh, M_TOTAL * D_MODEL / 4);

    // launch 3: fused Q/K/V projection (planes 0-2 of g_w), fp16 out
    dim3 qkv_grid(12, M_TOTAL / 128);   // 3072 CTAs
    gemm_f16<false><<<qkv_grid, 256, GEMM_SMEM>>>(xh, wp, bq, bk, bv,
                                                  nullptr, Qp, Kp, Vp);

    // launch 4: tensor-core attention (fp16 A)
    dim3 agrid(NUM_HEADS, NBLK);
    attn_mma_kernel<<<agrid, 256, ATTN_SMEM>>>();

    // launch 5: output projection (plane 3 of g_w), fp32 out
    dim3 o_grid(4, M_TOTAL / 128);
    gemm_f16<true><<<o_grid, 256, GEMM_SMEM>>>(Ap, wp + (size_t)3 * D_MODEL * D_MODEL,
                                               bo, bo, bo, out, nullptr, nullptr, nullptr);
}

// round 12
// speedup vs baseline: 7.4084x; 1.0043x over previous
#include <cuda_runtime.h>
#include <cuda_fp16.h>
#include <math_constants.h>
#include <cstdint>

#define D_MODEL   1024
#define NUM_HEADS 16
#define D_HEAD    64
#define PATCH     128
#define BATCH     4
#define SEQ       8192
#define M_TOTAL   (BATCH * SEQ)          // 32768 rows
#define NBLK      (M_TOTAL / PATCH)      // 256 patch blocks

// ---------------------------------------------------------------------------
// Scratch (static device globals — no runtime allocation)
// ---------------------------------------------------------------------------
__device__ __half g_x[(size_t)M_TOTAL * D_MODEL];
__device__ __half g_Q[(size_t)M_TOTAL * D_MODEL];
__device__ __half g_K[(size_t)M_TOTAL * D_MODEL];
__device__ __half g_V[(size_t)M_TOTAL * D_MODEL];
__device__ __half g_A[(size_t)M_TOTAL * D_MODEL];
// transposed weights, 4 planes: 0=Wq^T,1=Wk^T,2=Wv^T,3=Wo^T (row n, col k)
__device__ __half g_w[(size_t)4 * D_MODEL * D_MODEL];

// ---------------------------------------------------------------------------
// PTX helpers (base ISA only)
// ---------------------------------------------------------------------------
__device__ __forceinline__ uint32_t smem_u32(const void* p) {
    uint32_t a;
    asm("{ .reg .u64 t; cvta.to.shared.u64 t, %1; cvt.u32.u64 %0, t; }" : "=r"(a) : "l"(p));
    return a;
}
__device__ __forceinline__ void cp16(uint32_t dst, const void* src) {
    asm volatile("cp.async.cg.shared.global [%0], [%1], 16;" :: "r"(dst), "l"(src));
}
#define CP_COMMIT() asm volatile("cp.async.commit_group;" ::: "memory")
#define CP_WAIT2()  asm volatile("cp.async.wait_group 2;" ::: "memory")
#define CP_WAIT1()  asm volatile("cp.async.wait_group 1;" ::: "memory")
#define CP_WAIT0()  asm volatile("cp.async.wait_group 0;" ::: "memory")

#define LDSM4(r0, r1, r2, r3, addr) \
    asm volatile("ldmatrix.sync.aligned.m8n8.x4.shared.b16 {%0,%1,%2,%3}, [%4];" \
        : "=r"(r0), "=r"(r1), "=r"(r2), "=r"(r3) : "r"(addr))

#define LDSM4T(r0, r1, r2, r3, addr) \
    asm volatile("ldmatrix.sync.aligned.m8n8.x4.trans.shared.b16 {%0,%1,%2,%3}, [%4];" \
        : "=r"(r0), "=r"(r1), "=r"(r2), "=r"(r3) : "r"(addr))

#define MMA_F32(c, a, b0, b1) \
    asm volatile("mma.sync.aligned.m16n8k16.row.col.f32.f16.f16.f32 " \
        "{%0,%1,%2,%3}, {%4,%5,%6,%7}, {%8,%9}, {%0,%1,%2,%3};" \
        : "+f"((c)[0]), "+f"((c)[1]), "+f"((c)[2]), "+f"((c)[3]) \
        : "r"((a)[0]), "r"((a)[1]), "r"((a)[2]), "r"((a)[3]), "r"(b0), "r"(b1))

__device__ __forceinline__ uint32_t packh2(float x, float y) {
    __half2 h = __floats2half2_rn(x, y);
    return *reinterpret_cast<uint32_t*>(&h);
}
// single-MUFU exp2 (inputs <= 0 here; approx err ~2^-22)
__device__ __forceinline__ float ex2f(float x) {
    float r;
    asm("ex2.approx.f32 %0, %1;" : "=f"(r) : "f"(x));
    return r;
}

// ---------------------------------------------------------------------------
// Fused prep: z<4 -> transpose+convert weight plane z; z==4 -> convert x.
// grid (32,32,5), block (32,8).
// ---------------------------------------------------------------------------
__global__ void prep_kernel(const float* __restrict__ W0, const float* __restrict__ W1,
                            const float* __restrict__ W2, const float* __restrict__ W3,
                            const float4* __restrict__ x, uint32_t* __restrict__ xh)
{
    if (blockIdx.z == 4) {
        // x conversion: 1024 CTAs x 256 threads, grid-stride over 8388608 float4
        const int tid = threadIdx.y * 32 + threadIdx.x;
        const int bid = blockIdx.y * 32 + blockIdx.x;
        const int n4 = M_TOTAL * D_MODEL / 4;
        for (int i = bid * 256 + tid; i < n4; i += 1024 * 256) {
            float4 v = x[i];
            xh[i * 2 + 0] = packh2(v.x, v.y);
            xh[i * 2 + 1] = packh2(v.z, v.w);
        }
        return;
    }
    __shared__ float t[32][33];
    const float* W = blockIdx.z == 0 ? W0 : blockIdx.z == 1 ? W1 : blockIdx.z == 2 ? W2 : W3;
    __half* T = g_w + (size_t)blockIdx.z * D_MODEL * D_MODEL;
    int bx = blockIdx.x * 32, by = blockIdx.y * 32;
    int xx = threadIdx.x, yy = threadIdx.y;
    #pragma unroll
    for (int d = 0; d < 32; d += 8)
        t[yy + d][xx] = W[(size_t)(by + yy + d) * D_MODEL + bx + xx];
    __syncthreads();
    #pragma unroll
    for (int d = 0; d < 32; d += 8)
        T[(size_t)(bx + yy + d) * D_MODEL + by + xx] = __float2half_rn(t[xx][yy + d]);
}

// ---------------------------------------------------------------------------
// fp16 GEMM: out_plane = A @ Bplane^T + bias_plane.  CTA 128x256, BK=32,
// 6-stage cp.async pipeline, 2 k-chunks per __syncthreads (16 barriers).
// 8 warps, warp tile 64x64.  plane = blockIdx.x>>2 selects bias/output.
// smem: 6 stages x 30720 B = 184320 B (1 CTA/SM).
// ---------------------------------------------------------------------------
#define A_PLANE   10240
#define STAGE_B   30720
#define N_STAGES  6
#define GEMM_SMEM (N_STAGES * STAGE_B)
#define KCHUNKS   32

template<bool F32OUT>
__global__ __launch_bounds__(256)
void gemm_f16(const __half* __restrict__ A, const __half* __restrict__ B,
              const float* __restrict__ b0, const float* __restrict__ b1,
              const float* __restrict__ b2,
              float* __restrict__ C,
              __half* __restrict__ o0, __half* __restrict__ o1,
              __half* __restrict__ o2)
{
    extern __shared__ char smem_raw[];
    const uint32_t sbase = smem_u32(smem_raw);

    const int tid    = threadIdx.x;
    const int wid    = tid >> 5;
    const int lane   = tid & 31;
    const int warp_m = (wid >> 2) * 64;
    const int warp_n = (wid & 3) * 64;
    const size_t m0  = (size_t)blockIdx.y * 128;
    const size_t n0  = (size_t)blockIdx.x * 256;     // row in (possibly multi-plane) B
    const int plane  = blockIdx.x >> 2;
    const int col0   = (blockIdx.x & 3) * 256;       // column within output plane

    const float* bias = plane == 0 ? b0 : plane == 1 ? b1 : b2;
    __half* Ch        = plane == 0 ? o0 : plane == 1 ? o1 : o2;

    const char* sA = (const char*)(A + m0 * D_MODEL);
    const char* sB = (const char*)(B + n0 * D_MODEL);

    auto fill = [&](int stage, int kc) {
        const uint32_t st = sbase + stage * STAGE_B;
        const size_t ko = (size_t)kc * 64;
        #pragma unroll
        for (int i = 0; i < 2; i++) {
            int c = tid + i * 256, row = c >> 2, col = c & 3;
            cp16(st + row * 80 + col * 16, sA + (size_t)row * 2048 + ko + col * 16);
        }
        #pragma unroll
        for (int i = 0; i < 4; i++) {
            int c = tid + i * 256, row = c >> 2, col = c & 3;
            cp16(st + A_PLANE + row * 80 + col * 16, sB + (size_t)row * 2048 + ko + col * 16);
        }
        CP_COMMIT();
    };

    float acc[4][8][4];
    #pragma unroll
    for (int i = 0; i < 4; i++)
        #pragma unroll
        for (int j = 0; j < 8; j++)
            #pragma unroll
            for (int q = 0; q < 4; q++) acc[i][j][q] = 0.f;

    // prologue: chunks 0..3 into stages 0..3 (4 groups)
    fill(0, 0); fill(1, 1); fill(2, 2); fill(3, 3);

    const int lr = lane & 7, g = lane >> 3;
    const uint32_t a_loff = (uint32_t)((lr + (g & 1) * 8) * 80 + (g >> 1) * 16);
    const uint32_t b_loff = (uint32_t)((lr + (g >> 1) * 8) * 80 + (g & 1) * 16);

    auto compute = [&](int chunk) {
        const uint32_t st = sbase + (chunk % N_STAGES) * STAGE_B;
        const uint32_t aP = st +           warp_m * 80 + a_loff;
        const uint32_t bP = st + A_PLANE + warp_n * 80 + b_loff;
        #pragma unroll
        for (int ks = 0; ks < 2; ks++) {
            const uint32_t ko = ks * 32;
            uint32_t a_r[4][4], b_r[16];
            #pragma unroll
            for (int mt = 0; mt < 4; mt++)
                LDSM4(a_r[mt][0], a_r[mt][1], a_r[mt][2], a_r[mt][3],
                      aP + mt * (16 * 80) + ko);
            #pragma unroll
            for (int p = 0; p < 4; p++)
                LDSM4(b_r[p*4+0], b_r[p*4+1], b_r[p*4+2], b_r[p*4+3],
                      bP + p * (16 * 80) + ko);
            #pragma unroll
            for (int mt = 0; mt < 4; mt++)
                #pragma unroll
                for (int nt = 0; nt < 8; nt++)
                    MMA_F32(acc[mt][nt], a_r[mt], b_r[nt*2], b_r[nt*2+1]);
        }
    };

    #pragma unroll 1
    for (int it = 0; it < KCHUNKS / 2; it++) {
        CP_WAIT2();              // chunks <= 2it+1 resident
        __syncthreads();         // everyone done with stages being overwritten below
        int c0 = 2 * it + 4, c1 = 2 * it + 5;
        if (c0 < KCHUNKS) fill(c0 % N_STAGES, c0); else CP_COMMIT();
        if (c1 < KCHUNKS) fill(c1 % N_STAGES, c1); else CP_COMMIT();
        compute(2 * it);
        compute(2 * it + 1);
    }

    #pragma unroll
    for (int mt = 0; mt < 4; mt++) {
        #pragma unroll
        for (int nt = 0; nt < 8; nt++) {
            int row0 = (int)m0 + warp_m + mt * 16 + (lane >> 2);
            int colg = col0 + warp_n + nt * 8 + (lane & 3) * 2;
            float2 bv = *reinterpret_cast<const float2*>(bias + colg);
            float o00 = acc[mt][nt][0] + bv.x, o01 = acc[mt][nt][1] + bv.y;
            float o10 = acc[mt][nt][2] + bv.x, o11 = acc[mt][nt][3] + bv.y;
            size_t off0 = (size_t)row0 * D_MODEL + colg;
            size_t off1 = off0 + 8 * D_MODEL;
            if constexpr (F32OUT) {
                float2 a{o00, o01}, b{o10, o11};
                *reinterpret_cast<float2*>(C + off0) = a;
                *reinterpret_cast<float2*>(C + off1) = b;
            } else {
                *reinterpret_cast<uint32_t*>(Ch + off0) = packh2(o00, o01);
                *reinterpret_cast<uint32_t*>(Ch + off1) = packh2(o10, o11);
            }
        }
    }
}

// ---------------------------------------------------------------------------
// Tensor-core patch attention (fp16, fragment softmax, MUFU ex2, trans-LDSM V).
// V load in a second cp.async group — its latency hides behind S + softmax.
// grid = (NUM_HEADS, NBLK), 256 threads (8 warps; warp w owns rows 16w..16w+15).
// smem: Q,K,V each [128][72] fp16 (144B stride) = 55296 B.
// ---------------------------------------------------------------------------
#define QK_STRIDE_B 144          // 72 fp16
#define OFF_Q 0
#define OFF_K 18432
#define OFF_V 36864
#define ATTN_SMEM 55296

__global__ __launch_bounds__(256, 2)
void attn_mma_kernel()
{
    extern __shared__ char smc[];
    const uint32_t sb = smem_u32(smc);

    const int h   = blockIdx.x;
    const int pb  = blockIdx.y;
    const int tid = threadIdx.x;
    const int wid = tid >> 5;
    const int lane = tid & 31;
    const size_t base = (size_t)pb * 128 * D_MODEL + (size_t)h * D_HEAD;

    // group 0: Q + K;  group 1: V (latency hidden behind S + softmax)
    {
        const char* gq = (const char*)(g_Q + base);
        const char* gk = (const char*)(g_K + base);
        const char* gv = (const char*)(g_V + base);
        #pragma unroll
        for (int i = 0; i < 4; i++) {
            int idx = tid + i * 256;
            int row = idx >> 3, ch = idx & 7;
            uint32_t so = row * QK_STRIDE_B + ch * 16;
            size_t  go = (size_t)row * 2048 + ch * 16;
            cp16(sb + OFF_Q + so, gq + go);
            cp16(sb + OFF_K + so, gk + go);
        }
        CP_COMMIT();
        #pragma unroll
        for (int i = 0; i < 4; i++) {
            int idx = tid + i * 256;
            int row = idx >> 3, ch = idx & 7;
            cp16(sb + OFF_V + row * QK_STRIDE_B + ch * 16,
                 gv + (size_t)row * 2048 + ch * 16);
        }
        CP_COMMIT();
    }
    CP_WAIT1();          // Q, K resident (V still in flight)
    __syncthreads();

    const int lr = lane & 7, g = lane >> 3;
    const uint32_t a_off = (uint32_t)((lr + (g & 1) * 8) * QK_STRIDE_B + (g >> 1) * 16);
    const uint32_t b_off = (uint32_t)((lr + (g >> 1) * 8) * QK_STRIDE_B + (g & 1) * 16);
    const uint32_t v_off = (uint32_t)((lane & 15) * QK_STRIDE_B + (lane >> 4) * 16);

    // ---- S = Q K^T ----
    float cf[16][4];
    #pragma unroll
    for (int i = 0; i < 16; i++)
        #pragma unroll
        for (int q = 0; q < 4; q++) cf[i][q] = 0.f;

    const uint32_t q0 = sb + OFF_Q + wid * (16 * QK_STRIDE_B) + a_off;

    #pragma unroll
    for (int ks = 0; ks < 4; ks++) {
        const uint32_t ko = ks * 32;
        uint32_t aq[4];
        LDSM4(aq[0], aq[1], aq[2], aq[3], q0 + ko);
        #pragma unroll
        for (int p = 0; p < 8; p++) {
            uint32_t kh[4];
            LDSM4(kh[0], kh[1], kh[2], kh[3], sb + OFF_K + p * (16 * QK_STRIDE_B) + b_off + ko);
            MMA_F32(cf[2*p],   aq, kh[0], kh[1]);
            MMA_F32(cf[2*p+1], aq, kh[2], kh[3]);
        }
    }

    // ---- fragment softmax (MUFU exp2) ----
    float mx0 = -CUDART_INF_F, mx1 = -CUDART_INF_F;
    #pragma unroll
    for (int nt = 0; nt < 16; nt++) {
        mx0 = fmaxf(mx0, fmaxf(cf[nt][0], cf[nt][1]));
        mx1 = fmaxf(mx1, fmaxf(cf[nt][2], cf[nt][3]));
    }
    mx0 = fmaxf(mx0, __shfl_xor_sync(0xffffffffu, mx0, 1));
    mx0 = fmaxf(mx0, __shfl_xor_sync(0xffffffffu, mx0, 2));
    mx1 = fmaxf(mx1, __shfl_xor_sync(0xffffffffu, mx1, 1));
    mx1 = fmaxf(mx1, __shfl_xor_sync(0xffffffffu, mx1, 2));

    const float CS = 0.125f * 1.4426950408889634f;   // log2(e)/sqrt(64)
    float l0 = 0.f, l1 = 0.f;
    #pragma unroll
    for (int nt = 0; nt < 16; nt++) {
        float p0 = ex2f((cf[nt][0] - mx0) * CS);
        float p1 = ex2f((cf[nt][1] - mx0) * CS);
        float p2 = ex2f((cf[nt][2] - mx1) * CS);
        float p3 = ex2f((cf[nt][3] - mx1) * CS);
        cf[nt][0] = p0; cf[nt][1] = p1; cf[nt][2] = p2; cf[nt][3] = p3;
        l0 += p0 + p1; l1 += p2 + p3;
    }
    l0 += __shfl_xor_sync(0xffffffffu, l0, 1);
    l0 += __shfl_xor_sync(0xffffffffu, l0, 2);
    l1 += __shfl_xor_sync(0xffffffffu, l1, 1);
    l1 += __shfl_xor_sync(0xffffffffu, l1, 2);
    const float inv0 = 1.f / l0, inv1 = 1.f / l1;

    // now V must be resident
    CP_WAIT0();
    __syncthreads();

    // ---- O = P V (B-frags via ldmatrix.trans from row-major V) ----
    float of[8][4];
    #pragma unroll
    for (int i = 0; i < 8; i++)
        #pragma unroll
        for (int q = 0; q < 4; q++) of[i][q] = 0.f;

    #pragma unroll
    for (int kt = 0; kt < 8; kt++) {
        uint32_t ah[4];
        ah[0] = packh2(cf[2*kt][0],   cf[2*kt][1]);
        ah[1] = packh2(cf[2*kt][2],   cf[2*kt][3]);
        ah[2] = packh2(cf[2*kt+1][0], cf[2*kt+1][1]);
        ah[3] = packh2(cf[2*kt+1][2], cf[2*kt+1][3]);
        const uint32_t vrow = sb + OFF_V + kt * (16 * QK_STRIDE_B) + v_off;
        #pragma unroll
        for (int np = 0; np < 4; np++) {
            uint32_t vh[4];
            LDSM4T(vh[0], vh[1], vh[2], vh[3], vrow + np * 32);
            MMA_F32(of[2*np],   ah, vh[0], vh[1]);
            MMA_F32(of[2*np+1], ah, vh[2], vh[3]);
        }
    }

    // ---- write A = softmax(S)V as fp16 ----
    const int row  = pb * 128 + wid * 16 + (lane >> 2);
    const int colb = h * 64 + (lane & 3) * 2;
    #pragma unroll
    for (int nt = 0; nt < 8; nt++) {
        size_t off0 = (size_t)row * D_MODEL + colb + nt * 8;
        size_t off1 = off0 + 8 * D_MODEL;
        *reinterpret_cast<uint32_t*>(g_A + off0) = packh2(of[nt][0] * inv0, of[nt][1] * inv0);
        *reinterpret_cast<uint32_t*>(g_A + off1) = packh2(of[nt][2] * inv1, of[nt][3] * inv1);
    }
}

// ---------------------------------------------------------------------------
extern "C" void kernel_launch(void* const* d_in, const int* in_sizes, int n_in,
                              void* d_out, int out_size)
{
    const float* x  = (const float*)d_in[0];
    // d_in[1] = coords (unused by reference)
    const float* Wq = (const float*)d_in[2];
    const float* bq = (const float*)d_in[3];
    const float* Wk = (const float*)d_in[4];
    const float* bk = (const float*)d_in[5];
    const float* Wv = (const float*)d_in[6];
    const float* bv = (const float*)d_in[7];
    const float* Wo = (const float*)d_in[8];
    const float* bo = (const float*)d_in[9];
    float* out = (float*)d_out;

    __half *xh, *Qp, *Kp, *Vp, *Ap, *wp;
    cudaGetSymbolAddress((void**)&xh, g_x);
    cudaGetSymbolAddress((void**)&Qp, g_Q);
    cudaGetSymbolAddress((void**)&Kp, g_K);
    cudaGetSymbolAddress((void**)&Vp, g_V);
    cudaGetSymbolAddress((void**)&Ap, g_A);
    cudaGetSymbolAddress((void**)&wp, g_w);

    cudaFuncSetAttribute(gemm_f16<true>,  cudaFuncAttributeMaxDynamicSharedMemorySize, GEMM_SMEM);
    cudaFuncSetAttribute(gemm_f16<false>, cudaFuncAttributeMaxDynamicSharedMemorySize, GEMM_SMEM);
    cudaFuncSetAttribute(attn_mma_kernel, cudaFuncAttributeMaxDynamicSharedMemorySize, ATTN_SMEM);

    // launch 1: fused prep — transpose/convert weights (z<4) + convert x (z=4)
    dim3 pgrid(32, 32, 5), pblk(32, 8);
    prep_kernel<<<pgrid, pblk>>>(Wq, Wk, Wv, Wo, (const float4*)x, (uint32_t*)xh);

    // launch 2: fused Q/K/V projection (planes 0-2 of g_w), fp16 out
    dim3 qkv_grid(12, M_TOTAL / 128);   // 3072 CTAs
    gemm_f16<false><<<qkv_grid, 256, GEMM_SMEM>>>(xh, wp, bq, bk, bv,
                                                  nullptr, Qp, Kp, Vp);

    // launch 3: tensor-core attention (fp16 A)
    dim3 agrid(NUM_HEADS, NBLK);
    attn_mma_kernel<<<agrid, 256, ATTN_SMEM>>>();

    // launch 4: output projection (plane 3 of g_w), fp32 out
    dim3 o_grid(4, M_TOTAL / 128);
    gemm_f16<true><<<o_grid, 256, GEMM_SMEM>>>(Ap, wp + (size_t)3 * D_MODEL * D_MODEL,
                                               bo, bo, bo, out, nullptr, nullptr, nullptr);
}

// round 14
// speedup vs baseline: 7.5910x; 1.0247x over previous
#include <cuda_runtime.h>
#include <cuda_fp16.h>
#include <math_constants.h>
#include <cstdint>

#define D_MODEL   1024
#define NUM_HEADS 16
#define D_HEAD    64
#define PATCH     128
#define BATCH     4
#define SEQ       8192
#define M_TOTAL   (BATCH * SEQ)          // 32768 rows
#define NBLK      (M_TOTAL / PATCH)      // 256 patch blocks

// ---------------------------------------------------------------------------
// Scratch (static device globals — no runtime allocation)
// ---------------------------------------------------------------------------
__device__ __half g_x[(size_t)M_TOTAL * D_MODEL];
__device__ __half g_Q[(size_t)M_TOTAL * D_MODEL];
__device__ __half g_K[(size_t)M_TOTAL * D_MODEL];
__device__ __half g_V[(size_t)M_TOTAL * D_MODEL];
__device__ __half g_A[(size_t)M_TOTAL * D_MODEL];
// transposed weights, 4 planes: 0=Wq^T,1=Wk^T,2=Wv^T,3=Wo^T (row n, col k)
__device__ __half g_w[(size_t)4 * D_MODEL * D_MODEL];

// ---------------------------------------------------------------------------
// PTX helpers (base ISA only)
// ---------------------------------------------------------------------------
__device__ __forceinline__ uint32_t smem_u32(const void* p) {
    uint32_t a;
    asm("{ .reg .u64 t; cvta.to.shared.u64 t, %1; cvt.u32.u64 %0, t; }" : "=r"(a) : "l"(p));
    return a;
}
__device__ __forceinline__ void cp16(uint32_t dst, const void* src) {
    asm volatile("cp.async.cg.shared.global [%0], [%1], 16;" :: "r"(dst), "l"(src));
}
#define CP_COMMIT() asm volatile("cp.async.commit_group;" ::: "memory")
#define CP_WAIT2()  asm volatile("cp.async.wait_group 2;" ::: "memory")
#define CP_WAIT1()  asm volatile("cp.async.wait_group 1;" ::: "memory")
#define CP_WAIT0()  asm volatile("cp.async.wait_group 0;" ::: "memory")

#define LDSM4(r0, r1, r2, r3, addr) \
    asm volatile("ldmatrix.sync.aligned.m8n8.x4.shared.b16 {%0,%1,%2,%3}, [%4];" \
        : "=r"(r0), "=r"(r1), "=r"(r2), "=r"(r3) : "r"(addr))

#define LDSM4T(r0, r1, r2, r3, addr) \
    asm volatile("ldmatrix.sync.aligned.m8n8.x4.trans.shared.b16 {%0,%1,%2,%3}, [%4];" \
        : "=r"(r0), "=r"(r1), "=r"(r2), "=r"(r3) : "r"(addr))

#define MMA_F32(c, a, b0, b1) \
    asm volatile("mma.sync.aligned.m16n8k16.row.col.f32.f16.f16.f32 " \
        "{%0,%1,%2,%3}, {%4,%5,%6,%7}, {%8,%9}, {%0,%1,%2,%3};" \
        : "+f"((c)[0]), "+f"((c)[1]), "+f"((c)[2]), "+f"((c)[3]) \
        : "r"((a)[0]), "r"((a)[1]), "r"((a)[2]), "r"((a)[3]), "r"(b0), "r"(b1))

__device__ __forceinline__ uint32_t packh2(float x, float y) {
    __half2 h = __floats2half2_rn(x, y);
    return *reinterpret_cast<uint32_t*>(&h);
}
// single-MUFU exp2 (inputs <= 0 here; approx err ~2^-22)
__device__ __forceinline__ float ex2f(float x) {
    float r;
    asm("ex2.approx.f32 %0, %1;" : "=f"(r) : "f"(x));
    return r;
}

// ---------------------------------------------------------------------------
// Fused prep: z<4 -> transpose+convert weight plane z; z==4 -> convert x.
// grid (32,32,5), block (32,8).
// ---------------------------------------------------------------------------
__global__ void prep_kernel(const float* __restrict__ W0, const float* __restrict__ W1,
                            const float* __restrict__ W2, const float* __restrict__ W3,
                            const float4* __restrict__ x, uint32_t* __restrict__ xh)
{
    if (blockIdx.z == 4) {
        const int tid = threadIdx.y * 32 + threadIdx.x;
        const int bid = blockIdx.y * 32 + blockIdx.x;
        const int n4 = M_TOTAL * D_MODEL / 4;
        for (int i = bid * 256 + tid; i < n4; i += 1024 * 256) {
            float4 v = x[i];
            xh[i * 2 + 0] = packh2(v.x, v.y);
            xh[i * 2 + 1] = packh2(v.z, v.w);
        }
        return;
    }
    __shared__ float t[32][33];
    const float* W = blockIdx.z == 0 ? W0 : blockIdx.z == 1 ? W1 : blockIdx.z == 2 ? W2 : W3;
    __half* T = g_w + (size_t)blockIdx.z * D_MODEL * D_MODEL;
    int bx = blockIdx.x * 32, by = blockIdx.y * 32;
    int xx = threadIdx.x, yy = threadIdx.y;
    #pragma unroll
    for (int d = 0; d < 32; d += 8)
        t[yy + d][xx] = W[(size_t)(by + yy + d) * D_MODEL + bx + xx];
    __syncthreads();
    #pragma unroll
    for (int d = 0; d < 32; d += 8)
        T[(size_t)(bx + yy + d) * D_MODEL + by + xx] = __float2half_rn(t[xx][yy + d]);
}

// ---------------------------------------------------------------------------
// fp16 GEMM: out_plane = A @ Bplane^T + bias_plane.
// CTA 128x128, BK=32, 4-stage cp.async pipeline, 1 chunk per sync.
// Live set = 4 chunks (1 compute + 2 in-flight + 1 filling) = stage count.
// 8 warps, warp tile 64x32 (acc 64 regs) -> <=128 regs -> 2 CTAs/SM (16 warps).
// smem: 4 stages x 20480 B = 81920 B per CTA.
// plane = blockIdx.x>>3 selects bias/output; col0 = (blockIdx.x&7)*128.
// ---------------------------------------------------------------------------
#define A_PLANE   10240
#define STAGE_B   20480
#define N_STAGES  4
#define GEMM_SMEM (N_STAGES * STAGE_B)
#define KCHUNKS   32

template<bool F32OUT>
__global__ __launch_bounds__(256, 2)
void gemm_f16(const __half* __restrict__ A, const __half* __restrict__ B,
              const float* __restrict__ b0, const float* __restrict__ b1,
              const float* __restrict__ b2,
              float* __restrict__ C,
              __half* __restrict__ o0, __half* __restrict__ o1,
              __half* __restrict__ o2)
{
    extern __shared__ char smem_raw[];
    const uint32_t sbase = smem_u32(smem_raw);

    const int tid    = threadIdx.x;
    const int wid    = tid >> 5;
    const int lane   = tid & 31;
    const int warp_m = (wid >> 2) * 64;    // 0 or 64
    const int warp_n = (wid & 3) * 32;     // 0,32,64,96
    const size_t m0  = (size_t)blockIdx.y * 128;
    const size_t n0  = (size_t)blockIdx.x * 128;     // row in (possibly multi-plane) B
    const int plane  = blockIdx.x >> 3;
    const int col0   = (blockIdx.x & 7) * 128;       // column within output plane

    const float* bias = plane == 0 ? b0 : plane == 1 ? b1 : b2;
    __half* Ch        = plane == 0 ? o0 : plane == 1 ? o1 : o2;

    const char* sA = (const char*)(A + m0 * D_MODEL);
    const char* sB = (const char*)(B + n0 * D_MODEL);

    auto fill = [&](int stage, int kc) {
        const uint32_t st = sbase + stage * STAGE_B;
        const size_t ko = (size_t)kc * 64;
        #pragma unroll
        for (int i = 0; i < 2; i++) {
            int c = tid + i * 256, row = c >> 2, col = c & 3;
            cp16(st + row * 80 + col * 16, sA + (size_t)row * 2048 + ko + col * 16);
        }
        #pragma unroll
        for (int i = 0; i < 2; i++) {
            int c = tid + i * 256, row = c >> 2, col = c & 3;
            cp16(st + A_PLANE + row * 80 + col * 16, sB + (size_t)row * 2048 + ko + col * 16);
        }
        CP_COMMIT();
    };

    float acc[4][4][4];
    #pragma unroll
    for (int i = 0; i < 4; i++)
        #pragma unroll
        for (int j = 0; j < 4; j++)
            #pragma unroll
            for (int q = 0; q < 4; q++) acc[i][j][q] = 0.f;

    // prologue: chunks 0..2 into stages 0..2 (3 groups)
    fill(0, 0); fill(1, 1); fill(2, 2);

    const int lr = lane & 7, g = lane >> 3;
    const uint32_t a_loff = (uint32_t)((lr + (g & 1) * 8) * 80 + (g >> 1) * 16);
    const uint32_t b_loff = (uint32_t)((lr + (g >> 1) * 8) * 80 + (g & 1) * 16);

    #pragma unroll 1
    for (int j = 0; j < KCHUNKS; j++) {
        CP_WAIT2();              // chunks <= j resident (j+1, j+2 in flight)
        __syncthreads();         // all warps done reading stage (j-1)%4 (refilled below)
        if (j + 3 < KCHUNKS) fill((j + 3) % N_STAGES, j + 3);
        else CP_COMMIT();        // keep group counting uniform

        const uint32_t st = sbase + (j % N_STAGES) * STAGE_B;
        const uint32_t aP = st +           warp_m * 80 + a_loff;
        const uint32_t bP = st + A_PLANE + warp_n * 80 + b_loff;
        #pragma unroll
        for (int ks = 0; ks < 2; ks++) {
            const uint32_t ko = ks * 32;
            uint32_t a_r[4][4], b_r[8];
            #pragma unroll
            for (int mt = 0; mt < 4; mt++)
                LDSM4(a_r[mt][0], a_r[mt][1], a_r[mt][2], a_r[mt][3],
                      aP + mt * (16 * 80) + ko);
            #pragma unroll
            for (int p = 0; p < 2; p++)
                LDSM4(b_r[p*4+0], b_r[p*4+1], b_r[p*4+2], b_r[p*4+3],
                      bP + p * (16 * 80) + ko);
            #pragma unroll
            for (int mt = 0; mt < 4; mt++)
                #pragma unroll
                for (int nt = 0; nt < 4; nt++)
                    MMA_F32(acc[mt][nt], a_r[mt], b_r[nt*2], b_r[nt*2+1]);
        }
    }

    #pragma unroll
    for (int mt = 0; mt < 4; mt++) {
        #pragma unroll
        for (int nt = 0; nt < 4; nt++) {
            int row0 = (int)m0 + warp_m + mt * 16 + (lane >> 2);
            int colg = col0 + warp_n + nt * 8 + (lane & 3) * 2;
            float2 bv = *reinterpret_cast<const float2*>(bias + colg);
            float o00 = acc[mt][nt][0] + bv.x, o01 = acc[mt][nt][1] + bv.y;
            float o10 = acc[mt][nt][2] + bv.x, o11 = acc[mt][nt][3] + bv.y;
            size_t off0 = (size_t)row0 * D_MODEL + colg;
            size_t off1 = off0 + 8 * D_MODEL;
            if constexpr (F32OUT) {
                float2 a{o00, o01}, b{o10, o11};
                *reinterpret_cast<float2*>(C + off0) = a;
                *reinterpret_cast<float2*>(C + off1) = b;
            } else {
                *reinterpret_cast<uint32_t*>(Ch + off0) = packh2(o00, o01);
                *reinterpret_cast<uint32_t*>(Ch + off1) = packh2(o10, o11);
            }
        }
    }
}

// ---------------------------------------------------------------------------
// Tensor-core patch attention (fp16, fragment softmax, MUFU ex2, trans-LDSM V).
// V load in a second cp.async group — its latency hides behind S + softmax.
// grid = (NUM_HEADS, NBLK), 256 threads (8 warps; warp w owns rows 16w..16w+15).
// smem: Q,K,V each [128][72] fp16 (144B stride) = 55296 B.
// ---------------------------------------------------------------------------
#define QK_STRIDE_B 144          // 72 fp16
#define OFF_Q 0
#define OFF_K 18432
#define OFF_V 36864
#define ATTN_SMEM 55296

__global__ __launch_bounds__(256, 2)
void attn_mma_kernel()
{
    extern __shared__ char smc[];
    const uint32_t sb = smem_u32(smc);

    const int h   = blockIdx.x;
    const int pb  = blockIdx.y;
    const int tid = threadIdx.x;
    const int wid = tid >> 5;
    const int lane = tid & 31;
    const size_t base = (size_t)pb * 128 * D_MODEL + (size_t)h * D_HEAD;

    // group 0: Q + K;  group 1: V (latency hidden behind S + softmax)
    {
        const char* gq = (const char*)(g_Q + base);
        const char* gk = (const char*)(g_K + base);
        const char* gv = (const char*)(g_V + base);
        #pragma unroll
        for (int i = 0; i < 4; i++) {
            int idx = tid + i * 256;
            int row = idx >> 3, ch = idx & 7;
            uint32_t so = row * QK_STRIDE_B + ch * 16;
            size_t  go = (size_t)row * 2048 + ch * 16;
            cp16(sb + OFF_Q + so, gq + go);
            cp16(sb + OFF_K + so, gk + go);
        }
        CP_COMMIT();
        #pragma unroll
        for (int i = 0; i < 4; i++) {
            int idx = tid + i * 256;
            int row = idx >> 3, ch = idx & 7;
            cp16(sb + OFF_V + row * QK_STRIDE_B + ch * 16,
                 gv + (size_t)row * 2048 + ch * 16);
        }
        CP_COMMIT();
    }
    CP_WAIT1();          // Q, K resident (V still in flight)
    __syncthreads();

    const int lr = lane & 7, g = lane >> 3;
    const uint32_t a_off = (uint32_t)((lr + (g & 1) * 8) * QK_STRIDE_B + (g >> 1) * 16);
    const uint32_t b_off = (uint32_t)((lr + (g >> 1) * 8) * QK_STRIDE_B + (g & 1) * 16);
    const uint32_t v_off = (uint32_t)((lane & 15) * QK_STRIDE_B + (lane >> 4) * 16);

    // ---- S = Q K^T ----
    float cf[16][4];
    #pragma unroll
    for (int i = 0; i < 16; i++)
        #pragma unroll
        for (int q = 0; q < 4; q++) cf[i][q] = 0.f;

    const uint32_t q0 = sb + OFF_Q + wid * (16 * QK_STRIDE_B) + a_off;

    #pragma unroll
    for (int ks = 0; ks < 4; ks++) {
        const uint32_t ko = ks * 32;
        uint32_t aq[4];
        LDSM4(aq[0], aq[1], aq[2], aq[3], q0 + ko);
        #pragma unroll
        for (int p = 0; p < 8; p++) {
            uint32_t kh[4];
            LDSM4(kh[0], kh[1], kh[2], kh[3], sb + OFF_K + p * (16 * QK_STRIDE_B) + b_off + ko);
            MMA_F32(cf[2*p],   aq, kh[0], kh[1]);
            MMA_F32(cf[2*p+1], aq, kh[2], kh[3]);
        }
    }

    // ---- fragment softmax (MUFU exp2) ----
    float mx0 = -CUDART_INF_F, mx1 = -CUDART_INF_F;
    #pragma unroll
    for (int nt = 0; nt < 16; nt++) {
        mx0 = fmaxf(mx0, fmaxf(cf[nt][0], cf[nt][1]));
        mx1 = fmaxf(mx1, fmaxf(cf[nt][2], cf[nt][3]));
    }
    mx0 = fmaxf(mx0, __shfl_xor_sync(0xffffffffu, mx0, 1));
    mx0 = fmaxf(mx0, __shfl_xor_sync(0xffffffffu, mx0, 2));
    mx1 = fmaxf(mx1, __shfl_xor_sync(0xffffffffu, mx1, 1));
    mx1 = fmaxf(mx1, __shfl_xor_sync(0xffffffffu, mx1, 2));

    const float CS = 0.125f * 1.4426950408889634f;   // log2(e)/sqrt(64)
    float l0 = 0.f, l1 = 0.f;
    #pragma unroll
    for (int nt = 0; nt < 16; nt++) {
        float p0 = ex2f((cf[nt][0] - mx0) * CS);
        float p1 = ex2f((cf[nt][1] - mx0) * CS);
        float p2 = ex2f((cf[nt][2] - mx1) * CS);
        float p3 = ex2f((cf[nt][3] - mx1) * CS);
        cf[nt][0] = p0; cf[nt][1] = p1; cf[nt][2] = p2; cf[nt][3] = p3;
        l0 += p0 + p1; l1 += p2 + p3;
    }
    l0 += __shfl_xor_sync(0xffffffffu, l0, 1);
    l0 += __shfl_xor_sync(0xffffffffu, l0, 2);
    l1 += __shfl_xor_sync(0xffffffffu, l1, 1);
    l1 += __shfl_xor_sync(0xffffffffu, l1, 2);
    const float inv0 = 1.f / l0, inv1 = 1.f / l1;

    // now V must be resident
    CP_WAIT0();
    __syncthreads();

    // ---- O = P V (B-frags via ldmatrix.trans from row-major V) ----
    float of[8][4];
    #pragma unroll
    for (int i = 0; i < 8; i++)
        #pragma unroll
        for (int q = 0; q < 4; q++) of[i][q] = 0.f;

    #pragma unroll
    for (int kt = 0; kt < 8; kt++) {
        uint32_t ah[4];
        ah[0] = packh2(cf[2*kt][0],   cf[2*kt][1]);
        ah[1] = packh2(cf[2*kt][2],   cf[2*kt][3]);
        ah[2] = packh2(cf[2*kt+1][0], cf[2*kt+1][1]);
        ah[3] = packh2(cf[2*kt+1][2], cf[2*kt+1][3]);
        const uint32_t vrow = sb + OFF_V + kt * (16 * QK_STRIDE_B) + v_off;
        #pragma unroll
        for (int np = 0; np < 4; np++) {
            uint32_t vh[4];
            LDSM4T(vh[0], vh[1], vh[2], vh[3], vrow + np * 32);
            MMA_F32(of[2*np],   ah, vh[0], vh[1]);
            MMA_F32(of[2*np+1], ah, vh[2], vh[3]);
        }
    }

    // ---- write A = softmax(S)V as fp16 ----
    const int row  = pb * 128 + wid * 16 + (lane >> 2);
    const int colb = h * 64 + (lane & 3) * 2;
    #pragma unroll
    for (int nt = 0; nt < 8; nt++) {
        size_t off0 = (size_t)row * D_MODEL + colb + nt * 8;
        size_t off1 = off0 + 8 * D_MODEL;
        *reinterpret_cast<uint32_t*>(g_A + off0) = packh2(of[nt][0] * inv0, of[nt][1] * inv0);
        *reinterpret_cast<uint32_t*>(g_A + off1) = packh2(of[nt][2] * inv1, of[nt][3] * inv1);
    }
}

// ---------------------------------------------------------------------------
extern "C" void kernel_launch(void* const* d_in, const int* in_sizes, int n_in,
                              void* d_out, int out_size)
{
    const float* x  = (const float*)d_in[0];
    // d_in[1] = coords (unused by reference)
    const float* Wq = (const float*)d_in[2];
    const float* bq = (const float*)d_in[3];
    const float* Wk = (const float*)d_in[4];
    const float* bk = (const float*)d_in[5];
    const float* Wv = (const float*)d_in[6];
    const float* bv = (const float*)d_in[7];
    const float* Wo = (const float*)d_in[8];
    const float* bo = (const float*)d_in[9];
    float* out = (float*)d_out;

    __half *xh, *Qp, *Kp, *Vp, *Ap, *wp;
    cudaGetSymbolAddress((void**)&xh, g_x);
    cudaGetSymbolAddress((void**)&Qp, g_Q);
    cudaGetSymbolAddress((void**)&Kp, g_K);
    cudaGetSymbolAddress((void**)&Vp, g_V);
    cudaGetSymbolAddress((void**)&Ap, g_A);
    cudaGetSymbolAddress((void**)&wp, g_w);

    cudaFuncSetAttribute(gemm_f16<true>,  cudaFuncAttributeMaxDynamicSharedMemorySize, GEMM_SMEM);
    cudaFuncSetAttribute(gemm_f16<false>, cudaFuncAttributeMaxDynamicSharedMemorySize, GEMM_SMEM);
    cudaFuncSetAttribute(attn_mma_kernel, cudaFuncAttributeMaxDynamicSharedMemorySize, ATTN_SMEM);

    // launch 1: fused prep — transpose/convert weights (z<4) + convert x (z=4)
    dim3 pgrid(32, 32, 5), pblk(32, 8);
    prep_kernel<<<pgrid, pblk>>>(Wq, Wk, Wv, Wo, (const float4*)x, (uint32_t*)xh);

    // launch 2: fused Q/K/V projection (planes 0-2 of g_w), fp16 out
    dim3 qkv_grid(24, M_TOTAL / 128);   // 6144 CTAs (128x128 tiles)
    gemm_f16<false><<<qkv_grid, 256, GEMM_SMEM>>>(xh, wp, bq, bk, bv,
                                                  nullptr, Qp, Kp, Vp);

    // launch 3: tensor-core attention (fp16 A)
    dim3 agrid(NUM_HEADS, NBLK);
    attn_mma_kernel<<<agrid, 256, ATTN_SMEM>>>();

    // launch 4: output projection (plane 3 of g_w), fp32 out
    dim3 o_grid(8, M_TOTAL / 128);
    gemm_f16<true><<<o_grid, 256, GEMM_SMEM>>>(Ap, wp + (size_t)3 * D_MODEL * D_MODEL,
                                               bo, bo, bo, out, nullptr, nullptr, nullptr);
}